// round 5
// baseline (speedup 1.0000x reference)
#include <cuda_runtime.h>
#include <cuda_fp16.h>
#include <math.h>
#include <stdint.h>

// ============================================================================
// Masked ViT context encoder. R5: fp16 3-term split GEMM, 128x256 CTA tile,
// 64x64 warp tiles (MMA:LDSM 6:1), cp.async double buffer, ldmatrix.
// Fused flash attention (fp32), splits fused into producer epilogues.
// ============================================================================

#define BATCH    64
#define N_TOK    196
#define D_MODEL  768
#define N_HEADS  12
#define HEAD_DIM 64
#define N_LAYERS 12
#define FF_DIM   3072
#define M_MAX    (BATCH * N_TOK)

// ---------------- scratch (device globals; no allocation allowed) -----------
__device__ int    g_order[BATCH * N_TOK];
__device__ int    g_len[BATCH];
__device__ float  g_X[(size_t)M_MAX * D_MODEL];
__device__ float  g_qkv[(size_t)M_MAX * 3 * D_MODEL];
__device__ float  g_proj[(size_t)M_MAX * D_MODEL];
// fp16 hi/lo activation buffers
__device__ __half g_ah[(size_t)M_MAX * D_MODEL];
__device__ __half g_al[(size_t)M_MAX * D_MODEL];
__device__ __half g_fh[(size_t)M_MAX * FF_DIM];
__device__ __half g_fl[(size_t)M_MAX * FF_DIM];
// fp16 hi/lo weights
__device__ __half g_wqkv_h[(size_t)N_LAYERS * 3 * D_MODEL * D_MODEL];
__device__ __half g_wqkv_l[(size_t)N_LAYERS * 3 * D_MODEL * D_MODEL];
__device__ __half g_wo_h[(size_t)N_LAYERS * D_MODEL * D_MODEL];
__device__ __half g_wo_l[(size_t)N_LAYERS * D_MODEL * D_MODEL];
__device__ __half g_wf1_h[(size_t)N_LAYERS * FF_DIM * D_MODEL];
__device__ __half g_wf1_l[(size_t)N_LAYERS * FF_DIM * D_MODEL];
__device__ __half g_wf2_h[(size_t)N_LAYERS * FF_DIM * D_MODEL];
__device__ __half g_wf2_l[(size_t)N_LAYERS * FF_DIM * D_MODEL];
__device__ __half g_wp_h[(size_t)D_MODEL * D_MODEL];
__device__ __half g_wp_l[(size_t)D_MODEL * D_MODEL];

// ============================================================================
// helpers
// ============================================================================
__device__ __forceinline__ uint32_t smem_u32(const void* p) {
    uint32_t a;
    asm("{ .reg .u64 t; cvta.to.shared.u64 t, %1; cvt.u32.u64 %0, t; }"
        : "=r"(a) : "l"(p));
    return a;
}
__device__ __forceinline__ void split_hl(float v, __half& h, __half& l) {
    h = __float2half(v);
    l = __float2half(v - __half2float(h));
}

#define CP_ASYNC_16(dst, src) \
    asm volatile("cp.async.cg.shared.global [%0], [%1], 16;" :: "r"(dst), "l"(src))
#define CP_COMMIT() asm volatile("cp.async.commit_group;" ::: "memory")
#define CP_WAIT(n)  asm volatile("cp.async.wait_group %0;" :: "n"(n) : "memory")

#define LDSM4(r0, r1, r2, r3, addr) \
    asm volatile("ldmatrix.sync.aligned.m8n8.x4.shared.b16 {%0,%1,%2,%3}, [%4];" \
        : "=r"(r0), "=r"(r1), "=r"(r2), "=r"(r3) : "r"(addr))

#define MMA16816(c, a, b) \
    asm volatile("mma.sync.aligned.m16n8k16.row.col.f32.f16.f16.f32 " \
        "{%0,%1,%2,%3}, {%4,%5,%6,%7}, {%8,%9}, {%0,%1,%2,%3};" \
        : "+f"((c)[0]), "+f"((c)[1]), "+f"((c)[2]), "+f"((c)[3]) \
        : "r"((a)[0]), "r"((a)[1]), "r"((a)[2]), "r"((a)[3]), \
          "r"((b)[0]), "r"((b)[1]))

// ============================================================================
// weight split: fp32 -> (hi fp16, lo fp16)
// ============================================================================
__global__ void split_kernel(const float4* __restrict__ src,
                             __half2* __restrict__ hi, __half2* __restrict__ lo, int n4)
{
    int i = blockIdx.x * blockDim.x + threadIdx.x;
    if (i >= n4) return;
    float4 v = src[i];
    __half h0, h1, h2, h3, l0, l1, l2, l3;
    split_hl(v.x, h0, l0); split_hl(v.y, h1, l1);
    split_hl(v.z, h2, l2); split_hl(v.w, h3, l3);
    hi[i * 2 + 0] = __halves2half2(h0, h1);
    hi[i * 2 + 1] = __halves2half2(h2, h3);
    lo[i * 2 + 0] = __halves2half2(l0, l1);
    lo[i * 2 + 1] = __halves2half2(l2, l3);
}

// ============================================================================
// HMMA GEMM (fp16 3-term): C = (Ah+Al)(Bh+Bl)^T, AlBl dropped.
// CTA tile 128(M) x 256(N), K-chunk 64, double buffer, 8 warps (2m x 4n),
// warp tile 64x64 (4 x 8 m16n8k16). Term-sequenced to cap registers.
// flags: bit0 bias, bit1 exact GELU, bit2 write fp16 h/l (Ch/Cl) else fp32 C.
// ============================================================================
#define ROW_BYTES   144                  // 64 fp16 (128B) + 16B pad
#define A_TILE      (128 * ROW_BYTES)    // 18432
#define B_TILE      (256 * ROW_BYTES)    // 36864
#define STAGE_BYTES (2 * A_TILE + 2 * B_TILE)  // 110592
#define GEMM_SMEM   (2 * STAGE_BYTES)    // 221184

__global__ void __launch_bounds__(256, 1)
mma_gemm_kernel(const __half* __restrict__ Ah, const __half* __restrict__ Al,
                const __half* __restrict__ Bh, const __half* __restrict__ Bl,
                const float* __restrict__ bias,
                float* __restrict__ C, __half* __restrict__ Ch, __half* __restrict__ Cl,
                int ldc, int M, int K, int flags)
{
    extern __shared__ char smem[];
    const uint32_t sb = smem_u32(smem);
    const int tid  = threadIdx.x;
    const int wid  = tid >> 5, lane = tid & 31;
    const int wm   = wid & 1, wn = wid >> 1;          // 2(m) x 4(n)
    const int brow = blockIdx.y * 128;
    const int bcol = blockIdx.x * 256;

    float acc[4][8][4];
    #pragma unroll
    for (int mt = 0; mt < 4; mt++)
        #pragma unroll
        for (int nt = 0; nt < 8; nt++)
            #pragma unroll
            for (int i = 0; i < 4; i++) acc[mt][nt][i] = 0.0f;

    const int nC = K >> 6;

    // 6144 16B-chunks per stage; 24 per thread.
    auto load_chunk = [&](int c, int buf) {
        const int k0 = c << 6;
        const uint32_t tb = sb + (uint32_t)buf * STAGE_BYTES;
        #pragma unroll
        for (int j = 0; j < 24; j++) {
            int idx = tid + (j << 8);
            const __half* gp;
            uint32_t dst;
            if (idx < 2048) {                         // A hi/lo: 2 x 128 rows x 8
                int op  = idx >> 10;
                int rem = idx & 1023;
                int r = rem >> 3, q = rem & 7;
                int gr = brow + r;
                if (gr >= M) gr = M - 1;
                gp = (op ? Al : Ah) + (size_t)gr * K + k0 + (q << 3);
                dst = tb + (uint32_t)op * A_TILE + (uint32_t)r * ROW_BYTES + (q << 4);
            } else {                                  // B hi/lo: 2 x 256 rows x 8
                int idx2 = idx - 2048;
                int op   = idx2 >> 11;
                int rem  = idx2 & 2047;
                int r = rem >> 3, q = rem & 7;
                int gn = bcol + r;
                gp = (op ? Bl : Bh) + (size_t)gn * K + k0 + (q << 3);
                dst = tb + 2 * A_TILE + (uint32_t)op * B_TILE
                    + (uint32_t)r * ROW_BYTES + (q << 4);
            }
            CP_ASYNC_16(dst, gp);
        }
        CP_COMMIT();
    };

    load_chunk(0, 0);

    // intra-tile ldmatrix offsets
    const uint32_t a_off = (uint32_t)(wm * 64 + (lane & 15)) * ROW_BYTES
                         + (uint32_t)((lane >> 4) << 3) * 2;           // + mt*16*ROW + ks*2
    const int      b_mm  = lane >> 3;
    const uint32_t b_row_off = (uint32_t)(wn * 64 + ((b_mm >> 1) << 3) + (lane & 7)) * ROW_BYTES;
    const uint32_t b_k_off   = (uint32_t)((b_mm & 1) << 3) * 2;

    for (int c = 0; c < nC; c++) {
        const int buf = c & 1;
        if (c + 1 < nC) { load_chunk(c + 1, buf ^ 1); CP_WAIT(1); }
        else            { CP_WAIT(0); }
        __syncthreads();

        const uint32_t At  = sb + (uint32_t)buf * STAGE_BYTES;
        const uint32_t Alt = At + A_TILE;
        const uint32_t Bt  = At + 2 * A_TILE;
        const uint32_t Blt = Bt + B_TILE;

        #pragma unroll
        for (int ks = 0; ks < 64; ks += 16) {
            const uint32_t ksb = (uint32_t)ks * 2;
            uint32_t a[4][4], bh[8][2], bl[8][2];
            #pragma unroll
            for (int g = 0; g < 4; g++) {
                uint32_t off = b_row_off + (uint32_t)(g * 16) * ROW_BYTES + b_k_off + ksb;
                LDSM4(bh[2*g][0], bh[2*g][1], bh[2*g+1][0], bh[2*g+1][1], Bt  + off);
                LDSM4(bl[2*g][0], bl[2*g][1], bl[2*g+1][0], bl[2*g+1][1], Blt + off);
            }
            #pragma unroll
            for (int mt = 0; mt < 4; mt++)
                LDSM4(a[mt][0], a[mt][1], a[mt][2], a[mt][3],
                      At + a_off + (uint32_t)(mt * 16) * ROW_BYTES + ksb);
            #pragma unroll
            for (int mt = 0; mt < 4; mt++)
                #pragma unroll
                for (int nt = 0; nt < 8; nt++) MMA16816(acc[mt][nt], a[mt], bh[nt]);
            #pragma unroll
            for (int mt = 0; mt < 4; mt++)
                #pragma unroll
                for (int nt = 0; nt < 8; nt++) MMA16816(acc[mt][nt], a[mt], bl[nt]);
            // reload a-regs with Al fragments (term 3)
            #pragma unroll
            for (int mt = 0; mt < 4; mt++)
                LDSM4(a[mt][0], a[mt][1], a[mt][2], a[mt][3],
                      Alt + a_off + (uint32_t)(mt * 16) * ROW_BYTES + ksb);
            #pragma unroll
            for (int mt = 0; mt < 4; mt++)
                #pragma unroll
                for (int nt = 0; nt < 8; nt++) MMA16816(acc[mt][nt], a[mt], bh[nt]);
        }
        __syncthreads();
    }

    // ---- epilogue -----------------------------------------------------------
    const int lr = lane >> 2, lc = (lane & 3) * 2;
    #pragma unroll
    for (int mt = 0; mt < 4; mt++) {
        int r0 = brow + wm * 64 + mt * 16 + lr;
        #pragma unroll
        for (int nt = 0; nt < 8; nt++) {
            int cc = bcol + wn * 64 + nt * 8 + lc;
            float bv0 = 0.0f, bv1 = 0.0f;
            if (flags & 1) { bv0 = bias[cc]; bv1 = bias[cc + 1]; }
            #pragma unroll
            for (int half = 0; half < 2; half++) {
                int r = r0 + half * 8;
                if (r < M) {
                    float v0 = acc[mt][nt][half * 2 + 0] + bv0;
                    float v1 = acc[mt][nt][half * 2 + 1] + bv1;
                    if (flags & 2) {
                        v0 = 0.5f * v0 * (1.0f + erff(v0 * 0.70710678118654752440f));
                        v1 = 0.5f * v1 * (1.0f + erff(v1 * 0.70710678118654752440f));
                    }
                    if (flags & 4) {
                        __half h0, h1, l0, l1;
                        split_hl(v0, h0, l0); split_hl(v1, h1, l1);
                        *(__half2*)(Ch + (size_t)r * ldc + cc) = __halves2half2(h0, h1);
                        *(__half2*)(Cl + (size_t)r * ldc + cc) = __halves2half2(l0, l1);
                    } else {
                        *(float2*)(C + (size_t)r * ldc + cc) = make_float2(v0, v1);
                    }
                }
            }
        }
    }
}

// ============================================================================
// mask parse (parallel detection)
// ============================================================================
__global__ void mask_kernel(const unsigned char* __restrict__ mp)
{
    int tid = threadIdx.x;   // 256
    bool big = false, misal = false;
    for (int i = tid; i < BATCH * N_TOK; i += 256) {
        unsigned char v = mp[i];
        if (v >= 2) big = true;
        else if (v && (i & 3)) misal = true;
    }
    int anybig = __syncthreads_or(big ? 1 : 0);
    int anymis = __syncthreads_or(misal ? 1 : 0);
    int type = anybig ? 2 : (anymis ? 1 : 0);
    int b = tid;
    if (b < BATCH) {
        int cnt = 0;
        for (int t = 0; t < N_TOK; t++) {
            int idx = b * N_TOK + t;
            bool m;
            if (type == 2)      m = (((const float*)mp)[idx] != 0.0f);
            else if (type == 1) m = (mp[idx] != 0);
            else                m = (((const int*)mp)[idx] != 0);
            if (m) { g_order[b * N_TOK + cnt] = t; cnt++; }
        }
        g_len[b] = cnt;
    }
}

// ============================================================================
// im2col gather, writing fp16 h/l directly (patch GEMM inputs)
// ============================================================================
__global__ void im2col_kernel(const float* __restrict__ x, int Sc)
{
    int s = blockIdx.x, b = blockIdx.y;
    int m = b * Sc + s;
    __half* dh = g_ah + (size_t)m * D_MODEL;
    __half* dl = g_al + (size_t)m * D_MODEL;
    if (s >= g_len[b]) {
        for (int k = threadIdx.x; k < D_MODEL; k += blockDim.x) {
            dh[k] = __float2half(0.0f); dl[k] = __float2half(0.0f);
        }
        return;
    }
    int t = g_order[b * N_TOK + s];
    int gy = t / 14, gx = t % 14;
    const float* xb = x + (size_t)b * 3 * 224 * 224;
    for (int k = threadIdx.x; k < D_MODEL; k += blockDim.x) {
        int c = k >> 8, r = (k >> 4) & 15, cc = k & 15;
        float v = xb[((size_t)c * 224 + (gy * 16 + r)) * 224 + (gx * 16 + cc)];
        __half h, l; split_hl(v, h, l);
        dh[k] = h; dl[k] = l;
    }
}

// patch epilogue: X += patch_b + pos; emit h/l for QKV GEMM; zero pad rows.
__global__ void patch_epi_kernel(const float* __restrict__ pb,
                                 const float* __restrict__ pos, int Sc)
{
    int s = blockIdx.x, b = blockIdx.y;
    int m = b * Sc + s;
    float* row = g_X + (size_t)m * D_MODEL;
    __half* dh = g_ah + (size_t)m * D_MODEL;
    __half* dl = g_al + (size_t)m * D_MODEL;
    if (s >= g_len[b]) {
        for (int d = threadIdx.x; d < D_MODEL; d += blockDim.x) {
            row[d] = 0.0f;
            dh[d] = __float2half(0.0f); dl[d] = __float2half(0.0f);
        }
        return;
    }
    int t = g_order[b * N_TOK + s];
    const float* pr = pos + (size_t)t * D_MODEL;
    for (int d = threadIdx.x; d < D_MODEL; d += blockDim.x) {
        float v = row[d] + pb[d] + pr[d];
        row[d] = v;
        __half h, l; split_hl(v, h, l);
        dh[d] = h; dl[d] = l;
    }
}

// ============================================================================
// Fused flash attention (fp32), one CTA per (b,h). Whole Q/K/V in SMEM.
// Output written as fp16 h/l (proj GEMM inputs).
// ============================================================================
#define KS_STRIDE 65

__global__ void __launch_bounds__(256, 1)
flash_kernel(int Sc)
{
    extern __shared__ float fs[];
    float* qs = fs;                       // [Sc][64]
    float* ks = qs + Sc * 64;             // [Sc][65]
    float* vs = ks + Sc * KS_STRIDE;      // [Sc][64]
    float* es = vs + Sc * 64;             // [8][32]

    const int b = blockIdx.x / N_HEADS, h = blockIdx.x % N_HEADS;
    const int len = g_len[b];
    const int tid = threadIdx.x, lane = tid & 31, wid = tid >> 5;
    const size_t base = (size_t)(b * Sc) * (3 * D_MODEL) + h * HEAD_DIM;

    for (int idx = tid; idx < Sc * 64; idx += 256) {
        int r = idx >> 6, d = idx & 63;
        size_t g = base + (size_t)r * (3 * D_MODEL) + d;
        qs[idx] = g_qkv[g];
        ks[r * KS_STRIDE + d] = g_qkv[g + D_MODEL];
        vs[idx] = g_qkv[g + 2 * D_MODEL];
    }
    __syncthreads();

    float* ew = es + wid * 32;
    for (int q = wid; q < Sc; q += 8) {
        const float* qrow = qs + q * 64;
        float m = -3.4e38f, l = 0.0f;
        float o0a = 0.f, o0b = 0.f, o1a = 0.f, o1b = 0.f;
        for (int j0 = 0; j0 < len; j0 += 32) {
            int j = j0 + lane;
            int jj = (j < len) ? j : (len - 1);
            const float* krow = ks + jj * KS_STRIDE;
            float s0 = 0.f, s1 = 0.f, s2 = 0.f, s3 = 0.f;
            #pragma unroll
            for (int d = 0; d < 64; d += 4) {
                s0 += qrow[d + 0] * krow[d + 0];
                s1 += qrow[d + 1] * krow[d + 1];
                s2 += qrow[d + 2] * krow[d + 2];
                s3 += qrow[d + 3] * krow[d + 3];
            }
            float s = ((s0 + s1) + (s2 + s3)) * 0.125f;
            if (j >= len) s = -3.4e38f;
            float tmax = s;
            #pragma unroll
            for (int o = 16; o; o >>= 1) tmax = fmaxf(tmax, __shfl_xor_sync(0xffffffffu, tmax, o));
            float mnew = fmaxf(m, tmax);
            float scale = __expf(m - mnew);
            float e = (j < len) ? __expf(s - mnew) : 0.0f;
            float esum = e;
            #pragma unroll
            for (int o = 16; o; o >>= 1) esum += __shfl_xor_sync(0xffffffffu, esum, o);
            l = l * scale + esum;
            m = mnew;
            o0a *= scale; o0b *= scale; o1a *= scale; o1b *= scale;
            ew[lane] = e;
            __syncwarp();
            int jmax = (len - j0 < 32) ? (len - j0) : 32;
            int j2 = 0;
            for (; j2 + 2 <= jmax; j2 += 2) {
                float e0 = ew[j2], e1 = ew[j2 + 1];
                const float* v0 = vs + (j0 + j2) * 64;
                const float* v1 = v0 + 64;
                o0a += e0 * v0[lane];      o1a += e0 * v0[lane + 32];
                o0b += e1 * v1[lane];      o1b += e1 * v1[lane + 32];
            }
            if (j2 < jmax) {
                float e0 = ew[j2];
                const float* v0 = vs + (j0 + j2) * 64;
                o0a += e0 * v0[lane];      o1a += e0 * v0[lane + 32];
            }
            __syncwarp();
        }
        float inv = 1.0f / l;
        float r0 = (o0a + o0b) * inv, r1 = (o1a + o1b) * inv;
        size_t orow = (size_t)(b * Sc + q) * D_MODEL + h * HEAD_DIM;
        __half h0, l0, h1, l1;
        split_hl(r0, h0, l0); split_hl(r1, h1, l1);
        g_ah[orow + lane]      = h0;  g_al[orow + lane]      = l0;
        g_ah[orow + lane + 32] = h1;  g_al[orow + lane + 32] = l1;
    }
}

// ============================================================================
// LayerNorm (optionally +residual); optionally emits fp16 h/l alongside fp32.
// ============================================================================
__device__ __forceinline__ float blockReduce256(float v)
{
    __shared__ float sh[8];
    __syncthreads();
    #pragma unroll
    for (int o = 16; o; o >>= 1) v += __shfl_down_sync(0xffffffffu, v, o);
    if ((threadIdx.x & 31) == 0) sh[threadIdx.x >> 5] = v;
    __syncthreads();
    return sh[0] + sh[1] + sh[2] + sh[3] + sh[4] + sh[5] + sh[6] + sh[7];
}

template<bool RESID, bool EMITHL>
__global__ void ln_kernel(const float* __restrict__ X, const float* __restrict__ Rsd,
                          const float* __restrict__ gma, const float* __restrict__ bta,
                          float* __restrict__ out,
                          __half* __restrict__ outH, __half* __restrict__ outL)
{
    int m = blockIdx.x;
    int tid = threadIdx.x;
    const float* xr = X + (size_t)m * D_MODEL;
    float v[3];
    #pragma unroll
    for (int i = 0; i < 3; i++) {
        int d = tid + 256 * i;
        v[i] = xr[d];
        if (RESID) v[i] += Rsd[(size_t)m * D_MODEL + d];
    }
    float s = blockReduce256(v[0] + v[1] + v[2]);
    float mean = s * (1.0f / 768.0f);
    float q = 0.0f;
    #pragma unroll
    for (int i = 0; i < 3; i++) { float d = v[i] - mean; q += d * d; }
    q = blockReduce256(q);
    float inv = 1.0f / sqrtf(q * (1.0f / 768.0f) + 1e-5f);
    #pragma unroll
    for (int i = 0; i < 3; i++) {
        int d = tid + 256 * i;
        float r = (v[i] - mean) * inv * gma[d] + bta[d];
        out[(size_t)m * D_MODEL + d] = r;
        if (EMITHL) {
            __half h, l; split_hl(r, h, l);
            outH[(size_t)m * D_MODEL + d] = h;
            outL[(size_t)m * D_MODEL + d] = l;
        }
    }
}

__global__ void pad_out_kernel(float* __restrict__ out2, int Sc)
{
    int i = blockIdx.x * blockDim.x + threadIdx.x;
    if (i < BATCH * Sc) {
        int b = i / Sc, s = i % Sc;
        out2[i] = (s >= g_len[b]) ? 1.0f : 0.0f;
    }
}

// ===========================================================================
static void run_split(const float* src, __half* hi, __half* lo, size_t n)
{
    int n4 = (int)(n >> 2);
    split_kernel<<<(n4 + 255) / 256, 256>>>((const float4*)src, (__half2*)hi, (__half2*)lo, n4);
}

extern "C" void kernel_launch(void* const* d_in, const int* in_sizes, int n_in,
                              void* d_out, int out_size)
{
    const float* x       = (const float*)d_in[0];
    const void*  mask    = d_in[1];
    const float* patch_w = (const float*)d_in[2];
    const float* patch_b = (const float*)d_in[3];
    const float* pos     = (const float*)d_in[4];
    const float* inw     = (const float*)d_in[5];
    const float* inb     = (const float*)d_in[6];
    const float* outw    = (const float*)d_in[7];
    const float* outb    = (const float*)d_in[8];
    const float* ln1g    = (const float*)d_in[9];
    const float* ln1b    = (const float*)d_in[10];
    const float* f1w     = (const float*)d_in[11];
    const float* f1b     = (const float*)d_in[12];
    const float* f2w     = (const float*)d_in[13];
    const float* f2b     = (const float*)d_in[14];
    const float* ln2g    = (const float*)d_in[15];
    const float* ln2b    = (const float*)d_in[16];
    const float* ng      = (const float*)d_in[17];
    const float* nb      = (const float*)d_in[18];

    int Sc; bool tup;
    if (out_size % (64 * 769) == 0 &&
        out_size / (64 * 769) >= 1 && out_size / (64 * 769) <= N_TOK) {
        Sc = out_size / (64 * 769); tup = true;
    } else {
        Sc = out_size / (64 * 768); tup = false;
    }
    if (Sc < 1) Sc = 1;
    if (Sc > N_TOK) Sc = N_TOK;
    const int M  = BATCH * Sc;
    const int MB = (M + 127) / 128;
    const int flash_smem = Sc * (64 + KS_STRIDE + 64) * 4 + 8 * 32 * 4;

    float *pX, *pQ, *pP;
    __half *ah, *al, *fh, *fl, *wqh, *wql, *woh, *wol, *w1h, *w1l, *w2h, *w2l, *wph, *wpl;
    cudaGetSymbolAddress((void**)&pX,  g_X);
    cudaGetSymbolAddress((void**)&pQ,  g_qkv);
    cudaGetSymbolAddress((void**)&pP,  g_proj);
    cudaGetSymbolAddress((void**)&ah,  g_ah);
    cudaGetSymbolAddress((void**)&al,  g_al);
    cudaGetSymbolAddress((void**)&fh,  g_fh);
    cudaGetSymbolAddress((void**)&fl,  g_fl);
    cudaGetSymbolAddress((void**)&wqh, g_wqkv_h);
    cudaGetSymbolAddress((void**)&wql, g_wqkv_l);
    cudaGetSymbolAddress((void**)&woh, g_wo_h);
    cudaGetSymbolAddress((void**)&wol, g_wo_l);
    cudaGetSymbolAddress((void**)&w1h, g_wf1_h);
    cudaGetSymbolAddress((void**)&w1l, g_wf1_l);
    cudaGetSymbolAddress((void**)&w2h, g_wf2_h);
    cudaGetSymbolAddress((void**)&w2l, g_wf2_l);
    cudaGetSymbolAddress((void**)&wph, g_wp_h);
    cudaGetSymbolAddress((void**)&wpl, g_wp_l);

    cudaFuncSetAttribute(mma_gemm_kernel, cudaFuncAttributeMaxDynamicSharedMemorySize,
                         GEMM_SMEM);
    cudaFuncSetAttribute(flash_kernel, cudaFuncAttributeMaxDynamicSharedMemorySize,
                         160000);

    // --- weight splits --------------------------------------------------------
    run_split(inw,     wqh, wql, (size_t)N_LAYERS * 3 * D_MODEL * D_MODEL);
    run_split(outw,    woh, wol, (size_t)N_LAYERS * D_MODEL * D_MODEL);
    run_split(f1w,     w1h, w1l, (size_t)N_LAYERS * FF_DIM * D_MODEL);
    run_split(f2w,     w2h, w2l, (size_t)N_LAYERS * FF_DIM * D_MODEL);
    run_split(patch_w, wph, wpl, (size_t)D_MODEL * D_MODEL);

    // --- mask parse + gather + patch embedding --------------------------------
    mask_kernel<<<1, 256>>>((const unsigned char*)mask);
    im2col_kernel<<<dim3(Sc, BATCH), 256>>>(x, Sc);
    mma_gemm_kernel<<<dim3(3, MB), 256, GEMM_SMEM>>>(
        ah, al, wph, wpl, nullptr, pX, nullptr, nullptr, D_MODEL, M, D_MODEL, 0);
    patch_epi_kernel<<<dim3(Sc, BATCH), 256>>>(patch_b, pos, Sc);

    // --- transformer layers ---------------------------------------------------
    for (int l = 0; l < N_LAYERS; l++) {
        const __half* Wqh = wqh + (size_t)l * 3 * D_MODEL * D_MODEL;
        const __half* Wql = wql + (size_t)l * 3 * D_MODEL * D_MODEL;
        const __half* Woh = woh + (size_t)l * D_MODEL * D_MODEL;
        const __half* Wol = wol + (size_t)l * D_MODEL * D_MODEL;
        const __half* W1h = w1h + (size_t)l * FF_DIM * D_MODEL;
        const __half* W1l = w1l + (size_t)l * FF_DIM * D_MODEL;
        const __half* W2h = w2h + (size_t)l * FF_DIM * D_MODEL;
        const __half* W2l = w2l + (size_t)l * FF_DIM * D_MODEL;
        const float* bqkv = inb  + (size_t)l * 3 * D_MODEL;
        const float* bo   = outb + (size_t)l * D_MODEL;
        const float* b1   = f1b  + (size_t)l * FF_DIM;
        const float* b2   = f2b  + (size_t)l * D_MODEL;

        // QKV projection (reads ah/al from patch_epi or previous ln2)
        mma_gemm_kernel<<<dim3(9, MB), 256, GEMM_SMEM>>>(
            ah, al, Wqh, Wql, bqkv, pQ, nullptr, nullptr, 3 * D_MODEL, M, D_MODEL, 1);
        // fused attention -> ah/al
        flash_kernel<<<BATCH * N_HEADS, 256, flash_smem>>>(Sc);
        // output projection
        mma_gemm_kernel<<<dim3(3, MB), 256, GEMM_SMEM>>>(
            ah, al, Woh, Wol, bo, pP, nullptr, nullptr, D_MODEL, M, D_MODEL, 1);
        // residual + LN1 -> X, ah/al
        ln_kernel<true, true><<<M, 256>>>(pX, pP, ln1g + l * D_MODEL, ln1b + l * D_MODEL,
                                          pX, ah, al);
        // FFN1 (+GELU) -> fh/fl (fp16 h/l)
        mma_gemm_kernel<<<dim3(12, MB), 256, GEMM_SMEM>>>(
            ah, al, W1h, W1l, b1, nullptr, fh, fl, FF_DIM, M, D_MODEL, 1 | 2 | 4);
        // FFN2
        mma_gemm_kernel<<<dim3(3, MB), 256, GEMM_SMEM>>>(
            fh, fl, W2h, W2l, b2, pP, nullptr, nullptr, D_MODEL, M, FF_DIM, 1);
        // residual + LN2 -> X, ah/al
        ln_kernel<true, true><<<M, 256>>>(pX, pP, ln2g + l * D_MODEL, ln2b + l * D_MODEL,
                                          pX, ah, al);
    }

    // --- final LN into d_out --------------------------------------------------
    ln_kernel<false, false><<<M, 256>>>(pX, nullptr, ng, nb, (float*)d_out,
                                        nullptr, nullptr);
    if (tup) {
        pad_out_kernel<<<(BATCH * Sc + 255) / 256, 256>>>(
            (float*)d_out + (size_t)M * D_MODEL, Sc);
    }
}

// round 7
// speedup vs baseline: 1.1520x; 1.1520x over previous
#include <cuda_runtime.h>
#include <cuda_fp16.h>
#include <math.h>
#include <stdint.h>

// ============================================================================
// Masked ViT context encoder. R7 (= R6 resubmit; container infra failure):
// R4 GEMM config (128x128, 32x64 warp tiles) with K-chunk 32 (40KB stages)
// => 2 CTAs/SM for latency hiding. fp16 3-term split, fused flash attention,
// fused splits.
// ============================================================================

#define BATCH    64
#define N_TOK    196
#define D_MODEL  768
#define N_HEADS  12
#define HEAD_DIM 64
#define N_LAYERS 12
#define FF_DIM   3072
#define M_MAX    (BATCH * N_TOK)

// ---------------- scratch (device globals; no allocation allowed) -----------
__device__ int    g_order[BATCH * N_TOK];
__device__ int    g_len[BATCH];
__device__ float  g_X[(size_t)M_MAX * D_MODEL];
__device__ float  g_qkv[(size_t)M_MAX * 3 * D_MODEL];
__device__ float  g_proj[(size_t)M_MAX * D_MODEL];
// fp16 hi/lo activation buffers
__device__ __half g_ah[(size_t)M_MAX * D_MODEL];
__device__ __half g_al[(size_t)M_MAX * D_MODEL];
__device__ __half g_fh[(size_t)M_MAX * FF_DIM];
__device__ __half g_fl[(size_t)M_MAX * FF_DIM];
// fp16 hi/lo weights
__device__ __half g_wqkv_h[(size_t)N_LAYERS * 3 * D_MODEL * D_MODEL];
__device__ __half g_wqkv_l[(size_t)N_LAYERS * 3 * D_MODEL * D_MODEL];
__device__ __half g_wo_h[(size_t)N_LAYERS * D_MODEL * D_MODEL];
__device__ __half g_wo_l[(size_t)N_LAYERS * D_MODEL * D_MODEL];
__device__ __half g_wf1_h[(size_t)N_LAYERS * FF_DIM * D_MODEL];
__device__ __half g_wf1_l[(size_t)N_LAYERS * FF_DIM * D_MODEL];
__device__ __half g_wf2_h[(size_t)N_LAYERS * FF_DIM * D_MODEL];
__device__ __half g_wf2_l[(size_t)N_LAYERS * FF_DIM * D_MODEL];
__device__ __half g_wp_h[(size_t)D_MODEL * D_MODEL];
__device__ __half g_wp_l[(size_t)D_MODEL * D_MODEL];

// ============================================================================
// helpers
// ============================================================================
__device__ __forceinline__ uint32_t smem_u32(const void* p) {
    uint32_t a;
    asm("{ .reg .u64 t; cvta.to.shared.u64 t, %1; cvt.u32.u64 %0, t; }"
        : "=r"(a) : "l"(p));
    return a;
}
__device__ __forceinline__ void split_hl(float v, __half& h, __half& l) {
    h = __float2half(v);
    l = __float2half(v - __half2float(h));
}

#define CP_ASYNC_16(dst, src) \
    asm volatile("cp.async.cg.shared.global [%0], [%1], 16;" :: "r"(dst), "l"(src))
#define CP_COMMIT() asm volatile("cp.async.commit_group;" ::: "memory")
#define CP_WAIT(n)  asm volatile("cp.async.wait_group %0;" :: "n"(n) : "memory")

#define LDSM4(r0, r1, r2, r3, addr) \
    asm volatile("ldmatrix.sync.aligned.m8n8.x4.shared.b16 {%0,%1,%2,%3}, [%4];" \
        : "=r"(r0), "=r"(r1), "=r"(r2), "=r"(r3) : "r"(addr))

#define MMA16816(c, a, b) \
    asm volatile("mma.sync.aligned.m16n8k16.row.col.f32.f16.f16.f32 " \
        "{%0,%1,%2,%3}, {%4,%5,%6,%7}, {%8,%9}, {%0,%1,%2,%3};" \
        : "+f"((c)[0]), "+f"((c)[1]), "+f"((c)[2]), "+f"((c)[3]) \
        : "r"((a)[0]), "r"((a)[1]), "r"((a)[2]), "r"((a)[3]), \
          "r"((b)[0]), "r"((b)[1]))

// ============================================================================
// weight split: fp32 -> (hi fp16, lo fp16)
// ============================================================================
__global__ void split_kernel(const float4* __restrict__ src,
                             __half2* __restrict__ hi, __half2* __restrict__ lo, int n4)
{
    int i = blockIdx.x * blockDim.x + threadIdx.x;
    if (i >= n4) return;
    float4 v = src[i];
    __half h0, h1, h2, h3, l0, l1, l2, l3;
    split_hl(v.x, h0, l0); split_hl(v.y, h1, l1);
    split_hl(v.z, h2, l2); split_hl(v.w, h3, l3);
    hi[i * 2 + 0] = __halves2half2(h0, h1);
    hi[i * 2 + 1] = __halves2half2(h2, h3);
    lo[i * 2 + 0] = __halves2half2(l0, l1);
    lo[i * 2 + 1] = __halves2half2(l2, l3);
}

// ============================================================================
// HMMA GEMM (fp16 3-term): C = (Ah+Al)(Bh+Bl)^T, AlBl dropped.
// 128x128 CTA tile, K-chunk 32, cp.async double buffer (40KB stages,
// 2 CTAs/SM), ldmatrix fragments, 8 warps (4m x 2n), warp tile 32x64.
// flags: bit0 bias, bit1 exact GELU, bit2 write fp16 h/l (Ch/Cl) else fp32 C.
// ============================================================================
#define ROW_BYTES   80                  // 32 fp16 (64B) + 16B pad: conflict-free
#define TILE_BYTES  (128 * ROW_BYTES)   // 10240
#define STAGE_BYTES (4 * TILE_BYTES)    // 40960
#define GEMM_SMEM   (2 * STAGE_BYTES)   // 81920

__global__ void __launch_bounds__(256, 2)
mma_gemm_kernel(const __half* __restrict__ Ah, const __half* __restrict__ Al,
                const __half* __restrict__ Bh, const __half* __restrict__ Bl,
                const float* __restrict__ bias,
                float* __restrict__ C, __half* __restrict__ Ch, __half* __restrict__ Cl,
                int ldc, int M, int K, int flags)
{
    extern __shared__ char smem[];
    const uint32_t sb = smem_u32(smem);
    const int tid  = threadIdx.x;
    const int wid  = tid >> 5, lane = tid & 31;
    const int wm   = wid & 3, wn = wid >> 2;     // 4(m) x 2(n)
    const int brow = blockIdx.y * 128;
    const int bcol = blockIdx.x * 128;

    float acc[2][8][4];
    #pragma unroll
    for (int mt = 0; mt < 2; mt++)
        #pragma unroll
        for (int nt = 0; nt < 8; nt++)
            #pragma unroll
            for (int i = 0; i < 4; i++) acc[mt][nt][i] = 0.0f;

    const int nC = K >> 5;

    // 2048 16B-chunks per stage; 8 per thread.
    auto load_chunk = [&](int c, int buf) {
        const int k0 = c << 5;
        const uint32_t tb = sb + (uint32_t)buf * STAGE_BYTES;
        #pragma unroll
        for (int j = 0; j < 8; j++) {
            int idx = tid + (j << 8);
            int op  = idx >> 9;           // 0=Ah 1=Al 2=Bh 3=Bl
            int rem = idx & 511;
            int r   = rem >> 2;           // row 0..127
            int q   = rem & 3;            // 16B chunk (8 halves)
            const __half* gp;
            if (op < 2) {
                int gr = brow + r;
                if (gr >= M) gr = M - 1;
                gp = (op ? Al : Ah) + (size_t)gr * K + k0 + (q << 3);
            } else {
                int gn = bcol + r;
                gp = (op == 3 ? Bl : Bh) + (size_t)gn * K + k0 + (q << 3);
            }
            uint32_t dst = tb + (uint32_t)op * TILE_BYTES + (uint32_t)r * ROW_BYTES + (q << 4);
            CP_ASYNC_16(dst, gp);
        }
        CP_COMMIT();
    };

    load_chunk(0, 0);

    // intra-tile ldmatrix offsets
    const uint32_t a_off = (uint32_t)(wm * 32 + (lane & 15)) * ROW_BYTES
                         + (uint32_t)((lane >> 4) << 3) * 2;           // + ks*2
    const int      b_mm  = lane >> 3;
    const uint32_t b_row_off = (uint32_t)(wn * 64 + ((b_mm >> 1) << 3) + (lane & 7)) * ROW_BYTES;
    const uint32_t b_k_off   = (uint32_t)((b_mm & 1) << 3) * 2;

    for (int c = 0; c < nC; c++) {
        const int buf = c & 1;
        if (c + 1 < nC) { load_chunk(c + 1, buf ^ 1); CP_WAIT(1); }
        else            { CP_WAIT(0); }
        __syncthreads();

        const uint32_t At  = sb + (uint32_t)buf * STAGE_BYTES;
        const uint32_t Alt = At + TILE_BYTES;
        const uint32_t Bt  = At + 2 * TILE_BYTES;
        const uint32_t Blt = At + 3 * TILE_BYTES;

        #pragma unroll
        for (int ks = 0; ks < 32; ks += 16) {
            uint32_t ah[2][4], al[2][4], bh[8][2], bl[8][2];
            const uint32_t ksb = (uint32_t)ks * 2;
            LDSM4(ah[0][0], ah[0][1], ah[0][2], ah[0][3], At  + a_off + ksb);
            LDSM4(ah[1][0], ah[1][1], ah[1][2], ah[1][3], At  + a_off + ksb + 16 * ROW_BYTES);
            LDSM4(al[0][0], al[0][1], al[0][2], al[0][3], Alt + a_off + ksb);
            LDSM4(al[1][0], al[1][1], al[1][2], al[1][3], Alt + a_off + ksb + 16 * ROW_BYTES);
            #pragma unroll
            for (int g = 0; g < 4; g++) {
                uint32_t off = b_row_off + (uint32_t)(g * 16) * ROW_BYTES + b_k_off + ksb;
                LDSM4(bh[2*g][0], bh[2*g][1], bh[2*g+1][0], bh[2*g+1][1], Bt  + off);
                LDSM4(bl[2*g][0], bl[2*g][1], bl[2*g+1][0], bl[2*g+1][1], Blt + off);
            }
            #pragma unroll
            for (int mt = 0; mt < 2; mt++)
                #pragma unroll
                for (int nt = 0; nt < 8; nt++) MMA16816(acc[mt][nt], ah[mt], bh[nt]);
            #pragma unroll
            for (int mt = 0; mt < 2; mt++)
                #pragma unroll
                for (int nt = 0; nt < 8; nt++) MMA16816(acc[mt][nt], ah[mt], bl[nt]);
            #pragma unroll
            for (int mt = 0; mt < 2; mt++)
                #pragma unroll
                for (int nt = 0; nt < 8; nt++) MMA16816(acc[mt][nt], al[mt], bh[nt]);
        }
        __syncthreads();
    }

    // ---- epilogue -----------------------------------------------------------
    const int lr = lane >> 2, lc = (lane & 3) * 2;
    #pragma unroll
    for (int mt = 0; mt < 2; mt++) {
        int r0 = brow + wm * 32 + mt * 16 + lr;
        #pragma unroll
        for (int nt = 0; nt < 8; nt++) {
            int cc = bcol + wn * 64 + nt * 8 + lc;
            float bv0 = 0.0f, bv1 = 0.0f;
            if (flags & 1) { bv0 = bias[cc]; bv1 = bias[cc + 1]; }
            #pragma unroll
            for (int half = 0; half < 2; half++) {
                int r = r0 + half * 8;
                if (r < M) {
                    float v0 = acc[mt][nt][half * 2 + 0] + bv0;
                    float v1 = acc[mt][nt][half * 2 + 1] + bv1;
                    if (flags & 2) {
                        v0 = 0.5f * v0 * (1.0f + erff(v0 * 0.70710678118654752440f));
                        v1 = 0.5f * v1 * (1.0f + erff(v1 * 0.70710678118654752440f));
                    }
                    if (flags & 4) {
                        __half h0, h1, l0, l1;
                        split_hl(v0, h0, l0); split_hl(v1, h1, l1);
                        *(__half2*)(Ch + (size_t)r * ldc + cc) = __halves2half2(h0, h1);
                        *(__half2*)(Cl + (size_t)r * ldc + cc) = __halves2half2(l0, l1);
                    } else {
                        *(float2*)(C + (size_t)r * ldc + cc) = make_float2(v0, v1);
                    }
                }
            }
        }
    }
}

// ============================================================================
// mask parse (parallel detection)
// ============================================================================
__global__ void mask_kernel(const unsigned char* __restrict__ mp)
{
    int tid = threadIdx.x;   // 256
    bool big = false, misal = false;
    for (int i = tid; i < BATCH * N_TOK; i += 256) {
        unsigned char v = mp[i];
        if (v >= 2) big = true;
        else if (v && (i & 3)) misal = true;
    }
    int anybig = __syncthreads_or(big ? 1 : 0);
    int anymis = __syncthreads_or(misal ? 1 : 0);
    int type = anybig ? 2 : (anymis ? 1 : 0);
    int b = tid;
    if (b < BATCH) {
        int cnt = 0;
        for (int t = 0; t < N_TOK; t++) {
            int idx = b * N_TOK + t;
            bool m;
            if (type == 2)      m = (((const float*)mp)[idx] != 0.0f);
            else if (type == 1) m = (mp[idx] != 0);
            else                m = (((const int*)mp)[idx] != 0);
            if (m) { g_order[b * N_TOK + cnt] = t; cnt++; }
        }
        g_len[b] = cnt;
    }
}

// ============================================================================
// im2col gather, writing fp16 h/l directly (patch GEMM inputs)
// ============================================================================
__global__ void im2col_kernel(const float* __restrict__ x, int Sc)
{
    int s = blockIdx.x, b = blockIdx.y;
    int m = b * Sc + s;
    __half* dh = g_ah + (size_t)m * D_MODEL;
    __half* dl = g_al + (size_t)m * D_MODEL;
    if (s >= g_len[b]) {
        for (int k = threadIdx.x; k < D_MODEL; k += blockDim.x) {
            dh[k] = __float2half(0.0f); dl[k] = __float2half(0.0f);
        }
        return;
    }
    int t = g_order[b * N_TOK + s];
    int gy = t / 14, gx = t % 14;
    const float* xb = x + (size_t)b * 3 * 224 * 224;
    for (int k = threadIdx.x; k < D_MODEL; k += blockDim.x) {
        int c = k >> 8, r = (k >> 4) & 15, cc = k & 15;
        float v = xb[((size_t)c * 224 + (gy * 16 + r)) * 224 + (gx * 16 + cc)];
        __half h, l; split_hl(v, h, l);
        dh[k] = h; dl[k] = l;
    }
}

// patch epilogue: X += patch_b + pos; emit h/l for QKV GEMM; zero pad rows.
__global__ void patch_epi_kernel(const float* __restrict__ pb,
                                 const float* __restrict__ pos, int Sc)
{
    int s = blockIdx.x, b = blockIdx.y;
    int m = b * Sc + s;
    float* row = g_X + (size_t)m * D_MODEL;
    __half* dh = g_ah + (size_t)m * D_MODEL;
    __half* dl = g_al + (size_t)m * D_MODEL;
    if (s >= g_len[b]) {
        for (int d = threadIdx.x; d < D_MODEL; d += blockDim.x) {
            row[d] = 0.0f;
            dh[d] = __float2half(0.0f); dl[d] = __float2half(0.0f);
        }
        return;
    }
    int t = g_order[b * N_TOK + s];
    const float* pr = pos + (size_t)t * D_MODEL;
    for (int d = threadIdx.x; d < D_MODEL; d += blockDim.x) {
        float v = row[d] + pb[d] + pr[d];
        row[d] = v;
        __half h, l; split_hl(v, h, l);
        dh[d] = h; dl[d] = l;
    }
}

// ============================================================================
// Fused flash attention (fp32), one CTA per (b,h). Whole Q/K/V in SMEM.
// Output written as fp16 h/l (proj GEMM inputs).
// ============================================================================
#define KS_STRIDE 65

__global__ void __launch_bounds__(256, 1)
flash_kernel(int Sc)
{
    extern __shared__ float fs[];
    float* qs = fs;                       // [Sc][64]
    float* ks = qs + Sc * 64;             // [Sc][65]
    float* vs = ks + Sc * KS_STRIDE;      // [Sc][64]
    float* es = vs + Sc * 64;             // [8][32]

    const int b = blockIdx.x / N_HEADS, h = blockIdx.x % N_HEADS;
    const int len = g_len[b];
    const int tid = threadIdx.x, lane = tid & 31, wid = tid >> 5;
    const size_t base = (size_t)(b * Sc) * (3 * D_MODEL) + h * HEAD_DIM;

    for (int idx = tid; idx < Sc * 64; idx += 256) {
        int r = idx >> 6, d = idx & 63;
        size_t g = base + (size_t)r * (3 * D_MODEL) + d;
        qs[idx] = g_qkv[g];
        ks[r * KS_STRIDE + d] = g_qkv[g + D_MODEL];
        vs[idx] = g_qkv[g + 2 * D_MODEL];
    }
    __syncthreads();

    float* ew = es + wid * 32;
    for (int q = wid; q < Sc; q += 8) {
        const float* qrow = qs + q * 64;
        float m = -3.4e38f, l = 0.0f;
        float o0a = 0.f, o0b = 0.f, o1a = 0.f, o1b = 0.f;
        for (int j0 = 0; j0 < len; j0 += 32) {
            int j = j0 + lane;
            int jj = (j < len) ? j : (len - 1);
            const float* krow = ks + jj * KS_STRIDE;
            float s0 = 0.f, s1 = 0.f, s2 = 0.f, s3 = 0.f;
            #pragma unroll
            for (int d = 0; d < 64; d += 4) {
                s0 += qrow[d + 0] * krow[d + 0];
                s1 += qrow[d + 1] * krow[d + 1];
                s2 += qrow[d + 2] * krow[d + 2];
                s3 += qrow[d + 3] * krow[d + 3];
            }
            float s = ((s0 + s1) + (s2 + s3)) * 0.125f;
            if (j >= len) s = -3.4e38f;
            float tmax = s;
            #pragma unroll
            for (int o = 16; o; o >>= 1) tmax = fmaxf(tmax, __shfl_xor_sync(0xffffffffu, tmax, o));
            float mnew = fmaxf(m, tmax);
            float scale = __expf(m - mnew);
            float e = (j < len) ? __expf(s - mnew) : 0.0f;
            float esum = e;
            #pragma unroll
            for (int o = 16; o; o >>= 1) esum += __shfl_xor_sync(0xffffffffu, esum, o);
            l = l * scale + esum;
            m = mnew;
            o0a *= scale; o0b *= scale; o1a *= scale; o1b *= scale;
            ew[lane] = e;
            __syncwarp();
            int jmax = (len - j0 < 32) ? (len - j0) : 32;
            int j2 = 0;
            for (; j2 + 2 <= jmax; j2 += 2) {
                float e0 = ew[j2], e1 = ew[j2 + 1];
                const float* v0 = vs + (j0 + j2) * 64;
                const float* v1 = v0 + 64;
                o0a += e0 * v0[lane];      o1a += e0 * v0[lane + 32];
                o0b += e1 * v1[lane];      o1b += e1 * v1[lane + 32];
            }
            if (j2 < jmax) {
                float e0 = ew[j2];
                const float* v0 = vs + (j0 + j2) * 64;
                o0a += e0 * v0[lane];      o1a += e0 * v0[lane + 32];
            }
            __syncwarp();
        }
        float inv = 1.0f / l;
        float r0 = (o0a + o0b) * inv, r1 = (o1a + o1b) * inv;
        size_t orow = (size_t)(b * Sc + q) * D_MODEL + h * HEAD_DIM;
        __half h0, l0, h1, l1;
        split_hl(r0, h0, l0); split_hl(r1, h1, l1);
        g_ah[orow + lane]      = h0;  g_al[orow + lane]      = l0;
        g_ah[orow + lane + 32] = h1;  g_al[orow + lane + 32] = l1;
    }
}

// ============================================================================
// LayerNorm (optionally +residual); optionally emits fp16 h/l alongside fp32.
// ============================================================================
__device__ __forceinline__ float blockReduce256(float v)
{
    __shared__ float sh[8];
    __syncthreads();
    #pragma unroll
    for (int o = 16; o; o >>= 1) v += __shfl_down_sync(0xffffffffu, v, o);
    if ((threadIdx.x & 31) == 0) sh[threadIdx.x >> 5] = v;
    __syncthreads();
    return sh[0] + sh[1] + sh[2] + sh[3] + sh[4] + sh[5] + sh[6] + sh[7];
}

template<bool RESID, bool EMITHL>
__global__ void ln_kernel(const float* __restrict__ X, const float* __restrict__ Rsd,
                          const float* __restrict__ gma, const float* __restrict__ bta,
                          float* __restrict__ out,
                          __half* __restrict__ outH, __half* __restrict__ outL)
{
    int m = blockIdx.x;
    int tid = threadIdx.x;
    const float* xr = X + (size_t)m * D_MODEL;
    float v[3];
    #pragma unroll
    for (int i = 0; i < 3; i++) {
        int d = tid + 256 * i;
        v[i] = xr[d];
        if (RESID) v[i] += Rsd[(size_t)m * D_MODEL + d];
    }
    float s = blockReduce256(v[0] + v[1] + v[2]);
    float mean = s * (1.0f / 768.0f);
    float q = 0.0f;
    #pragma unroll
    for (int i = 0; i < 3; i++) { float d = v[i] - mean; q += d * d; }
    q = blockReduce256(q);
    float inv = 1.0f / sqrtf(q * (1.0f / 768.0f) + 1e-5f);
    #pragma unroll
    for (int i = 0; i < 3; i++) {
        int d = tid + 256 * i;
        float r = (v[i] - mean) * inv * gma[d] + bta[d];
        out[(size_t)m * D_MODEL + d] = r;
        if (EMITHL) {
            __half h, l; split_hl(r, h, l);
            outH[(size_t)m * D_MODEL + d] = h;
            outL[(size_t)m * D_MODEL + d] = l;
        }
    }
}

__global__ void pad_out_kernel(float* __restrict__ out2, int Sc)
{
    int i = blockIdx.x * blockDim.x + threadIdx.x;
    if (i < BATCH * Sc) {
        int b = i / Sc, s = i % Sc;
        out2[i] = (s >= g_len[b]) ? 1.0f : 0.0f;
    }
}

// ===========================================================================
static void run_split(const float* src, __half* hi, __half* lo, size_t n)
{
    int n4 = (int)(n >> 2);
    split_kernel<<<(n4 + 255) / 256, 256>>>((const float4*)src, (__half2*)hi, (__half2*)lo, n4);
}

extern "C" void kernel_launch(void* const* d_in, const int* in_sizes, int n_in,
                              void* d_out, int out_size)
{
    const float* x       = (const float*)d_in[0];
    const void*  mask    = d_in[1];
    const float* patch_w = (const float*)d_in[2];
    const float* patch_b = (const float*)d_in[3];
    const float* pos     = (const float*)d_in[4];
    const float* inw     = (const float*)d_in[5];
    const float* inb     = (const float*)d_in[6];
    const float* outw    = (const float*)d_in[7];
    const float* outb    = (const float*)d_in[8];
    const float* ln1g    = (const float*)d_in[9];
    const float* ln1b    = (const float*)d_in[10];
    const float* f1w     = (const float*)d_in[11];
    const float* f1b     = (const float*)d_in[12];
    const float* f2w     = (const float*)d_in[13];
    const float* f2b     = (const float*)d_in[14];
    const float* ln2g    = (const float*)d_in[15];
    const float* ln2b    = (const float*)d_in[16];
    const float* ng      = (const float*)d_in[17];
    const float* nb      = (const float*)d_in[18];

    int Sc; bool tup;
    if (out_size % (64 * 769) == 0 &&
        out_size / (64 * 769) >= 1 && out_size / (64 * 769) <= N_TOK) {
        Sc = out_size / (64 * 769); tup = true;
    } else {
        Sc = out_size / (64 * 768); tup = false;
    }
    if (Sc < 1) Sc = 1;
    if (Sc > N_TOK) Sc = N_TOK;
    const int M  = BATCH * Sc;
    const int MB = (M + 127) / 128;
    const int flash_smem = Sc * (64 + KS_STRIDE + 64) * 4 + 8 * 32 * 4;

    float *pX, *pQ, *pP;
    __half *ah, *al, *fh, *fl, *wqh, *wql, *woh, *wol, *w1h, *w1l, *w2h, *w2l, *wph, *wpl;
    cudaGetSymbolAddress((void**)&pX,  g_X);
    cudaGetSymbolAddress((void**)&pQ,  g_qkv);
    cudaGetSymbolAddress((void**)&pP,  g_proj);
    cudaGetSymbolAddress((void**)&ah,  g_ah);
    cudaGetSymbolAddress((void**)&al,  g_al);
    cudaGetSymbolAddress((void**)&fh,  g_fh);
    cudaGetSymbolAddress((void**)&fl,  g_fl);
    cudaGetSymbolAddress((void**)&wqh, g_wqkv_h);
    cudaGetSymbolAddress((void**)&wql, g_wqkv_l);
    cudaGetSymbolAddress((void**)&woh, g_wo_h);
    cudaGetSymbolAddress((void**)&wol, g_wo_l);
    cudaGetSymbolAddress((void**)&w1h, g_wf1_h);
    cudaGetSymbolAddress((void**)&w1l, g_wf1_l);
    cudaGetSymbolAddress((void**)&w2h, g_wf2_h);
    cudaGetSymbolAddress((void**)&w2l, g_wf2_l);
    cudaGetSymbolAddress((void**)&wph, g_wp_h);
    cudaGetSymbolAddress((void**)&wpl, g_wp_l);

    cudaFuncSetAttribute(mma_gemm_kernel, cudaFuncAttributeMaxDynamicSharedMemorySize,
                         GEMM_SMEM);
    cudaFuncSetAttribute(flash_kernel, cudaFuncAttributeMaxDynamicSharedMemorySize,
                         160000);

    // --- weight splits --------------------------------------------------------
    run_split(inw,     wqh, wql, (size_t)N_LAYERS * 3 * D_MODEL * D_MODEL);
    run_split(outw,    woh, wol, (size_t)N_LAYERS * D_MODEL * D_MODEL);
    run_split(f1w,     w1h, w1l, (size_t)N_LAYERS * FF_DIM * D_MODEL);
    run_split(f2w,     w2h, w2l, (size_t)N_LAYERS * FF_DIM * D_MODEL);
    run_split(patch_w, wph, wpl, (size_t)D_MODEL * D_MODEL);

    // --- mask parse + gather + patch embedding --------------------------------
    mask_kernel<<<1, 256>>>((const unsigned char*)mask);
    im2col_kernel<<<dim3(Sc, BATCH), 256>>>(x, Sc);
    mma_gemm_kernel<<<dim3(6, MB), 256, GEMM_SMEM>>>(
        ah, al, wph, wpl, nullptr, pX, nullptr, nullptr, D_MODEL, M, D_MODEL, 0);
    patch_epi_kernel<<<dim3(Sc, BATCH), 256>>>(patch_b, pos, Sc);

    // --- transformer layers ---------------------------------------------------
    for (int l = 0; l < N_LAYERS; l++) {
        const __half* Wqh = wqh + (size_t)l * 3 * D_MODEL * D_MODEL;
        const __half* Wql = wql + (size_t)l * 3 * D_MODEL * D_MODEL;
        const __half* Woh = woh + (size_t)l * D_MODEL * D_MODEL;
        const __half* Wol = wol + (size_t)l * D_MODEL * D_MODEL;
        const __half* W1h = w1h + (size_t)l * FF_DIM * D_MODEL;
        const __half* W1l = w1l + (size_t)l * FF_DIM * D_MODEL;
        const __half* W2h = w2h + (size_t)l * FF_DIM * D_MODEL;
        const __half* W2l = w2l + (size_t)l * FF_DIM * D_MODEL;
        const float* bqkv = inb  + (size_t)l * 3 * D_MODEL;
        const float* bo   = outb + (size_t)l * D_MODEL;
        const float* b1   = f1b  + (size_t)l * FF_DIM;
        const float* b2   = f2b  + (size_t)l * D_MODEL;

        // QKV projection (reads ah/al from patch_epi or previous ln2)
        mma_gemm_kernel<<<dim3(18, MB), 256, GEMM_SMEM>>>(
            ah, al, Wqh, Wql, bqkv, pQ, nullptr, nullptr, 3 * D_MODEL, M, D_MODEL, 1);
        // fused attention -> ah/al
        flash_kernel<<<BATCH * N_HEADS, 256, flash_smem>>>(Sc);
        // output projection
        mma_gemm_kernel<<<dim3(6, MB), 256, GEMM_SMEM>>>(
            ah, al, Woh, Wol, bo, pP, nullptr, nullptr, D_MODEL, M, D_MODEL, 1);
        // residual + LN1 -> X, ah/al
        ln_kernel<true, true><<<M, 256>>>(pX, pP, ln1g + l * D_MODEL, ln1b + l * D_MODEL,
                                          pX, ah, al);
        // FFN1 (+GELU) -> fh/fl (fp16 h/l)
        mma_gemm_kernel<<<dim3(24, MB), 256, GEMM_SMEM>>>(
            ah, al, W1h, W1l, b1, nullptr, fh, fl, FF_DIM, M, D_MODEL, 1 | 2 | 4);
        // FFN2
        mma_gemm_kernel<<<dim3(6, MB), 256, GEMM_SMEM>>>(
            fh, fl, W2h, W2l, b2, pP, nullptr, nullptr, D_MODEL, M, FF_DIM, 1);
        // residual + LN2 -> X, ah/al
        ln_kernel<true, true><<<M, 256>>>(pX, pP, ln2g + l * D_MODEL, ln2b + l * D_MODEL,
                                          pX, ah, al);
    }

    // --- final LN into d_out --------------------------------------------------
    ln_kernel<false, false><<<M, 256>>>(pX, nullptr, ng, nb, (float*)d_out,
                                        nullptr, nullptr);
    if (tup) {
        pad_out_kernel<<<(BATCH * Sc + 255) / 256, 256>>>(
            (float*)d_out + (size_t)M * D_MODEL, Sc);
    }
}

// round 9
// speedup vs baseline: 1.3355x; 1.1593x over previous
#include <cuda_runtime.h>
#include <cuda_fp16.h>
#include <math.h>
#include <stdint.h>

// ============================================================================
// Masked ViT context encoder. R8: R7 base (128x128 tiles, K-chunk 32,
// 2 CTAs/SM) + 2-term fp16 GEMM for FFN1/FFN2 (drop activation-lo side;
// QKV/proj/patch remain 3-term). mma.sync issue-rate ceiling => cut FLOPs.
// ============================================================================

#define BATCH    64
#define N_TOK    196
#define D_MODEL  768
#define N_HEADS  12
#define HEAD_DIM 64
#define N_LAYERS 12
#define FF_DIM   3072
#define M_MAX    (BATCH * N_TOK)

// flags
#define F_BIAS    1
#define F_GELU    2
#define F_OUT16   4
#define F_2TERM   8
#define F_HIONLY  16

// ---------------- scratch (device globals; no allocation allowed) -----------
__device__ int    g_order[BATCH * N_TOK];
__device__ int    g_len[BATCH];
__device__ float  g_X[(size_t)M_MAX * D_MODEL];
__device__ float  g_qkv[(size_t)M_MAX * 3 * D_MODEL];
__device__ float  g_proj[(size_t)M_MAX * D_MODEL];
// fp16 hi/lo activation buffers
__device__ __half g_ah[(size_t)M_MAX * D_MODEL];
__device__ __half g_al[(size_t)M_MAX * D_MODEL];
__device__ __half g_fh[(size_t)M_MAX * FF_DIM];
// fp16 hi/lo weights
__device__ __half g_wqkv_h[(size_t)N_LAYERS * 3 * D_MODEL * D_MODEL];
__device__ __half g_wqkv_l[(size_t)N_LAYERS * 3 * D_MODEL * D_MODEL];
__device__ __half g_wo_h[(size_t)N_LAYERS * D_MODEL * D_MODEL];
__device__ __half g_wo_l[(size_t)N_LAYERS * D_MODEL * D_MODEL];
__device__ __half g_wf1_h[(size_t)N_LAYERS * FF_DIM * D_MODEL];
__device__ __half g_wf1_l[(size_t)N_LAYERS * FF_DIM * D_MODEL];
__device__ __half g_wf2_h[(size_t)N_LAYERS * FF_DIM * D_MODEL];
__device__ __half g_wf2_l[(size_t)N_LAYERS * FF_DIM * D_MODEL];
__device__ __half g_wp_h[(size_t)D_MODEL * D_MODEL];
__device__ __half g_wp_l[(size_t)D_MODEL * D_MODEL];

// ============================================================================
// helpers
// ============================================================================
__device__ __forceinline__ uint32_t smem_u32(const void* p) {
    uint32_t a;
    asm("{ .reg .u64 t; cvta.to.shared.u64 t, %1; cvt.u32.u64 %0, t; }"
        : "=r"(a) : "l"(p));
    return a;
}
__device__ __forceinline__ void split_hl(float v, __half& h, __half& l) {
    h = __float2half(v);
    l = __float2half(v - __half2float(h));
}

#define CP_ASYNC_16(dst, src) \
    asm volatile("cp.async.cg.shared.global [%0], [%1], 16;" :: "r"(dst), "l"(src))
#define CP_COMMIT() asm volatile("cp.async.commit_group;" ::: "memory")
#define CP_WAIT(n)  asm volatile("cp.async.wait_group %0;" :: "n"(n) : "memory")

#define LDSM4(r0, r1, r2, r3, addr) \
    asm volatile("ldmatrix.sync.aligned.m8n8.x4.shared.b16 {%0,%1,%2,%3}, [%4];" \
        : "=r"(r0), "=r"(r1), "=r"(r2), "=r"(r3) : "r"(addr))

#define MMA16816(c, a, b) \
    asm volatile("mma.sync.aligned.m16n8k16.row.col.f32.f16.f16.f32 " \
        "{%0,%1,%2,%3}, {%4,%5,%6,%7}, {%8,%9}, {%0,%1,%2,%3};" \
        : "+f"((c)[0]), "+f"((c)[1]), "+f"((c)[2]), "+f"((c)[3]) \
        : "r"((a)[0]), "r"((a)[1]), "r"((a)[2]), "r"((a)[3]), \
          "r"((b)[0]), "r"((b)[1]))

// ============================================================================
// weight split: fp32 -> (hi fp16, lo fp16)
// ============================================================================
__global__ void split_kernel(const float4* __restrict__ src,
                             __half2* __restrict__ hi, __half2* __restrict__ lo, int n4)
{
    int i = blockIdx.x * blockDim.x + threadIdx.x;
    if (i >= n4) return;
    float4 v = src[i];
    __half h0, h1, h2, h3, l0, l1, l2, l3;
    split_hl(v.x, h0, l0); split_hl(v.y, h1, l1);
    split_hl(v.z, h2, l2); split_hl(v.w, h3, l3);
    hi[i * 2 + 0] = __halves2half2(h0, h1);
    hi[i * 2 + 1] = __halves2half2(h2, h3);
    lo[i * 2 + 0] = __halves2half2(l0, l1);
    lo[i * 2 + 1] = __halves2half2(l2, l3);
}

// ============================================================================
// HMMA GEMM: 3-term (AhBh+AhBl+AlBh) or 2-term (AhBh+AhBl) via F_2TERM.
// 128x128 CTA tile, K-chunk 32, cp.async double buffer (40KB stages,
// 2 CTAs/SM), ldmatrix fragments, 8 warps (4m x 2n), warp tile 32x64.
// ============================================================================
#define ROW_BYTES   80                  // 32 fp16 (64B) + 16B pad: conflict-free
#define TILE_BYTES  (128 * ROW_BYTES)   // 10240
#define STAGE_BYTES (4 * TILE_BYTES)    // 40960
#define GEMM_SMEM   (2 * STAGE_BYTES)   // 81920

__global__ void __launch_bounds__(256, 2)
mma_gemm_kernel(const __half* __restrict__ Ah, const __half* __restrict__ Al,
                const __half* __restrict__ Bh, const __half* __restrict__ Bl,
                const float* __restrict__ bias,
                float* __restrict__ C, __half* __restrict__ Ch, __half* __restrict__ Cl,
                int ldc, int M, int K, int flags)
{
    extern __shared__ char smem[];
    const uint32_t sb = smem_u32(smem);
    const int tid  = threadIdx.x;
    const int wid  = tid >> 5, lane = tid & 31;
    const int wm   = wid & 3, wn = wid >> 2;     // 4(m) x 2(n)
    const int brow = blockIdx.y * 128;
    const int bcol = blockIdx.x * 128;
    const bool twoterm = (flags & F_2TERM) != 0;

    float acc[2][8][4];
    #pragma unroll
    for (int mt = 0; mt < 2; mt++)
        #pragma unroll
        for (int nt = 0; nt < 8; nt++)
            #pragma unroll
            for (int i = 0; i < 4; i++) acc[mt][nt][i] = 0.0f;

    const int nC = K >> 5;

    // 2048 16B-chunks per stage; 8 per thread (Al tile skipped in 2-term mode).
    auto load_chunk = [&](int c, int buf) {
        const int k0 = c << 5;
        const uint32_t tb = sb + (uint32_t)buf * STAGE_BYTES;
        #pragma unroll
        for (int j = 0; j < 8; j++) {
            int idx = tid + (j << 8);
            int op  = idx >> 9;           // 0=Ah 1=Al 2=Bh 3=Bl
            if (twoterm && op == 1) continue;
            int rem = idx & 511;
            int r   = rem >> 2;           // row 0..127
            int q   = rem & 3;            // 16B chunk (8 halves)
            const __half* gp;
            if (op < 2) {
                int gr = brow + r;
                if (gr >= M) gr = M - 1;
                gp = (op ? Al : Ah) + (size_t)gr * K + k0 + (q << 3);
            } else {
                int gn = bcol + r;
                gp = (op == 3 ? Bl : Bh) + (size_t)gn * K + k0 + (q << 3);
            }
            uint32_t dst = tb + (uint32_t)op * TILE_BYTES + (uint32_t)r * ROW_BYTES + (q << 4);
            CP_ASYNC_16(dst, gp);
        }
        CP_COMMIT();
    };

    load_chunk(0, 0);

    // intra-tile ldmatrix offsets
    const uint32_t a_off = (uint32_t)(wm * 32 + (lane & 15)) * ROW_BYTES
                         + (uint32_t)((lane >> 4) << 3) * 2;           // + ks*2
    const int      b_mm  = lane >> 3;
    const uint32_t b_row_off = (uint32_t)(wn * 64 + ((b_mm >> 1) << 3) + (lane & 7)) * ROW_BYTES;
    const uint32_t b_k_off   = (uint32_t)((b_mm & 1) << 3) * 2;

    for (int c = 0; c < nC; c++) {
        const int buf = c & 1;
        if (c + 1 < nC) { load_chunk(c + 1, buf ^ 1); CP_WAIT(1); }
        else            { CP_WAIT(0); }
        __syncthreads();

        const uint32_t At  = sb + (uint32_t)buf * STAGE_BYTES;
        const uint32_t Alt = At + TILE_BYTES;
        const uint32_t Bt  = At + 2 * TILE_BYTES;
        const uint32_t Blt = At + 3 * TILE_BYTES;

        #pragma unroll
        for (int ks = 0; ks < 32; ks += 16) {
            uint32_t ah[2][4], bh[8][2], bl[8][2];
            const uint32_t ksb = (uint32_t)ks * 2;
            LDSM4(ah[0][0], ah[0][1], ah[0][2], ah[0][3], At  + a_off + ksb);
            LDSM4(ah[1][0], ah[1][1], ah[1][2], ah[1][3], At  + a_off + ksb + 16 * ROW_BYTES);
            #pragma unroll
            for (int g = 0; g < 4; g++) {
                uint32_t off = b_row_off + (uint32_t)(g * 16) * ROW_BYTES + b_k_off + ksb;
                LDSM4(bh[2*g][0], bh[2*g][1], bh[2*g+1][0], bh[2*g+1][1], Bt  + off);
                LDSM4(bl[2*g][0], bl[2*g][1], bl[2*g+1][0], bl[2*g+1][1], Blt + off);
            }
            #pragma unroll
            for (int mt = 0; mt < 2; mt++)
                #pragma unroll
                for (int nt = 0; nt < 8; nt++) MMA16816(acc[mt][nt], ah[mt], bh[nt]);
            #pragma unroll
            for (int mt = 0; mt < 2; mt++)
                #pragma unroll
                for (int nt = 0; nt < 8; nt++) MMA16816(acc[mt][nt], ah[mt], bl[nt]);
            if (!twoterm) {
                uint32_t al[2][4];
                LDSM4(al[0][0], al[0][1], al[0][2], al[0][3], Alt + a_off + ksb);
                LDSM4(al[1][0], al[1][1], al[1][2], al[1][3], Alt + a_off + ksb + 16 * ROW_BYTES);
                #pragma unroll
                for (int mt = 0; mt < 2; mt++)
                    #pragma unroll
                    for (int nt = 0; nt < 8; nt++) MMA16816(acc[mt][nt], al[mt], bh[nt]);
            }
        }
        __syncthreads();
    }

    // ---- epilogue -----------------------------------------------------------
    const int lr = lane >> 2, lc = (lane & 3) * 2;
    #pragma unroll
    for (int mt = 0; mt < 2; mt++) {
        int r0 = brow + wm * 32 + mt * 16 + lr;
        #pragma unroll
        for (int nt = 0; nt < 8; nt++) {
            int cc = bcol + wn * 64 + nt * 8 + lc;
            float bv0 = 0.0f, bv1 = 0.0f;
            if (flags & F_BIAS) { bv0 = bias[cc]; bv1 = bias[cc + 1]; }
            #pragma unroll
            for (int half = 0; half < 2; half++) {
                int r = r0 + half * 8;
                if (r < M) {
                    float v0 = acc[mt][nt][half * 2 + 0] + bv0;
                    float v1 = acc[mt][nt][half * 2 + 1] + bv1;
                    if (flags & F_GELU) {
                        v0 = 0.5f * v0 * (1.0f + erff(v0 * 0.70710678118654752440f));
                        v1 = 0.5f * v1 * (1.0f + erff(v1 * 0.70710678118654752440f));
                    }
                    if (flags & F_OUT16) {
                        __half h0, h1, l0, l1;
                        split_hl(v0, h0, l0); split_hl(v1, h1, l1);
                        *(__half2*)(Ch + (size_t)r * ldc + cc) = __halves2half2(h0, h1);
                        if (!(flags & F_HIONLY))
                            *(__half2*)(Cl + (size_t)r * ldc + cc) = __halves2half2(l0, l1);
                    } else {
                        *(float2*)(C + (size_t)r * ldc + cc) = make_float2(v0, v1);
                    }
                }
            }
        }
    }
}

// ============================================================================
// mask parse (parallel detection)
// ============================================================================
__global__ void mask_kernel(const unsigned char* __restrict__ mp)
{
    int tid = threadIdx.x;   // 256
    bool big = false, misal = false;
    for (int i = tid; i < BATCH * N_TOK; i += 256) {
        unsigned char v = mp[i];
        if (v >= 2) big = true;
        else if (v && (i & 3)) misal = true;
    }
    int anybig = __syncthreads_or(big ? 1 : 0);
    int anymis = __syncthreads_or(misal ? 1 : 0);
    int type = anybig ? 2 : (anymis ? 1 : 0);
    int b = tid;
    if (b < BATCH) {
        int cnt = 0;
        for (int t = 0; t < N_TOK; t++) {
            int idx = b * N_TOK + t;
            bool m;
            if (type == 2)      m = (((const float*)mp)[idx] != 0.0f);
            else if (type == 1) m = (mp[idx] != 0);
            else                m = (((const int*)mp)[idx] != 0);
            if (m) { g_order[b * N_TOK + cnt] = t; cnt++; }
        }
        g_len[b] = cnt;
    }
}

// ============================================================================
// im2col gather, writing fp16 h/l directly (patch GEMM inputs)
// ============================================================================
__global__ void im2col_kernel(const float* __restrict__ x, int Sc)
{
    int s = blockIdx.x, b = blockIdx.y;
    int m = b * Sc + s;
    __half* dh = g_ah + (size_t)m * D_MODEL;
    __half* dl = g_al + (size_t)m * D_MODEL;
    if (s >= g_len[b]) {
        for (int k = threadIdx.x; k < D_MODEL; k += blockDim.x) {
            dh[k] = __float2half(0.0f); dl[k] = __float2half(0.0f);
        }
        return;
    }
    int t = g_order[b * N_TOK + s];
    int gy = t / 14, gx = t % 14;
    const float* xb = x + (size_t)b * 3 * 224 * 224;
    for (int k = threadIdx.x; k < D_MODEL; k += blockDim.x) {
        int c = k >> 8, r = (k >> 4) & 15, cc = k & 15;
        float v = xb[((size_t)c * 224 + (gy * 16 + r)) * 224 + (gx * 16 + cc)];
        __half h, l; split_hl(v, h, l);
        dh[k] = h; dl[k] = l;
    }
}

// patch epilogue: X += patch_b + pos; emit h/l for QKV GEMM; zero pad rows.
__global__ void patch_epi_kernel(const float* __restrict__ pb,
                                 const float* __restrict__ pos, int Sc)
{
    int s = blockIdx.x, b = blockIdx.y;
    int m = b * Sc + s;
    float* row = g_X + (size_t)m * D_MODEL;
    __half* dh = g_ah + (size_t)m * D_MODEL;
    __half* dl = g_al + (size_t)m * D_MODEL;
    if (s >= g_len[b]) {
        for (int d = threadIdx.x; d < D_MODEL; d += blockDim.x) {
            row[d] = 0.0f;
            dh[d] = __float2half(0.0f); dl[d] = __float2half(0.0f);
        }
        return;
    }
    int t = g_order[b * N_TOK + s];
    const float* pr = pos + (size_t)t * D_MODEL;
    for (int d = threadIdx.x; d < D_MODEL; d += blockDim.x) {
        float v = row[d] + pb[d] + pr[d];
        row[d] = v;
        __half h, l; split_hl(v, h, l);
        dh[d] = h; dl[d] = l;
    }
}

// ============================================================================
// Fused flash attention (fp32), one CTA per (b,h). Whole Q/K/V in SMEM.
// Output written as fp16 h/l (proj GEMM inputs).
// ============================================================================
#define KS_STRIDE 65

__global__ void __launch_bounds__(256, 1)
flash_kernel(int Sc)
{
    extern __shared__ float fs[];
    float* qs = fs;                       // [Sc][64]
    float* ks = qs + Sc * 64;             // [Sc][65]
    float* vs = ks + Sc * KS_STRIDE;      // [Sc][64]
    float* es = vs + Sc * 64;             // [8][32]

    const int b = blockIdx.x / N_HEADS, h = blockIdx.x % N_HEADS;
    const int len = g_len[b];
    const int tid = threadIdx.x, lane = tid & 31, wid = tid >> 5;
    const size_t base = (size_t)(b * Sc) * (3 * D_MODEL) + h * HEAD_DIM;

    for (int idx = tid; idx < Sc * 64; idx += 256) {
        int r = idx >> 6, d = idx & 63;
        size_t g = base + (size_t)r * (3 * D_MODEL) + d;
        qs[idx] = g_qkv[g];
        ks[r * KS_STRIDE + d] = g_qkv[g + D_MODEL];
        vs[idx] = g_qkv[g + 2 * D_MODEL];
    }
    __syncthreads();

    float* ew = es + wid * 32;
    for (int q = wid; q < Sc; q += 8) {
        const float* qrow = qs + q * 64;
        float m = -3.4e38f, l = 0.0f;
        float o0a = 0.f, o0b = 0.f, o1a = 0.f, o1b = 0.f;
        for (int j0 = 0; j0 < len; j0 += 32) {
            int j = j0 + lane;
            int jj = (j < len) ? j : (len - 1);
            const float* krow = ks + jj * KS_STRIDE;
            float s0 = 0.f, s1 = 0.f, s2 = 0.f, s3 = 0.f;
            #pragma unroll
            for (int d = 0; d < 64; d += 4) {
                s0 += qrow[d + 0] * krow[d + 0];
                s1 += qrow[d + 1] * krow[d + 1];
                s2 += qrow[d + 2] * krow[d + 2];
                s3 += qrow[d + 3] * krow[d + 3];
            }
            float s = ((s0 + s1) + (s2 + s3)) * 0.125f;
            if (j >= len) s = -3.4e38f;
            float tmax = s;
            #pragma unroll
            for (int o = 16; o; o >>= 1) tmax = fmaxf(tmax, __shfl_xor_sync(0xffffffffu, tmax, o));
            float mnew = fmaxf(m, tmax);
            float scale = __expf(m - mnew);
            float e = (j < len) ? __expf(s - mnew) : 0.0f;
            float esum = e;
            #pragma unroll
            for (int o = 16; o; o >>= 1) esum += __shfl_xor_sync(0xffffffffu, esum, o);
            l = l * scale + esum;
            m = mnew;
            o0a *= scale; o0b *= scale; o1a *= scale; o1b *= scale;
            ew[lane] = e;
            __syncwarp();
            int jmax = (len - j0 < 32) ? (len - j0) : 32;
            int j2 = 0;
            for (; j2 + 2 <= jmax; j2 += 2) {
                float e0 = ew[j2], e1 = ew[j2 + 1];
                const float* v0 = vs + (j0 + j2) * 64;
                const float* v1 = v0 + 64;
                o0a += e0 * v0[lane];      o1a += e0 * v0[lane + 32];
                o0b += e1 * v1[lane];      o1b += e1 * v1[lane + 32];
            }
            if (j2 < jmax) {
                float e0 = ew[j2];
                const float* v0 = vs + (j0 + j2) * 64;
                o0a += e0 * v0[lane];      o1a += e0 * v0[lane + 32];
            }
            __syncwarp();
        }
        float inv = 1.0f / l;
        float r0 = (o0a + o0b) * inv, r1 = (o1a + o1b) * inv;
        size_t orow = (size_t)(b * Sc + q) * D_MODEL + h * HEAD_DIM;
        __half h0, l0, h1, l1;
        split_hl(r0, h0, l0); split_hl(r1, h1, l1);
        g_ah[orow + lane]      = h0;  g_al[orow + lane]      = l0;
        g_ah[orow + lane + 32] = h1;  g_al[orow + lane + 32] = l1;
    }
}

// ============================================================================
// LayerNorm (optionally +residual); optionally emits fp16 h/l alongside fp32.
// ============================================================================
__device__ __forceinline__ float blockReduce256(float v)
{
    __shared__ float sh[8];
    __syncthreads();
    #pragma unroll
    for (int o = 16; o; o >>= 1) v += __shfl_down_sync(0xffffffffu, v, o);
    if ((threadIdx.x & 31) == 0) sh[threadIdx.x >> 5] = v;
    __syncthreads();
    return sh[0] + sh[1] + sh[2] + sh[3] + sh[4] + sh[5] + sh[6] + sh[7];
}

template<bool RESID, bool EMITHL>
__global__ void ln_kernel(const float* __restrict__ X, const float* __restrict__ Rsd,
                          const float* __restrict__ gma, const float* __restrict__ bta,
                          float* __restrict__ out,
                          __half* __restrict__ outH, __half* __restrict__ outL)
{
    int m = blockIdx.x;
    int tid = threadIdx.x;
    const float* xr = X + (size_t)m * D_MODEL;
    float v[3];
    #pragma unroll
    for (int i = 0; i < 3; i++) {
        int d = tid + 256 * i;
        v[i] = xr[d];
        if (RESID) v[i] += Rsd[(size_t)m * D_MODEL + d];
    }
    float s = blockReduce256(v[0] + v[1] + v[2]);
    float mean = s * (1.0f / 768.0f);
    float q = 0.0f;
    #pragma unroll
    for (int i = 0; i < 3; i++) { float d = v[i] - mean; q += d * d; }
    q = blockReduce256(q);
    float inv = 1.0f / sqrtf(q * (1.0f / 768.0f) + 1e-5f);
    #pragma unroll
    for (int i = 0; i < 3; i++) {
        int d = tid + 256 * i;
        float r = (v[i] - mean) * inv * gma[d] + bta[d];
        out[(size_t)m * D_MODEL + d] = r;
        if (EMITHL) {
            __half h, l; split_hl(r, h, l);
            outH[(size_t)m * D_MODEL + d] = h;
            outL[(size_t)m * D_MODEL + d] = l;
        }
    }
}

__global__ void pad_out_kernel(float* __restrict__ out2, int Sc)
{
    int i = blockIdx.x * blockDim.x + threadIdx.x;
    if (i < BATCH * Sc) {
        int b = i / Sc, s = i % Sc;
        out2[i] = (s >= g_len[b]) ? 1.0f : 0.0f;
    }
}

// ===========================================================================
static void run_split(const float* src, __half* hi, __half* lo, size_t n)
{
    int n4 = (int)(n >> 2);
    split_kernel<<<(n4 + 255) / 256, 256>>>((const float4*)src, (__half2*)hi, (__half2*)lo, n4);
}

extern "C" void kernel_launch(void* const* d_in, const int* in_sizes, int n_in,
                              void* d_out, int out_size)
{
    const float* x       = (const float*)d_in[0];
    const void*  mask    = d_in[1];
    const float* patch_w = (const float*)d_in[2];
    const float* patch_b = (const float*)d_in[3];
    const float* pos     = (const float*)d_in[4];
    const float* inw     = (const float*)d_in[5];
    const float* inb     = (const float*)d_in[6];
    const float* outw    = (const float*)d_in[7];
    const float* outb    = (const float*)d_in[8];
    const float* ln1g    = (const float*)d_in[9];
    const float* ln1b    = (const float*)d_in[10];
    const float* f1w     = (const float*)d_in[11];
    const float* f1b     = (const float*)d_in[12];
    const float* f2w     = (const float*)d_in[13];
    const float* f2b     = (const float*)d_in[14];
    const float* ln2g    = (const float*)d_in[15];
    const float* ln2b    = (const float*)d_in[16];
    const float* ng      = (const float*)d_in[17];
    const float* nb      = (const float*)d_in[18];

    int Sc; bool tup;
    if (out_size % (64 * 769) == 0 &&
        out_size / (64 * 769) >= 1 && out_size / (64 * 769) <= N_TOK) {
        Sc = out_size / (64 * 769); tup = true;
    } else {
        Sc = out_size / (64 * 768); tup = false;
    }
    if (Sc < 1) Sc = 1;
    if (Sc > N_TOK) Sc = N_TOK;
    const int M  = BATCH * Sc;
    const int MB = (M + 127) / 128;
    const int flash_smem = Sc * (64 + KS_STRIDE + 64) * 4 + 8 * 32 * 4;

    float *pX, *pQ, *pP;
    __half *ah, *al, *fh, *wqh, *wql, *woh, *wol, *w1h, *w1l, *w2h, *w2l, *wph, *wpl;
    cudaGetSymbolAddress((void**)&pX,  g_X);
    cudaGetSymbolAddress((void**)&pQ,  g_qkv);
    cudaGetSymbolAddress((void**)&pP,  g_proj);
    cudaGetSymbolAddress((void**)&ah,  g_ah);
    cudaGetSymbolAddress((void**)&al,  g_al);
    cudaGetSymbolAddress((void**)&fh,  g_fh);
    cudaGetSymbolAddress((void**)&wqh, g_wqkv_h);
    cudaGetSymbolAddress((void**)&wql, g_wqkv_l);
    cudaGetSymbolAddress((void**)&woh, g_wo_h);
    cudaGetSymbolAddress((void**)&wol, g_wo_l);
    cudaGetSymbolAddress((void**)&w1h, g_wf1_h);
    cudaGetSymbolAddress((void**)&w1l, g_wf1_l);
    cudaGetSymbolAddress((void**)&w2h, g_wf2_h);
    cudaGetSymbolAddress((void**)&w2l, g_wf2_l);
    cudaGetSymbolAddress((void**)&wph, g_wp_h);
    cudaGetSymbolAddress((void**)&wpl, g_wp_l);

    cudaFuncSetAttribute(mma_gemm_kernel, cudaFuncAttributeMaxDynamicSharedMemorySize,
                         GEMM_SMEM);
    cudaFuncSetAttribute(flash_kernel, cudaFuncAttributeMaxDynamicSharedMemorySize,
                         160000);

    // --- weight splits --------------------------------------------------------
    run_split(inw,     wqh, wql, (size_t)N_LAYERS * 3 * D_MODEL * D_MODEL);
    run_split(outw,    woh, wol, (size_t)N_LAYERS * D_MODEL * D_MODEL);
    run_split(f1w,     w1h, w1l, (size_t)N_LAYERS * FF_DIM * D_MODEL);
    run_split(f2w,     w2h, w2l, (size_t)N_LAYERS * FF_DIM * D_MODEL);
    run_split(patch_w, wph, wpl, (size_t)D_MODEL * D_MODEL);

    // --- mask parse + gather + patch embedding --------------------------------
    mask_kernel<<<1, 256>>>((const unsigned char*)mask);
    im2col_kernel<<<dim3(Sc, BATCH), 256>>>(x, Sc);
    mma_gemm_kernel<<<dim3(6, MB), 256, GEMM_SMEM>>>(
        ah, al, wph, wpl, nullptr, pX, nullptr, nullptr, D_MODEL, M, D_MODEL, 0);
    patch_epi_kernel<<<dim3(Sc, BATCH), 256>>>(patch_b, pos, Sc);

    // --- transformer layers ---------------------------------------------------
    for (int l = 0; l < N_LAYERS; l++) {
        const __half* Wqh = wqh + (size_t)l * 3 * D_MODEL * D_MODEL;
        const __half* Wql = wql + (size_t)l * 3 * D_MODEL * D_MODEL;
        const __half* Woh = woh + (size_t)l * D_MODEL * D_MODEL;
        const __half* Wol = wol + (size_t)l * D_MODEL * D_MODEL;
        const __half* W1h = w1h + (size_t)l * FF_DIM * D_MODEL;
        const __half* W1l = w1l + (size_t)l * FF_DIM * D_MODEL;
        const __half* W2h = w2h + (size_t)l * FF_DIM * D_MODEL;
        const __half* W2l = w2l + (size_t)l * FF_DIM * D_MODEL;
        const float* bqkv = inb  + (size_t)l * 3 * D_MODEL;
        const float* bo   = outb + (size_t)l * D_MODEL;
        const float* b1   = f1b  + (size_t)l * FF_DIM;
        const float* b2   = f2b  + (size_t)l * D_MODEL;

        // QKV projection (3-term)
        mma_gemm_kernel<<<dim3(18, MB), 256, GEMM_SMEM>>>(
            ah, al, Wqh, Wql, bqkv, pQ, nullptr, nullptr, 3 * D_MODEL, M, D_MODEL,
            F_BIAS);
        // fused attention -> ah/al
        flash_kernel<<<BATCH * N_HEADS, 256, flash_smem>>>(Sc);
        // output projection (3-term)
        mma_gemm_kernel<<<dim3(6, MB), 256, GEMM_SMEM>>>(
            ah, al, Woh, Wol, bo, pP, nullptr, nullptr, D_MODEL, M, D_MODEL,
            F_BIAS);
        // residual + LN1 -> X, ah/al
        ln_kernel<true, true><<<M, 256>>>(pX, pP, ln1g + l * D_MODEL, ln1b + l * D_MODEL,
                                          pX, ah, al);
        // FFN1 (+GELU), 2-term, fp16 hi-only output -> fh
        mma_gemm_kernel<<<dim3(24, MB), 256, GEMM_SMEM>>>(
            ah, nullptr, W1h, W1l, b1, nullptr, fh, nullptr, FF_DIM, M, D_MODEL,
            F_BIAS | F_GELU | F_OUT16 | F_2TERM | F_HIONLY);
        // FFN2, 2-term (A = fh)
        mma_gemm_kernel<<<dim3(6, MB), 256, GEMM_SMEM>>>(
            fh, nullptr, W2h, W2l, b2, pP, nullptr, nullptr, D_MODEL, M, FF_DIM,
            F_BIAS | F_2TERM);
        // residual + LN2 -> X, ah/al
        ln_kernel<true, true><<<M, 256>>>(pX, pP, ln2g + l * D_MODEL, ln2b + l * D_MODEL,
                                          pX, ah, al);
    }

    // --- final LN into d_out --------------------------------------------------
    ln_kernel<false, false><<<M, 256>>>(pX, nullptr, ng, nb, (float*)d_out,
                                        nullptr, nullptr);
    if (tup) {
        pad_out_kernel<<<(BATCH * Sc + 255) / 256, 256>>>(
            (float*)d_out + (size_t)M * D_MODEL, Sc);
    }
}

// round 12
// speedup vs baseline: 1.4515x; 1.0868x over previous
#include <cuda_runtime.h>
#include <cuda_fp16.h>
#include <math.h>
#include <stdint.h>

// ============================================================================
// Masked ViT context encoder. R9: 2-term fp16 GEMM (AhBh + AhBl) for QKV,
// proj, FFN1, FFN2 (patch GEMM stays 3-term). 128x128 tiles, K-chunk 32,
// 2 CTAs/SM, cp.async double buffer, ldmatrix. Fused flash attention (fp32).
// ============================================================================

#define BATCH    64
#define N_TOK    196
#define D_MODEL  768
#define N_HEADS  12
#define HEAD_DIM 64
#define N_LAYERS 12
#define FF_DIM   3072
#define M_MAX    (BATCH * N_TOK)

// flags
#define F_BIAS    1
#define F_GELU    2
#define F_OUT16   4
#define F_2TERM   8
#define F_HIONLY  16

// ---------------- scratch (device globals; no allocation allowed) -----------
__device__ int    g_order[BATCH * N_TOK];
__device__ int    g_len[BATCH];
__device__ float  g_X[(size_t)M_MAX * D_MODEL];
__device__ float  g_qkv[(size_t)M_MAX * 3 * D_MODEL];
__device__ float  g_proj[(size_t)M_MAX * D_MODEL];
// fp16 hi/lo activation buffers
__device__ __half g_ah[(size_t)M_MAX * D_MODEL];
__device__ __half g_al[(size_t)M_MAX * D_MODEL];
__device__ __half g_fh[(size_t)M_MAX * FF_DIM];
// fp16 hi/lo weights
__device__ __half g_wqkv_h[(size_t)N_LAYERS * 3 * D_MODEL * D_MODEL];
__device__ __half g_wqkv_l[(size_t)N_LAYERS * 3 * D_MODEL * D_MODEL];
__device__ __half g_wo_h[(size_t)N_LAYERS * D_MODEL * D_MODEL];
__device__ __half g_wo_l[(size_t)N_LAYERS * D_MODEL * D_MODEL];
__device__ __half g_wf1_h[(size_t)N_LAYERS * FF_DIM * D_MODEL];
__device__ __half g_wf1_l[(size_t)N_LAYERS * FF_DIM * D_MODEL];
__device__ __half g_wf2_h[(size_t)N_LAYERS * FF_DIM * D_MODEL];
__device__ __half g_wf2_l[(size_t)N_LAYERS * FF_DIM * D_MODEL];
__device__ __half g_wp_h[(size_t)D_MODEL * D_MODEL];
__device__ __half g_wp_l[(size_t)D_MODEL * D_MODEL];

// ============================================================================
// helpers
// ============================================================================
__device__ __forceinline__ uint32_t smem_u32(const void* p) {
    uint32_t a;
    asm("{ .reg .u64 t; cvta.to.shared.u64 t, %1; cvt.u32.u64 %0, t; }"
        : "=r"(a) : "l"(p));
    return a;
}
__device__ __forceinline__ void split_hl(float v, __half& h, __half& l) {
    h = __float2half(v);
    l = __float2half(v - __half2float(h));
}

#define CP_ASYNC_16(dst, src) \
    asm volatile("cp.async.cg.shared.global [%0], [%1], 16;" :: "r"(dst), "l"(src))
#define CP_COMMIT() asm volatile("cp.async.commit_group;" ::: "memory")
#define CP_WAIT(n)  asm volatile("cp.async.wait_group %0;" :: "n"(n) : "memory")

#define LDSM4(r0, r1, r2, r3, addr) \
    asm volatile("ldmatrix.sync.aligned.m8n8.x4.shared.b16 {%0,%1,%2,%3}, [%4];" \
        : "=r"(r0), "=r"(r1), "=r"(r2), "=r"(r3) : "r"(addr))

#define MMA16816(c, a, b) \
    asm volatile("mma.sync.aligned.m16n8k16.row.col.f32.f16.f16.f32 " \
        "{%0,%1,%2,%3}, {%4,%5,%6,%7}, {%8,%9}, {%0,%1,%2,%3};" \
        : "+f"((c)[0]), "+f"((c)[1]), "+f"((c)[2]), "+f"((c)[3]) \
        : "r"((a)[0]), "r"((a)[1]), "r"((a)[2]), "r"((a)[3]), \
          "r"((b)[0]), "r"((b)[1]))

// ============================================================================
// weight split: fp32 -> (hi fp16, lo fp16)
// ============================================================================
__global__ void split_kernel(const float4* __restrict__ src,
                             __half2* __restrict__ hi, __half2* __restrict__ lo, int n4)
{
    int i = blockIdx.x * blockDim.x + threadIdx.x;
    if (i >= n4) return;
    float4 v = src[i];
    __half h0, h1, h2, h3, l0, l1, l2, l3;
    split_hl(v.x, h0, l0); split_hl(v.y, h1, l1);
    split_hl(v.z, h2, l2); split_hl(v.w, h3, l3);
    hi[i * 2 + 0] = __halves2half2(h0, h1);
    hi[i * 2 + 1] = __halves2half2(h2, h3);
    lo[i * 2 + 0] = __halves2half2(l0, l1);
    lo[i * 2 + 1] = __halves2half2(l2, l3);
}

// ============================================================================
// HMMA GEMM: 3-term (AhBh+AhBl+AlBh) or 2-term (AhBh+AhBl) via F_2TERM.
// 128x128 CTA tile, K-chunk 32, cp.async double buffer (40KB stages,
// 2 CTAs/SM), ldmatrix fragments, 8 warps (4m x 2n), warp tile 32x64.
// ============================================================================
#define ROW_BYTES   80                  // 32 fp16 (64B) + 16B pad: conflict-free
#define TILE_BYTES  (128 * ROW_BYTES)   // 10240
#define STAGE_BYTES (4 * TILE_BYTES)    // 40960
#define GEMM_SMEM   (2 * STAGE_BYTES)   // 81920

__global__ void __launch_bounds__(256, 2)
mma_gemm_kernel(const __half* __restrict__ Ah, const __half* __restrict__ Al,
                const __half* __restrict__ Bh, const __half* __restrict__ Bl,
                const float* __restrict__ bias,
                float* __restrict__ C, __half* __restrict__ Ch, __half* __restrict__ Cl,
                int ldc, int M, int K, int flags)
{
    extern __shared__ char smem[];
    const uint32_t sb = smem_u32(smem);
    const int tid  = threadIdx.x;
    const int wid  = tid >> 5, lane = tid & 31;
    const int wm   = wid & 3, wn = wid >> 2;     // 4(m) x 2(n)
    const int brow = blockIdx.y * 128;
    const int bcol = blockIdx.x * 128;
    const bool twoterm = (flags & F_2TERM) != 0;

    float acc[2][8][4];
    #pragma unroll
    for (int mt = 0; mt < 2; mt++)
        #pragma unroll
        for (int nt = 0; nt < 8; nt++)
            #pragma unroll
            for (int i = 0; i < 4; i++) acc[mt][nt][i] = 0.0f;

    const int nC = K >> 5;

    // 2048 16B-chunks per stage; 8 per thread (Al tile skipped in 2-term mode).
    auto load_chunk = [&](int c, int buf) {
        const int k0 = c << 5;
        const uint32_t tb = sb + (uint32_t)buf * STAGE_BYTES;
        #pragma unroll
        for (int j = 0; j < 8; j++) {
            int idx = tid + (j << 8);
            int op  = idx >> 9;           // 0=Ah 1=Al 2=Bh 3=Bl
            if (twoterm && op == 1) continue;
            int rem = idx & 511;
            int r   = rem >> 2;           // row 0..127
            int q   = rem & 3;            // 16B chunk (8 halves)
            const __half* gp;
            if (op < 2) {
                int gr = brow + r;
                if (gr >= M) gr = M - 1;
                gp = (op ? Al : Ah) + (size_t)gr * K + k0 + (q << 3);
            } else {
                int gn = bcol + r;
                gp = (op == 3 ? Bl : Bh) + (size_t)gn * K + k0 + (q << 3);
            }
            uint32_t dst = tb + (uint32_t)op * TILE_BYTES + (uint32_t)r * ROW_BYTES + (q << 4);
            CP_ASYNC_16(dst, gp);
        }
        CP_COMMIT();
    };

    load_chunk(0, 0);

    // intra-tile ldmatrix offsets
    const uint32_t a_off = (uint32_t)(wm * 32 + (lane & 15)) * ROW_BYTES
                         + (uint32_t)((lane >> 4) << 3) * 2;           // + ks*2
    const int      b_mm  = lane >> 3;
    const uint32_t b_row_off = (uint32_t)(wn * 64 + ((b_mm >> 1) << 3) + (lane & 7)) * ROW_BYTES;
    const uint32_t b_k_off   = (uint32_t)((b_mm & 1) << 3) * 2;

    for (int c = 0; c < nC; c++) {
        const int buf = c & 1;
        if (c + 1 < nC) { load_chunk(c + 1, buf ^ 1); CP_WAIT(1); }
        else            { CP_WAIT(0); }
        __syncthreads();

        const uint32_t At  = sb + (uint32_t)buf * STAGE_BYTES;
        const uint32_t Alt = At + TILE_BYTES;
        const uint32_t Bt  = At + 2 * TILE_BYTES;
        const uint32_t Blt = At + 3 * TILE_BYTES;

        #pragma unroll
        for (int ks = 0; ks < 32; ks += 16) {
            uint32_t ah[2][4], bh[8][2], bl[8][2];
            const uint32_t ksb = (uint32_t)ks * 2;
            LDSM4(ah[0][0], ah[0][1], ah[0][2], ah[0][3], At  + a_off + ksb);
            LDSM4(ah[1][0], ah[1][1], ah[1][2], ah[1][3], At  + a_off + ksb + 16 * ROW_BYTES);
            #pragma unroll
            for (int g = 0; g < 4; g++) {
                uint32_t off = b_row_off + (uint32_t)(g * 16) * ROW_BYTES + b_k_off + ksb;
                LDSM4(bh[2*g][0], bh[2*g][1], bh[2*g+1][0], bh[2*g+1][1], Bt  + off);
                LDSM4(bl[2*g][0], bl[2*g][1], bl[2*g+1][0], bl[2*g+1][1], Blt + off);
            }
            #pragma unroll
            for (int mt = 0; mt < 2; mt++)
                #pragma unroll
                for (int nt = 0; nt < 8; nt++) MMA16816(acc[mt][nt], ah[mt], bh[nt]);
            #pragma unroll
            for (int mt = 0; mt < 2; mt++)
                #pragma unroll
                for (int nt = 0; nt < 8; nt++) MMA16816(acc[mt][nt], ah[mt], bl[nt]);
            if (!twoterm) {
                uint32_t al[2][4];
                LDSM4(al[0][0], al[0][1], al[0][2], al[0][3], Alt + a_off + ksb);
                LDSM4(al[1][0], al[1][1], al[1][2], al[1][3], Alt + a_off + ksb + 16 * ROW_BYTES);
                #pragma unroll
                for (int mt = 0; mt < 2; mt++)
                    #pragma unroll
                    for (int nt = 0; nt < 8; nt++) MMA16816(acc[mt][nt], al[mt], bh[nt]);
            }
        }
        __syncthreads();
    }

    // ---- epilogue -----------------------------------------------------------
    const int lr = lane >> 2, lc = (lane & 3) * 2;
    #pragma unroll
    for (int mt = 0; mt < 2; mt++) {
        int r0 = brow + wm * 32 + mt * 16 + lr;
        #pragma unroll
        for (int nt = 0; nt < 8; nt++) {
            int cc = bcol + wn * 64 + nt * 8 + lc;
            float bv0 = 0.0f, bv1 = 0.0f;
            if (flags & F_BIAS) { bv0 = bias[cc]; bv1 = bias[cc + 1]; }
            #pragma unroll
            for (int half = 0; half < 2; half++) {
                int r = r0 + half * 8;
                if (r < M) {
                    float v0 = acc[mt][nt][half * 2 + 0] + bv0;
                    float v1 = acc[mt][nt][half * 2 + 1] + bv1;
                    if (flags & F_GELU) {
                        v0 = 0.5f * v0 * (1.0f + erff(v0 * 0.70710678118654752440f));
                        v1 = 0.5f * v1 * (1.0f + erff(v1 * 0.70710678118654752440f));
                    }
                    if (flags & F_OUT16) {
                        __half h0, h1, l0, l1;
                        split_hl(v0, h0, l0); split_hl(v1, h1, l1);
                        *(__half2*)(Ch + (size_t)r * ldc + cc) = __halves2half2(h0, h1);
                        if (!(flags & F_HIONLY))
                            *(__half2*)(Cl + (size_t)r * ldc + cc) = __halves2half2(l0, l1);
                    } else {
                        *(float2*)(C + (size_t)r * ldc + cc) = make_float2(v0, v1);
                    }
                }
            }
        }
    }
}

// ============================================================================
// mask parse (parallel detection)
// ============================================================================
__global__ void mask_kernel(const unsigned char* __restrict__ mp)
{
    int tid = threadIdx.x;   // 256
    bool big = false, misal = false;
    for (int i = tid; i < BATCH * N_TOK; i += 256) {
        unsigned char v = mp[i];
        if (v >= 2) big = true;
        else if (v && (i & 3)) misal = true;
    }
    int anybig = __syncthreads_or(big ? 1 : 0);
    int anymis = __syncthreads_or(misal ? 1 : 0);
    int type = anybig ? 2 : (anymis ? 1 : 0);
    int b = tid;
    if (b < BATCH) {
        int cnt = 0;
        for (int t = 0; t < N_TOK; t++) {
            int idx = b * N_TOK + t;
            bool m;
            if (type == 2)      m = (((const float*)mp)[idx] != 0.0f);
            else if (type == 1) m = (mp[idx] != 0);
            else                m = (((const int*)mp)[idx] != 0);
            if (m) { g_order[b * N_TOK + cnt] = t; cnt++; }
        }
        g_len[b] = cnt;
    }
}

// ============================================================================
// im2col gather, writing fp16 h/l directly (patch GEMM inputs)
// ============================================================================
__global__ void im2col_kernel(const float* __restrict__ x, int Sc)
{
    int s = blockIdx.x, b = blockIdx.y;
    int m = b * Sc + s;
    __half* dh = g_ah + (size_t)m * D_MODEL;
    __half* dl = g_al + (size_t)m * D_MODEL;
    if (s >= g_len[b]) {
        for (int k = threadIdx.x; k < D_MODEL; k += blockDim.x) {
            dh[k] = __float2half(0.0f); dl[k] = __float2half(0.0f);
        }
        return;
    }
    int t = g_order[b * N_TOK + s];
    int gy = t / 14, gx = t % 14;
    const float* xb = x + (size_t)b * 3 * 224 * 224;
    for (int k = threadIdx.x; k < D_MODEL; k += blockDim.x) {
        int c = k >> 8, r = (k >> 4) & 15, cc = k & 15;
        float v = xb[((size_t)c * 224 + (gy * 16 + r)) * 224 + (gx * 16 + cc)];
        __half h, l; split_hl(v, h, l);
        dh[k] = h; dl[k] = l;
    }
}

// patch epilogue: X += patch_b + pos; emit h/l for QKV GEMM; zero pad rows.
__global__ void patch_epi_kernel(const float* __restrict__ pb,
                                 const float* __restrict__ pos, int Sc)
{
    int s = blockIdx.x, b = blockIdx.y;
    int m = b * Sc + s;
    float* row = g_X + (size_t)m * D_MODEL;
    __half* dh = g_ah + (size_t)m * D_MODEL;
    __half* dl = g_al + (size_t)m * D_MODEL;
    if (s >= g_len[b]) {
        for (int d = threadIdx.x; d < D_MODEL; d += blockDim.x) {
            row[d] = 0.0f;
            dh[d] = __float2half(0.0f); dl[d] = __float2half(0.0f);
        }
        return;
    }
    int t = g_order[b * N_TOK + s];
    const float* pr = pos + (size_t)t * D_MODEL;
    for (int d = threadIdx.x; d < D_MODEL; d += blockDim.x) {
        float v = row[d] + pb[d] + pr[d];
        row[d] = v;
        __half h, l; split_hl(v, h, l);
        dh[d] = h; dl[d] = l;
    }
}

// ============================================================================
// Fused flash attention (fp32), one CTA per (b,h). Whole Q/K/V in SMEM.
// Output written as fp16 h/l (proj GEMM inputs).
// ============================================================================
#define KS_STRIDE 65

__global__ void __launch_bounds__(256, 1)
flash_kernel(int Sc)
{
    extern __shared__ float fs[];
    float* qs = fs;                       // [Sc][64]
    float* ks = qs + Sc * 64;             // [Sc][65]
    float* vs = ks + Sc * KS_STRIDE;      // [Sc][64]
    float* es = vs + Sc * 64;             // [8][32]

    const int b = blockIdx.x / N_HEADS, h = blockIdx.x % N_HEADS;
    const int len = g_len[b];
    const int tid = threadIdx.x, lane = tid & 31, wid = tid >> 5;
    const size_t base = (size_t)(b * Sc) * (3 * D_MODEL) + h * HEAD_DIM;

    for (int idx = tid; idx < Sc * 64; idx += 256) {
        int r = idx >> 6, d = idx & 63;
        size_t g = base + (size_t)r * (3 * D_MODEL) + d;
        qs[idx] = g_qkv[g];
        ks[r * KS_STRIDE + d] = g_qkv[g + D_MODEL];
        vs[idx] = g_qkv[g + 2 * D_MODEL];
    }
    __syncthreads();

    float* ew = es + wid * 32;
    for (int q = wid; q < Sc; q += 8) {
        const float* qrow = qs + q * 64;
        float m = -3.4e38f, l = 0.0f;
        float o0a = 0.f, o0b = 0.f, o1a = 0.f, o1b = 0.f;
        for (int j0 = 0; j0 < len; j0 += 32) {
            int j = j0 + lane;
            int jj = (j < len) ? j : (len - 1);
            const float* krow = ks + jj * KS_STRIDE;
            float s0 = 0.f, s1 = 0.f, s2 = 0.f, s3 = 0.f;
            #pragma unroll
            for (int d = 0; d < 64; d += 4) {
                s0 += qrow[d + 0] * krow[d + 0];
                s1 += qrow[d + 1] * krow[d + 1];
                s2 += qrow[d + 2] * krow[d + 2];
                s3 += qrow[d + 3] * krow[d + 3];
            }
            float s = ((s0 + s1) + (s2 + s3)) * 0.125f;
            if (j >= len) s = -3.4e38f;
            float tmax = s;
            #pragma unroll
            for (int o = 16; o; o >>= 1) tmax = fmaxf(tmax, __shfl_xor_sync(0xffffffffu, tmax, o));
            float mnew = fmaxf(m, tmax);
            float scale = __expf(m - mnew);
            float e = (j < len) ? __expf(s - mnew) : 0.0f;
            float esum = e;
            #pragma unroll
            for (int o = 16; o; o >>= 1) esum += __shfl_xor_sync(0xffffffffu, esum, o);
            l = l * scale + esum;
            m = mnew;
            o0a *= scale; o0b *= scale; o1a *= scale; o1b *= scale;
            ew[lane] = e;
            __syncwarp();
            int jmax = (len - j0 < 32) ? (len - j0) : 32;
            int j2 = 0;
            for (; j2 + 2 <= jmax; j2 += 2) {
                float e0 = ew[j2], e1 = ew[j2 + 1];
                const float* v0 = vs + (j0 + j2) * 64;
                const float* v1 = v0 + 64;
                o0a += e0 * v0[lane];      o1a += e0 * v0[lane + 32];
                o0b += e1 * v1[lane];      o1b += e1 * v1[lane + 32];
            }
            if (j2 < jmax) {
                float e0 = ew[j2];
                const float* v0 = vs + (j0 + j2) * 64;
                o0a += e0 * v0[lane];      o1a += e0 * v0[lane + 32];
            }
            __syncwarp();
        }
        float inv = 1.0f / l;
        float r0 = (o0a + o0b) * inv, r1 = (o1a + o1b) * inv;
        size_t orow = (size_t)(b * Sc + q) * D_MODEL + h * HEAD_DIM;
        __half h0, l0, h1, l1;
        split_hl(r0, h0, l0); split_hl(r1, h1, l1);
        g_ah[orow + lane]      = h0;  g_al[orow + lane]      = l0;
        g_ah[orow + lane + 32] = h1;  g_al[orow + lane + 32] = l1;
    }
}

// ============================================================================
// LayerNorm (optionally +residual); optionally emits fp16 h/l alongside fp32.
// ============================================================================
__device__ __forceinline__ float blockReduce256(float v)
{
    __shared__ float sh[8];
    __syncthreads();
    #pragma unroll
    for (int o = 16; o; o >>= 1) v += __shfl_down_sync(0xffffffffu, v, o);
    if ((threadIdx.x & 31) == 0) sh[threadIdx.x >> 5] = v;
    __syncthreads();
    return sh[0] + sh[1] + sh[2] + sh[3] + sh[4] + sh[5] + sh[6] + sh[7];
}

template<bool RESID, bool EMITHL>
__global__ void ln_kernel(const float* __restrict__ X, const float* __restrict__ Rsd,
                          const float* __restrict__ gma, const float* __restrict__ bta,
                          float* __restrict__ out,
                          __half* __restrict__ outH, __half* __restrict__ outL)
{
    int m = blockIdx.x;
    int tid = threadIdx.x;
    const float* xr = X + (size_t)m * D_MODEL;
    float v[3];
    #pragma unroll
    for (int i = 0; i < 3; i++) {
        int d = tid + 256 * i;
        v[i] = xr[d];
        if (RESID) v[i] += Rsd[(size_t)m * D_MODEL + d];
    }
    float s = blockReduce256(v[0] + v[1] + v[2]);
    float mean = s * (1.0f / 768.0f);
    float q = 0.0f;
    #pragma unroll
    for (int i = 0; i < 3; i++) { float d = v[i] - mean; q += d * d; }
    q = blockReduce256(q);
    float inv = 1.0f / sqrtf(q * (1.0f / 768.0f) + 1e-5f);
    #pragma unroll
    for (int i = 0; i < 3; i++) {
        int d = tid + 256 * i;
        float r = (v[i] - mean) * inv * gma[d] + bta[d];
        out[(size_t)m * D_MODEL + d] = r;
        if (EMITHL) {
            __half h, l; split_hl(r, h, l);
            outH[(size_t)m * D_MODEL + d] = h;
            outL[(size_t)m * D_MODEL + d] = l;
        }
    }
}

__global__ void pad_out_kernel(float* __restrict__ out2, int Sc)
{
    int i = blockIdx.x * blockDim.x + threadIdx.x;
    if (i < BATCH * Sc) {
        int b = i / Sc, s = i % Sc;
        out2[i] = (s >= g_len[b]) ? 1.0f : 0.0f;
    }
}

// ===========================================================================
static void run_split(const float* src, __half* hi, __half* lo, size_t n)
{
    int n4 = (int)(n >> 2);
    split_kernel<<<(n4 + 255) / 256, 256>>>((const float4*)src, (__half2*)hi, (__half2*)lo, n4);
}

extern "C" void kernel_launch(void* const* d_in, const int* in_sizes, int n_in,
                              void* d_out, int out_size)
{
    const float* x       = (const float*)d_in[0];
    const void*  mask    = d_in[1];
    const float* patch_w = (const float*)d_in[2];
    const float* patch_b = (const float*)d_in[3];
    const float* pos     = (const float*)d_in[4];
    const float* inw     = (const float*)d_in[5];
    const float* inb     = (const float*)d_in[6];
    const float* outw    = (const float*)d_in[7];
    const float* outb    = (const float*)d_in[8];
    const float* ln1g    = (const float*)d_in[9];
    const float* ln1b    = (const float*)d_in[10];
    const float* f1w     = (const float*)d_in[11];
    const float* f1b     = (const float*)d_in[12];
    const float* f2w     = (const float*)d_in[13];
    const float* f2b     = (const float*)d_in[14];
    const float* ln2g    = (const float*)d_in[15];
    const float* ln2b    = (const float*)d_in[16];
    const float* ng      = (const float*)d_in[17];
    const float* nb      = (const float*)d_in[18];

    int Sc; bool tup;
    if (out_size % (64 * 769) == 0 &&
        out_size / (64 * 769) >= 1 && out_size / (64 * 769) <= N_TOK) {
        Sc = out_size / (64 * 769); tup = true;
    } else {
        Sc = out_size / (64 * 768); tup = false;
    }
    if (Sc < 1) Sc = 1;
    if (Sc > N_TOK) Sc = N_TOK;
    const int M  = BATCH * Sc;
    const int MB = (M + 127) / 128;
    const int flash_smem = Sc * (64 + KS_STRIDE + 64) * 4 + 8 * 32 * 4;

    float *pX, *pQ, *pP;
    __half *ah, *al, *fh, *wqh, *wql, *woh, *wol, *w1h, *w1l, *w2h, *w2l, *wph, *wpl;
    cudaGetSymbolAddress((void**)&pX,  g_X);
    cudaGetSymbolAddress((void**)&pQ,  g_qkv);
    cudaGetSymbolAddress((void**)&pP,  g_proj);
    cudaGetSymbolAddress((void**)&ah,  g_ah);
    cudaGetSymbolAddress((void**)&al,  g_al);
    cudaGetSymbolAddress((void**)&fh,  g_fh);
    cudaGetSymbolAddress((void**)&wqh, g_wqkv_h);
    cudaGetSymbolAddress((void**)&wql, g_wqkv_l);
    cudaGetSymbolAddress((void**)&woh, g_wo_h);
    cudaGetSymbolAddress((void**)&wol, g_wo_l);
    cudaGetSymbolAddress((void**)&w1h, g_wf1_h);
    cudaGetSymbolAddress((void**)&w1l, g_wf1_l);
    cudaGetSymbolAddress((void**)&w2h, g_wf2_h);
    cudaGetSymbolAddress((void**)&w2l, g_wf2_l);
    cudaGetSymbolAddress((void**)&wph, g_wp_h);
    cudaGetSymbolAddress((void**)&wpl, g_wp_l);

    cudaFuncSetAttribute(mma_gemm_kernel, cudaFuncAttributeMaxDynamicSharedMemorySize,
                         GEMM_SMEM);
    cudaFuncSetAttribute(flash_kernel, cudaFuncAttributeMaxDynamicSharedMemorySize,
                         160000);

    // --- weight splits --------------------------------------------------------
    run_split(inw,     wqh, wql, (size_t)N_LAYERS * 3 * D_MODEL * D_MODEL);
    run_split(outw,    woh, wol, (size_t)N_LAYERS * D_MODEL * D_MODEL);
    run_split(f1w,     w1h, w1l, (size_t)N_LAYERS * FF_DIM * D_MODEL);
    run_split(f2w,     w2h, w2l, (size_t)N_LAYERS * FF_DIM * D_MODEL);
    run_split(patch_w, wph, wpl, (size_t)D_MODEL * D_MODEL);

    // --- mask parse + gather + patch embedding --------------------------------
    mask_kernel<<<1, 256>>>((const unsigned char*)mask);
    im2col_kernel<<<dim3(Sc, BATCH), 256>>>(x, Sc);
    mma_gemm_kernel<<<dim3(6, MB), 256, GEMM_SMEM>>>(
        ah, al, wph, wpl, nullptr, pX, nullptr, nullptr, D_MODEL, M, D_MODEL, 0);
    patch_epi_kernel<<<dim3(Sc, BATCH), 256>>>(patch_b, pos, Sc);

    // --- transformer layers ---------------------------------------------------
    for (int l = 0; l < N_LAYERS; l++) {
        const __half* Wqh = wqh + (size_t)l * 3 * D_MODEL * D_MODEL;
        const __half* Wql = wql + (size_t)l * 3 * D_MODEL * D_MODEL;
        const __half* Woh = woh + (size_t)l * D_MODEL * D_MODEL;
        const __half* Wol = wol + (size_t)l * D_MODEL * D_MODEL;
        const __half* W1h = w1h + (size_t)l * FF_DIM * D_MODEL;
        const __half* W1l = w1l + (size_t)l * FF_DIM * D_MODEL;
        const __half* W2h = w2h + (size_t)l * FF_DIM * D_MODEL;
        const __half* W2l = w2l + (size_t)l * FF_DIM * D_MODEL;
        const float* bqkv = inb  + (size_t)l * 3 * D_MODEL;
        const float* bo   = outb + (size_t)l * D_MODEL;
        const float* b1   = f1b  + (size_t)l * FF_DIM;
        const float* b2   = f2b  + (size_t)l * D_MODEL;

        // QKV projection (2-term)
        mma_gemm_kernel<<<dim3(18, MB), 256, GEMM_SMEM>>>(
            ah, nullptr, Wqh, Wql, bqkv, pQ, nullptr, nullptr, 3 * D_MODEL, M, D_MODEL,
            F_BIAS | F_2TERM);
        // fused attention -> ah/al
        flash_kernel<<<BATCH * N_HEADS, 256, flash_smem>>>(Sc);
        // output projection (2-term)
        mma_gemm_kernel<<<dim3(6, MB), 256, GEMM_SMEM>>>(
            ah, nullptr, Woh, Wol, bo, pP, nullptr, nullptr, D_MODEL, M, D_MODEL,
            F_BIAS | F_2TERM);
        // residual + LN1 -> X, ah/al
        ln_kernel<true, true><<<M, 256>>>(pX, pP, ln1g + l * D_MODEL, ln1b + l * D_MODEL,
                                          pX, ah, al);
        // FFN1 (+GELU), 2-term, fp16 hi-only output -> fh
        mma_gemm_kernel<<<dim3(24, MB), 256, GEMM_SMEM>>>(
            ah, nullptr, W1h, W1l, b1, nullptr, fh, nullptr, FF_DIM, M, D_MODEL,
            F_BIAS | F_GELU | F_OUT16 | F_2TERM | F_HIONLY);
        // FFN2, 2-term (A = fh)
        mma_gemm_kernel<<<dim3(6, MB), 256, GEMM_SMEM>>>(
            fh, nullptr, W2h, W2l, b2, pP, nullptr, nullptr, D_MODEL, M, FF_DIM,
            F_BIAS | F_2TERM);
        // residual + LN2 -> X, ah/al
        ln_kernel<true, true><<<M, 256>>>(pX, pP, ln2g + l * D_MODEL, ln2b + l * D_MODEL,
                                          pX, ah, al);
    }

    // --- final LN into d_out --------------------------------------------------
    ln_kernel<false, false><<<M, 256>>>(pX, nullptr, ng, nb, (float*)d_out,
                                        nullptr, nullptr);
    if (tup) {
        pad_out_kernel<<<(BATCH * Sc + 255) / 256, 256>>>(
            (float*)d_out + (size_t)M * D_MODEL, Sc);
    }
}

// round 13
// speedup vs baseline: 2.0252x; 1.3952x over previous
#include <cuda_runtime.h>
#include <cuda_fp16.h>
#include <math.h>
#include <stdint.h>

// ============================================================================
// Masked ViT context encoder. R10: pure fp16 1-term GEMM (AhBh, fp32 accum)
// for QKV/proj/FFN1/FFN2; patch GEMM stays 3-term. 128x128 tiles, K-chunk 32,
// 2 CTAs/SM, cp.async double buffer, ldmatrix. Fused flash attention (fp32).
// ============================================================================

#define BATCH    64
#define N_TOK    196
#define D_MODEL  768
#define N_HEADS  12
#define HEAD_DIM 64
#define N_LAYERS 12
#define FF_DIM   3072
#define M_MAX    (BATCH * N_TOK)

// flags
#define F_BIAS    1
#define F_GELU    2
#define F_OUT16   4
#define F_2TERM   8   // drop Al (activation lo)
#define F_HIONLY  16
#define F_1TERM   32  // additionally drop Bl (weight lo)

// ---------------- scratch (device globals; no allocation allowed) -----------
__device__ int    g_order[BATCH * N_TOK];
__device__ int    g_len[BATCH];
__device__ float  g_X[(size_t)M_MAX * D_MODEL];
__device__ float  g_qkv[(size_t)M_MAX * 3 * D_MODEL];
__device__ float  g_proj[(size_t)M_MAX * D_MODEL];
// fp16 activation buffers (al only used by 3-term patch GEMM)
__device__ __half g_ah[(size_t)M_MAX * D_MODEL];
__device__ __half g_al[(size_t)M_MAX * D_MODEL];
__device__ __half g_fh[(size_t)M_MAX * FF_DIM];
// fp16 weights (hi-only for 1-term GEMMs; patch keeps hi+lo)
__device__ __half g_wqkv_h[(size_t)N_LAYERS * 3 * D_MODEL * D_MODEL];
__device__ __half g_wo_h[(size_t)N_LAYERS * D_MODEL * D_MODEL];
__device__ __half g_wf1_h[(size_t)N_LAYERS * FF_DIM * D_MODEL];
__device__ __half g_wf2_h[(size_t)N_LAYERS * FF_DIM * D_MODEL];
__device__ __half g_wp_h[(size_t)D_MODEL * D_MODEL];
__device__ __half g_wp_l[(size_t)D_MODEL * D_MODEL];

// ============================================================================
// helpers
// ============================================================================
__device__ __forceinline__ uint32_t smem_u32(const void* p) {
    uint32_t a;
    asm("{ .reg .u64 t; cvta.to.shared.u64 t, %1; cvt.u32.u64 %0, t; }"
        : "=r"(a) : "l"(p));
    return a;
}
__device__ __forceinline__ void split_hl(float v, __half& h, __half& l) {
    h = __float2half(v);
    l = __float2half(v - __half2float(h));
}

#define CP_ASYNC_16(dst, src) \
    asm volatile("cp.async.cg.shared.global [%0], [%1], 16;" :: "r"(dst), "l"(src))
#define CP_COMMIT() asm volatile("cp.async.commit_group;" ::: "memory")
#define CP_WAIT(n)  asm volatile("cp.async.wait_group %0;" :: "n"(n) : "memory")

#define LDSM4(r0, r1, r2, r3, addr) \
    asm volatile("ldmatrix.sync.aligned.m8n8.x4.shared.b16 {%0,%1,%2,%3}, [%4];" \
        : "=r"(r0), "=r"(r1), "=r"(r2), "=r"(r3) : "r"(addr))

#define MMA16816(c, a, b) \
    asm volatile("mma.sync.aligned.m16n8k16.row.col.f32.f16.f16.f32 " \
        "{%0,%1,%2,%3}, {%4,%5,%6,%7}, {%8,%9}, {%0,%1,%2,%3};" \
        : "+f"((c)[0]), "+f"((c)[1]), "+f"((c)[2]), "+f"((c)[3]) \
        : "r"((a)[0]), "r"((a)[1]), "r"((a)[2]), "r"((a)[3]), \
          "r"((b)[0]), "r"((b)[1]))

// ============================================================================
// weight conversion: split (hi+lo) for patch; hi-only cvt for the rest
// ============================================================================
__global__ void split_kernel(const float4* __restrict__ src,
                             __half2* __restrict__ hi, __half2* __restrict__ lo, int n4)
{
    int i = blockIdx.x * blockDim.x + threadIdx.x;
    if (i >= n4) return;
    float4 v = src[i];
    __half h0, h1, h2, h3, l0, l1, l2, l3;
    split_hl(v.x, h0, l0); split_hl(v.y, h1, l1);
    split_hl(v.z, h2, l2); split_hl(v.w, h3, l3);
    hi[i * 2 + 0] = __halves2half2(h0, h1);
    hi[i * 2 + 1] = __halves2half2(h2, h3);
    lo[i * 2 + 0] = __halves2half2(l0, l1);
    lo[i * 2 + 1] = __halves2half2(l2, l3);
}

__global__ void cvt_kernel(const float4* __restrict__ src,
                           __half2* __restrict__ hi, int n4)
{
    int i = blockIdx.x * blockDim.x + threadIdx.x;
    if (i >= n4) return;
    float4 v = src[i];
    hi[i * 2 + 0] = __halves2half2(__float2half(v.x), __float2half(v.y));
    hi[i * 2 + 1] = __halves2half2(__float2half(v.z), __float2half(v.w));
}

// ============================================================================
// HMMA GEMM: 3-term / 2-term / 1-term via flags.
// 128x128 CTA tile, K-chunk 32, cp.async double buffer (40KB stages,
// 2 CTAs/SM), ldmatrix fragments, 8 warps (4m x 2n), warp tile 32x64.
// ============================================================================
#define ROW_BYTES   80                  // 32 fp16 (64B) + 16B pad: conflict-free
#define TILE_BYTES  (128 * ROW_BYTES)   // 10240
#define STAGE_BYTES (4 * TILE_BYTES)    // 40960
#define GEMM_SMEM   (2 * STAGE_BYTES)   // 81920

__global__ void __launch_bounds__(256, 2)
mma_gemm_kernel(const __half* __restrict__ Ah, const __half* __restrict__ Al,
                const __half* __restrict__ Bh, const __half* __restrict__ Bl,
                const float* __restrict__ bias,
                float* __restrict__ C, __half* __restrict__ Ch, __half* __restrict__ Cl,
                int ldc, int M, int K, int flags)
{
    extern __shared__ char smem[];
    const uint32_t sb = smem_u32(smem);
    const int tid  = threadIdx.x;
    const int wid  = tid >> 5, lane = tid & 31;
    const int wm   = wid & 3, wn = wid >> 2;     // 4(m) x 2(n)
    const int brow = blockIdx.y * 128;
    const int bcol = blockIdx.x * 128;
    const bool twoterm = (flags & F_2TERM) != 0;
    const bool oneterm = (flags & F_1TERM) != 0;

    float acc[2][8][4];
    #pragma unroll
    for (int mt = 0; mt < 2; mt++)
        #pragma unroll
        for (int nt = 0; nt < 8; nt++)
            #pragma unroll
            for (int i = 0; i < 4; i++) acc[mt][nt][i] = 0.0f;

    const int nC = K >> 5;

    // 2048 16B-chunks per stage; 8 per thread (lo tiles skipped per flags).
    auto load_chunk = [&](int c, int buf) {
        const int k0 = c << 5;
        const uint32_t tb = sb + (uint32_t)buf * STAGE_BYTES;
        #pragma unroll
        for (int j = 0; j < 8; j++) {
            int idx = tid + (j << 8);
            int op  = idx >> 9;           // 0=Ah 1=Al 2=Bh 3=Bl
            if (twoterm && op == 1) continue;
            if (oneterm && op == 3) continue;
            int rem = idx & 511;
            int r   = rem >> 2;           // row 0..127
            int q   = rem & 3;            // 16B chunk (8 halves)
            const __half* gp;
            if (op < 2) {
                int gr = brow + r;
                if (gr >= M) gr = M - 1;
                gp = (op ? Al : Ah) + (size_t)gr * K + k0 + (q << 3);
            } else {
                int gn = bcol + r;
                gp = (op == 3 ? Bl : Bh) + (size_t)gn * K + k0 + (q << 3);
            }
            uint32_t dst = tb + (uint32_t)op * TILE_BYTES + (uint32_t)r * ROW_BYTES + (q << 4);
            CP_ASYNC_16(dst, gp);
        }
        CP_COMMIT();
    };

    load_chunk(0, 0);

    // intra-tile ldmatrix offsets
    const uint32_t a_off = (uint32_t)(wm * 32 + (lane & 15)) * ROW_BYTES
                         + (uint32_t)((lane >> 4) << 3) * 2;           // + ks*2
    const int      b_mm  = lane >> 3;
    const uint32_t b_row_off = (uint32_t)(wn * 64 + ((b_mm >> 1) << 3) + (lane & 7)) * ROW_BYTES;
    const uint32_t b_k_off   = (uint32_t)((b_mm & 1) << 3) * 2;

    for (int c = 0; c < nC; c++) {
        const int buf = c & 1;
        if (c + 1 < nC) { load_chunk(c + 1, buf ^ 1); CP_WAIT(1); }
        else            { CP_WAIT(0); }
        __syncthreads();

        const uint32_t At  = sb + (uint32_t)buf * STAGE_BYTES;
        const uint32_t Alt = At + TILE_BYTES;
        const uint32_t Bt  = At + 2 * TILE_BYTES;
        const uint32_t Blt = At + 3 * TILE_BYTES;

        #pragma unroll
        for (int ks = 0; ks < 32; ks += 16) {
            uint32_t ah[2][4], bh[8][2];
            const uint32_t ksb = (uint32_t)ks * 2;
            LDSM4(ah[0][0], ah[0][1], ah[0][2], ah[0][3], At  + a_off + ksb);
            LDSM4(ah[1][0], ah[1][1], ah[1][2], ah[1][3], At  + a_off + ksb + 16 * ROW_BYTES);
            #pragma unroll
            for (int g = 0; g < 4; g++) {
                uint32_t off = b_row_off + (uint32_t)(g * 16) * ROW_BYTES + b_k_off + ksb;
                LDSM4(bh[2*g][0], bh[2*g][1], bh[2*g+1][0], bh[2*g+1][1], Bt + off);
            }
            #pragma unroll
            for (int mt = 0; mt < 2; mt++)
                #pragma unroll
                for (int nt = 0; nt < 8; nt++) MMA16816(acc[mt][nt], ah[mt], bh[nt]);
            if (!oneterm) {
                uint32_t bl[8][2];
                #pragma unroll
                for (int g = 0; g < 4; g++) {
                    uint32_t off = b_row_off + (uint32_t)(g * 16) * ROW_BYTES + b_k_off + ksb;
                    LDSM4(bl[2*g][0], bl[2*g][1], bl[2*g+1][0], bl[2*g+1][1], Blt + off);
                }
                #pragma unroll
                for (int mt = 0; mt < 2; mt++)
                    #pragma unroll
                    for (int nt = 0; nt < 8; nt++) MMA16816(acc[mt][nt], ah[mt], bl[nt]);
                if (!twoterm) {
                    uint32_t al[2][4];
                    LDSM4(al[0][0], al[0][1], al[0][2], al[0][3], Alt + a_off + ksb);
                    LDSM4(al[1][0], al[1][1], al[1][2], al[1][3], Alt + a_off + ksb + 16 * ROW_BYTES);
                    #pragma unroll
                    for (int mt = 0; mt < 2; mt++)
                        #pragma unroll
                        for (int nt = 0; nt < 8; nt++) MMA16816(acc[mt][nt], al[mt], bh[nt]);
                }
            }
        }
        __syncthreads();
    }

    // ---- epilogue -----------------------------------------------------------
    const int lr = lane >> 2, lc = (lane & 3) * 2;
    #pragma unroll
    for (int mt = 0; mt < 2; mt++) {
        int r0 = brow + wm * 32 + mt * 16 + lr;
        #pragma unroll
        for (int nt = 0; nt < 8; nt++) {
            int cc = bcol + wn * 64 + nt * 8 + lc;
            float bv0 = 0.0f, bv1 = 0.0f;
            if (flags & F_BIAS) { bv0 = bias[cc]; bv1 = bias[cc + 1]; }
            #pragma unroll
            for (int half = 0; half < 2; half++) {
                int r = r0 + half * 8;
                if (r < M) {
                    float v0 = acc[mt][nt][half * 2 + 0] + bv0;
                    float v1 = acc[mt][nt][half * 2 + 1] + bv1;
                    if (flags & F_GELU) {
                        v0 = 0.5f * v0 * (1.0f + erff(v0 * 0.70710678118654752440f));
                        v1 = 0.5f * v1 * (1.0f + erff(v1 * 0.70710678118654752440f));
                    }
                    if (flags & F_OUT16) {
                        __half h0, h1, l0, l1;
                        split_hl(v0, h0, l0); split_hl(v1, h1, l1);
                        *(__half2*)(Ch + (size_t)r * ldc + cc) = __halves2half2(h0, h1);
                        if (!(flags & F_HIONLY))
                            *(__half2*)(Cl + (size_t)r * ldc + cc) = __halves2half2(l0, l1);
                    } else {
                        *(float2*)(C + (size_t)r * ldc + cc) = make_float2(v0, v1);
                    }
                }
            }
        }
    }
}

// ============================================================================
// mask parse (parallel detection)
// ============================================================================
__global__ void mask_kernel(const unsigned char* __restrict__ mp)
{
    int tid = threadIdx.x;   // 256
    bool big = false, misal = false;
    for (int i = tid; i < BATCH * N_TOK; i += 256) {
        unsigned char v = mp[i];
        if (v >= 2) big = true;
        else if (v && (i & 3)) misal = true;
    }
    int anybig = __syncthreads_or(big ? 1 : 0);
    int anymis = __syncthreads_or(misal ? 1 : 0);
    int type = anybig ? 2 : (anymis ? 1 : 0);
    int b = tid;
    if (b < BATCH) {
        int cnt = 0;
        for (int t = 0; t < N_TOK; t++) {
            int idx = b * N_TOK + t;
            bool m;
            if (type == 2)      m = (((const float*)mp)[idx] != 0.0f);
            else if (type == 1) m = (mp[idx] != 0);
            else                m = (((const int*)mp)[idx] != 0);
            if (m) { g_order[b * N_TOK + cnt] = t; cnt++; }
        }
        g_len[b] = cnt;
    }
}

// ============================================================================
// im2col gather, writing fp16 h/l (patch GEMM is 3-term)
// ============================================================================
__global__ void im2col_kernel(const float* __restrict__ x, int Sc)
{
    int s = blockIdx.x, b = blockIdx.y;
    int m = b * Sc + s;
    __half* dh = g_ah + (size_t)m * D_MODEL;
    __half* dl = g_al + (size_t)m * D_MODEL;
    if (s >= g_len[b]) {
        for (int k = threadIdx.x; k < D_MODEL; k += blockDim.x) {
            dh[k] = __float2half(0.0f); dl[k] = __float2half(0.0f);
        }
        return;
    }
    int t = g_order[b * N_TOK + s];
    int gy = t / 14, gx = t % 14;
    const float* xb = x + (size_t)b * 3 * 224 * 224;
    for (int k = threadIdx.x; k < D_MODEL; k += blockDim.x) {
        int c = k >> 8, r = (k >> 4) & 15, cc = k & 15;
        float v = xb[((size_t)c * 224 + (gy * 16 + r)) * 224 + (gx * 16 + cc)];
        __half h, l; split_hl(v, h, l);
        dh[k] = h; dl[k] = l;
    }
}

// patch epilogue: X += patch_b + pos; emit hi fp16 for QKV (1-term); zero pads.
__global__ void patch_epi_kernel(const float* __restrict__ pb,
                                 const float* __restrict__ pos, int Sc)
{
    int s = blockIdx.x, b = blockIdx.y;
    int m = b * Sc + s;
    float* row = g_X + (size_t)m * D_MODEL;
    __half* dh = g_ah + (size_t)m * D_MODEL;
    if (s >= g_len[b]) {
        for (int d = threadIdx.x; d < D_MODEL; d += blockDim.x) {
            row[d] = 0.0f;
            dh[d] = __float2half(0.0f);
        }
        return;
    }
    int t = g_order[b * N_TOK + s];
    const float* pr = pos + (size_t)t * D_MODEL;
    for (int d = threadIdx.x; d < D_MODEL; d += blockDim.x) {
        float v = row[d] + pb[d] + pr[d];
        row[d] = v;
        dh[d] = __float2half(v);
    }
}

// ============================================================================
// Fused flash attention (fp32), one CTA per (b,h). Whole Q/K/V in SMEM.
// Output written as hi fp16 (proj GEMM is 1-term).
// ============================================================================
#define KS_STRIDE 65

__global__ void __launch_bounds__(256, 1)
flash_kernel(int Sc)
{
    extern __shared__ float fs[];
    float* qs = fs;                       // [Sc][64]
    float* ks = qs + Sc * 64;             // [Sc][65]
    float* vs = ks + Sc * KS_STRIDE;      // [Sc][64]
    float* es = vs + Sc * 64;             // [8][32]

    const int b = blockIdx.x / N_HEADS, h = blockIdx.x % N_HEADS;
    const int len = g_len[b];
    const int tid = threadIdx.x, lane = tid & 31, wid = tid >> 5;
    const size_t base = (size_t)(b * Sc) * (3 * D_MODEL) + h * HEAD_DIM;

    for (int idx = tid; idx < Sc * 64; idx += 256) {
        int r = idx >> 6, d = idx & 63;
        size_t g = base + (size_t)r * (3 * D_MODEL) + d;
        qs[idx] = g_qkv[g];
        ks[r * KS_STRIDE + d] = g_qkv[g + D_MODEL];
        vs[idx] = g_qkv[g + 2 * D_MODEL];
    }
    __syncthreads();

    float* ew = es + wid * 32;
    for (int q = wid; q < Sc; q += 8) {
        const float* qrow = qs + q * 64;
        float m = -3.4e38f, l = 0.0f;
        float o0a = 0.f, o0b = 0.f, o1a = 0.f, o1b = 0.f;
        for (int j0 = 0; j0 < len; j0 += 32) {
            int j = j0 + lane;
            int jj = (j < len) ? j : (len - 1);
            const float* krow = ks + jj * KS_STRIDE;
            float s0 = 0.f, s1 = 0.f, s2 = 0.f, s3 = 0.f;
            #pragma unroll
            for (int d = 0; d < 64; d += 4) {
                s0 += qrow[d + 0] * krow[d + 0];
                s1 += qrow[d + 1] * krow[d + 1];
                s2 += qrow[d + 2] * krow[d + 2];
                s3 += qrow[d + 3] * krow[d + 3];
            }
            float s = ((s0 + s1) + (s2 + s3)) * 0.125f;
            if (j >= len) s = -3.4e38f;
            float tmax = s;
            #pragma unroll
            for (int o = 16; o; o >>= 1) tmax = fmaxf(tmax, __shfl_xor_sync(0xffffffffu, tmax, o));
            float mnew = fmaxf(m, tmax);
            float scale = __expf(m - mnew);
            float e = (j < len) ? __expf(s - mnew) : 0.0f;
            float esum = e;
            #pragma unroll
            for (int o = 16; o; o >>= 1) esum += __shfl_xor_sync(0xffffffffu, esum, o);
            l = l * scale + esum;
            m = mnew;
            o0a *= scale; o0b *= scale; o1a *= scale; o1b *= scale;
            ew[lane] = e;
            __syncwarp();
            int jmax = (len - j0 < 32) ? (len - j0) : 32;
            int j2 = 0;
            for (; j2 + 2 <= jmax; j2 += 2) {
                float e0 = ew[j2], e1 = ew[j2 + 1];
                const float* v0 = vs + (j0 + j2) * 64;
                const float* v1 = v0 + 64;
                o0a += e0 * v0[lane];      o1a += e0 * v0[lane + 32];
                o0b += e1 * v1[lane];      o1b += e1 * v1[lane + 32];
            }
            if (j2 < jmax) {
                float e0 = ew[j2];
                const float* v0 = vs + (j0 + j2) * 64;
                o0a += e0 * v0[lane];      o1a += e0 * v0[lane + 32];
            }
            __syncwarp();
        }
        float inv = 1.0f / l;
        float r0 = (o0a + o0b) * inv, r1 = (o1a + o1b) * inv;
        size_t orow = (size_t)(b * Sc + q) * D_MODEL + h * HEAD_DIM;
        g_ah[orow + lane]      = __float2half(r0);
        g_ah[orow + lane + 32] = __float2half(r1);
    }
}

// ============================================================================
// LayerNorm (optionally +residual); optionally emits hi fp16.
// ============================================================================
__device__ __forceinline__ float blockReduce256(float v)
{
    __shared__ float sh[8];
    __syncthreads();
    #pragma unroll
    for (int o = 16; o; o >>= 1) v += __shfl_down_sync(0xffffffffu, v, o);
    if ((threadIdx.x & 31) == 0) sh[threadIdx.x >> 5] = v;
    __syncthreads();
    return sh[0] + sh[1] + sh[2] + sh[3] + sh[4] + sh[5] + sh[6] + sh[7];
}

template<bool RESID, bool EMITH>
__global__ void ln_kernel(const float* __restrict__ X, const float* __restrict__ Rsd,
                          const float* __restrict__ gma, const float* __restrict__ bta,
                          float* __restrict__ out, __half* __restrict__ outH)
{
    int m = blockIdx.x;
    int tid = threadIdx.x;
    const float* xr = X + (size_t)m * D_MODEL;
    float v[3];
    #pragma unroll
    for (int i = 0; i < 3; i++) {
        int d = tid + 256 * i;
        v[i] = xr[d];
        if (RESID) v[i] += Rsd[(size_t)m * D_MODEL + d];
    }
    float s = blockReduce256(v[0] + v[1] + v[2]);
    float mean = s * (1.0f / 768.0f);
    float q = 0.0f;
    #pragma unroll
    for (int i = 0; i < 3; i++) { float d = v[i] - mean; q += d * d; }
    q = blockReduce256(q);
    float inv = 1.0f / sqrtf(q * (1.0f / 768.0f) + 1e-5f);
    #pragma unroll
    for (int i = 0; i < 3; i++) {
        int d = tid + 256 * i;
        float r = (v[i] - mean) * inv * gma[d] + bta[d];
        out[(size_t)m * D_MODEL + d] = r;
        if (EMITH) outH[(size_t)m * D_MODEL + d] = __float2half(r);
    }
}

__global__ void pad_out_kernel(float* __restrict__ out2, int Sc)
{
    int i = blockIdx.x * blockDim.x + threadIdx.x;
    if (i < BATCH * Sc) {
        int b = i / Sc, s = i % Sc;
        out2[i] = (s >= g_len[b]) ? 1.0f : 0.0f;
    }
}

// ===========================================================================
static void run_cvt(const float* src, __half* hi, size_t n)
{
    int n4 = (int)(n >> 2);
    cvt_kernel<<<(n4 + 255) / 256, 256>>>((const float4*)src, (__half2*)hi, n4);
}

extern "C" void kernel_launch(void* const* d_in, const int* in_sizes, int n_in,
                              void* d_out, int out_size)
{
    const float* x       = (const float*)d_in[0];
    const void*  mask    = d_in[1];
    const float* patch_w = (const float*)d_in[2];
    const float* patch_b = (const float*)d_in[3];
    const float* pos     = (const float*)d_in[4];
    const float* inw     = (const float*)d_in[5];
    const float* inb     = (const float*)d_in[6];
    const float* outw    = (const float*)d_in[7];
    const float* outb    = (const float*)d_in[8];
    const float* ln1g    = (const float*)d_in[9];
    const float* ln1b    = (const float*)d_in[10];
    const float* f1w     = (const float*)d_in[11];
    const float* f1b     = (const float*)d_in[12];
    const float* f2w     = (const float*)d_in[13];
    const float* f2b     = (const float*)d_in[14];
    const float* ln2g    = (const float*)d_in[15];
    const float* ln2b    = (const float*)d_in[16];
    const float* ng      = (const float*)d_in[17];
    const float* nb      = (const float*)d_in[18];

    int Sc; bool tup;
    if (out_size % (64 * 769) == 0 &&
        out_size / (64 * 769) >= 1 && out_size / (64 * 769) <= N_TOK) {
        Sc = out_size / (64 * 769); tup = true;
    } else {
        Sc = out_size / (64 * 768); tup = false;
    }
    if (Sc < 1) Sc = 1;
    if (Sc > N_TOK) Sc = N_TOK;
    const int M  = BATCH * Sc;
    const int MB = (M + 127) / 128;
    const int flash_smem = Sc * (64 + KS_STRIDE + 64) * 4 + 8 * 32 * 4;

    float *pX, *pQ, *pP;
    __half *ah, *al, *fh, *wqh, *woh, *w1h, *w2h, *wph, *wpl;
    cudaGetSymbolAddress((void**)&pX,  g_X);
    cudaGetSymbolAddress((void**)&pQ,  g_qkv);
    cudaGetSymbolAddress((void**)&pP,  g_proj);
    cudaGetSymbolAddress((void**)&ah,  g_ah);
    cudaGetSymbolAddress((void**)&al,  g_al);
    cudaGetSymbolAddress((void**)&fh,  g_fh);
    cudaGetSymbolAddress((void**)&wqh, g_wqkv_h);
    cudaGetSymbolAddress((void**)&woh, g_wo_h);
    cudaGetSymbolAddress((void**)&w1h, g_wf1_h);
    cudaGetSymbolAddress((void**)&w2h, g_wf2_h);
    cudaGetSymbolAddress((void**)&wph, g_wp_h);
    cudaGetSymbolAddress((void**)&wpl, g_wp_l);

    cudaFuncSetAttribute(mma_gemm_kernel, cudaFuncAttributeMaxDynamicSharedMemorySize,
                         GEMM_SMEM);
    cudaFuncSetAttribute(flash_kernel, cudaFuncAttributeMaxDynamicSharedMemorySize,
                         160000);

    // --- weight conversion ----------------------------------------------------
    run_cvt(inw,  wqh, (size_t)N_LAYERS * 3 * D_MODEL * D_MODEL);
    run_cvt(outw, woh, (size_t)N_LAYERS * D_MODEL * D_MODEL);
    run_cvt(f1w,  w1h, (size_t)N_LAYERS * FF_DIM * D_MODEL);
    run_cvt(f2w,  w2h, (size_t)N_LAYERS * FF_DIM * D_MODEL);
    {
        int n4 = (int)(((size_t)D_MODEL * D_MODEL) >> 2);
        split_kernel<<<(n4 + 255) / 256, 256>>>((const float4*)patch_w,
                                                (__half2*)wph, (__half2*)wpl, n4);
    }

    // --- mask parse + gather + patch embedding --------------------------------
    mask_kernel<<<1, 256>>>((const unsigned char*)mask);
    im2col_kernel<<<dim3(Sc, BATCH), 256>>>(x, Sc);
    mma_gemm_kernel<<<dim3(6, MB), 256, GEMM_SMEM>>>(
        ah, al, wph, wpl, nullptr, pX, nullptr, nullptr, D_MODEL, M, D_MODEL, 0);
    patch_epi_kernel<<<dim3(Sc, BATCH), 256>>>(patch_b, pos, Sc);

    // --- transformer layers (all GEMMs pure fp16 1-term) ----------------------
    const int FT = F_BIAS | F_2TERM | F_1TERM;
    for (int l = 0; l < N_LAYERS; l++) {
        const __half* Wqh = wqh + (size_t)l * 3 * D_MODEL * D_MODEL;
        const __half* Woh = woh + (size_t)l * D_MODEL * D_MODEL;
        const __half* W1h = w1h + (size_t)l * FF_DIM * D_MODEL;
        const __half* W2h = w2h + (size_t)l * FF_DIM * D_MODEL;
        const float* bqkv = inb  + (size_t)l * 3 * D_MODEL;
        const float* bo   = outb + (size_t)l * D_MODEL;
        const float* b1   = f1b  + (size_t)l * FF_DIM;
        const float* b2   = f2b  + (size_t)l * D_MODEL;

        // QKV projection
        mma_gemm_kernel<<<dim3(18, MB), 256, GEMM_SMEM>>>(
            ah, nullptr, Wqh, nullptr, bqkv, pQ, nullptr, nullptr, 3 * D_MODEL, M, D_MODEL,
            FT);
        // fused attention -> ah
        flash_kernel<<<BATCH * N_HEADS, 256, flash_smem>>>(Sc);
        // output projection
        mma_gemm_kernel<<<dim3(6, MB), 256, GEMM_SMEM>>>(
            ah, nullptr, Woh, nullptr, bo, pP, nullptr, nullptr, D_MODEL, M, D_MODEL,
            FT);
        // residual + LN1 -> X, ah
        ln_kernel<true, true><<<M, 256>>>(pX, pP, ln1g + l * D_MODEL, ln1b + l * D_MODEL,
                                          pX, ah);
        // FFN1 (+GELU) -> fh (fp16 hi-only)
        mma_gemm_kernel<<<dim3(24, MB), 256, GEMM_SMEM>>>(
            ah, nullptr, W1h, nullptr, b1, nullptr, fh, nullptr, FF_DIM, M, D_MODEL,
            FT | F_GELU | F_OUT16 | F_HIONLY);
        // FFN2
        mma_gemm_kernel<<<dim3(6, MB), 256, GEMM_SMEM>>>(
            fh, nullptr, W2h, nullptr, b2, pP, nullptr, nullptr, D_MODEL, M, FF_DIM,
            FT);
        // residual + LN2 -> X, ah
        ln_kernel<true, true><<<M, 256>>>(pX, pP, ln2g + l * D_MODEL, ln2b + l * D_MODEL,
                                          pX, ah);
    }

    // --- final LN into d_out --------------------------------------------------
    ln_kernel<false, false><<<M, 256>>>(pX, nullptr, ng, nb, (float*)d_out, nullptr);
    if (tup) {
        pad_out_kernel<<<(BATCH * Sc + 255) / 256, 256>>>(
            (float*)d_out + (size_t)M * D_MODEL, Sc);
    }
}

// round 15
// speedup vs baseline: 2.8437x; 1.4042x over previous
#include <cuda_runtime.h>
#include <cuda_fp16.h>
#include <math.h>
#include <stdint.h>

// ============================================================================
// Masked ViT context encoder. R14 (= R11/R13 resubmit; container infra
// failure): pure fp16 1-term GEMMs + tensor-core flash attention (fp16
// operands, fp32 accum/softmax). QKV GEMM emits fp16.
// ============================================================================

#define BATCH    64
#define N_TOK    196
#define D_MODEL  768
#define N_HEADS  12
#define HEAD_DIM 64
#define N_LAYERS 12
#define FF_DIM   3072
#define M_MAX    (BATCH * N_TOK)

// flags
#define F_BIAS    1
#define F_GELU    2
#define F_OUT16   4
#define F_2TERM   8   // drop Al (activation lo)
#define F_HIONLY  16
#define F_1TERM   32  // additionally drop Bl (weight lo)

// ---------------- scratch (device globals; no allocation allowed) -----------
__device__ int    g_order[BATCH * N_TOK];
__device__ int    g_len[BATCH];
__device__ float  g_X[(size_t)M_MAX * D_MODEL];
__device__ float  g_qkv[(size_t)M_MAX * 3 * D_MODEL];   // reused as fp16 qkv
__device__ float  g_proj[(size_t)M_MAX * D_MODEL];
// fp16 activation buffers (al only used by 3-term patch GEMM)
__device__ __half g_ah[(size_t)M_MAX * D_MODEL];
__device__ __half g_al[(size_t)M_MAX * D_MODEL];
__device__ __half g_fh[(size_t)M_MAX * FF_DIM];
// fp16 weights (hi-only for 1-term GEMMs; patch keeps hi+lo)
__device__ __half g_wqkv_h[(size_t)N_LAYERS * 3 * D_MODEL * D_MODEL];
__device__ __half g_wo_h[(size_t)N_LAYERS * D_MODEL * D_MODEL];
__device__ __half g_wf1_h[(size_t)N_LAYERS * FF_DIM * D_MODEL];
__device__ __half g_wf2_h[(size_t)N_LAYERS * FF_DIM * D_MODEL];
__device__ __half g_wp_h[(size_t)D_MODEL * D_MODEL];
__device__ __half g_wp_l[(size_t)D_MODEL * D_MODEL];

// ============================================================================
// helpers
// ============================================================================
__device__ __forceinline__ uint32_t smem_u32(const void* p) {
    uint32_t a;
    asm("{ .reg .u64 t; cvta.to.shared.u64 t, %1; cvt.u32.u64 %0, t; }"
        : "=r"(a) : "l"(p));
    return a;
}
__device__ __forceinline__ void split_hl(float v, __half& h, __half& l) {
    h = __float2half(v);
    l = __float2half(v - __half2float(h));
}
__device__ __forceinline__ uint32_t f2h2(float a, float b) {
    __half2 h = __halves2half2(__float2half(a), __float2half(b));
    return *reinterpret_cast<uint32_t*>(&h);
}

#define CP_ASYNC_16(dst, src) \
    asm volatile("cp.async.cg.shared.global [%0], [%1], 16;" :: "r"(dst), "l"(src))
#define CP_COMMIT() asm volatile("cp.async.commit_group;" ::: "memory")
#define CP_WAIT(n)  asm volatile("cp.async.wait_group %0;" :: "n"(n) : "memory")

#define LDSM4(r0, r1, r2, r3, addr) \
    asm volatile("ldmatrix.sync.aligned.m8n8.x4.shared.b16 {%0,%1,%2,%3}, [%4];" \
        : "=r"(r0), "=r"(r1), "=r"(r2), "=r"(r3) : "r"(addr))

#define MMA16816(c, a, b) \
    asm volatile("mma.sync.aligned.m16n8k16.row.col.f32.f16.f16.f32 " \
        "{%0,%1,%2,%3}, {%4,%5,%6,%7}, {%8,%9}, {%0,%1,%2,%3};" \
        : "+f"((c)[0]), "+f"((c)[1]), "+f"((c)[2]), "+f"((c)[3]) \
        : "r"((a)[0]), "r"((a)[1]), "r"((a)[2]), "r"((a)[3]), \
          "r"((b)[0]), "r"((b)[1]))

// ============================================================================
// weight conversion
// ============================================================================
__global__ void split_kernel(const float4* __restrict__ src,
                             __half2* __restrict__ hi, __half2* __restrict__ lo, int n4)
{
    int i = blockIdx.x * blockDim.x + threadIdx.x;
    if (i >= n4) return;
    float4 v = src[i];
    __half h0, h1, h2, h3, l0, l1, l2, l3;
    split_hl(v.x, h0, l0); split_hl(v.y, h1, l1);
    split_hl(v.z, h2, l2); split_hl(v.w, h3, l3);
    hi[i * 2 + 0] = __halves2half2(h0, h1);
    hi[i * 2 + 1] = __halves2half2(h2, h3);
    lo[i * 2 + 0] = __halves2half2(l0, l1);
    lo[i * 2 + 1] = __halves2half2(l2, l3);
}

__global__ void cvt_kernel(const float4* __restrict__ src,
                           __half2* __restrict__ hi, int n4)
{
    int i = blockIdx.x * blockDim.x + threadIdx.x;
    if (i >= n4) return;
    float4 v = src[i];
    hi[i * 2 + 0] = __halves2half2(__float2half(v.x), __float2half(v.y));
    hi[i * 2 + 1] = __halves2half2(__float2half(v.z), __float2half(v.w));
}

// ============================================================================
// HMMA GEMM: 3-term / 2-term / 1-term via flags.
// 128x128 CTA tile, K-chunk 32, cp.async double buffer (40KB stages,
// 2 CTAs/SM), ldmatrix fragments, 8 warps (4m x 2n), warp tile 32x64.
// ============================================================================
#define ROW_BYTES   80
#define TILE_BYTES  (128 * ROW_BYTES)
#define STAGE_BYTES (4 * TILE_BYTES)
#define GEMM_SMEM   (2 * STAGE_BYTES)

__global__ void __launch_bounds__(256, 2)
mma_gemm_kernel(const __half* __restrict__ Ah, const __half* __restrict__ Al,
                const __half* __restrict__ Bh, const __half* __restrict__ Bl,
                const float* __restrict__ bias,
                float* __restrict__ C, __half* __restrict__ Ch, __half* __restrict__ Cl,
                int ldc, int M, int K, int flags)
{
    extern __shared__ char smem[];
    const uint32_t sb = smem_u32(smem);
    const int tid  = threadIdx.x;
    const int wid  = tid >> 5, lane = tid & 31;
    const int wm   = wid & 3, wn = wid >> 2;
    const int brow = blockIdx.y * 128;
    const int bcol = blockIdx.x * 128;
    const bool twoterm = (flags & F_2TERM) != 0;
    const bool oneterm = (flags & F_1TERM) != 0;

    float acc[2][8][4];
    #pragma unroll
    for (int mt = 0; mt < 2; mt++)
        #pragma unroll
        for (int nt = 0; nt < 8; nt++)
            #pragma unroll
            for (int i = 0; i < 4; i++) acc[mt][nt][i] = 0.0f;

    const int nC = K >> 5;

    auto load_chunk = [&](int c, int buf) {
        const int k0 = c << 5;
        const uint32_t tb = sb + (uint32_t)buf * STAGE_BYTES;
        #pragma unroll
        for (int j = 0; j < 8; j++) {
            int idx = tid + (j << 8);
            int op  = idx >> 9;
            if (twoterm && op == 1) continue;
            if (oneterm && op == 3) continue;
            int rem = idx & 511;
            int r   = rem >> 2;
            int q   = rem & 3;
            const __half* gp;
            if (op < 2) {
                int gr = brow + r;
                if (gr >= M) gr = M - 1;
                gp = (op ? Al : Ah) + (size_t)gr * K + k0 + (q << 3);
            } else {
                int gn = bcol + r;
                gp = (op == 3 ? Bl : Bh) + (size_t)gn * K + k0 + (q << 3);
            }
            uint32_t dst = tb + (uint32_t)op * TILE_BYTES + (uint32_t)r * ROW_BYTES + (q << 4);
            CP_ASYNC_16(dst, gp);
        }
        CP_COMMIT();
    };

    load_chunk(0, 0);

    const uint32_t a_off = (uint32_t)(wm * 32 + (lane & 15)) * ROW_BYTES
                         + (uint32_t)((lane >> 4) << 3) * 2;
    const int      b_mm  = lane >> 3;
    const uint32_t b_row_off = (uint32_t)(wn * 64 + ((b_mm >> 1) << 3) + (lane & 7)) * ROW_BYTES;
    const uint32_t b_k_off   = (uint32_t)((b_mm & 1) << 3) * 2;

    for (int c = 0; c < nC; c++) {
        const int buf = c & 1;
        if (c + 1 < nC) { load_chunk(c + 1, buf ^ 1); CP_WAIT(1); }
        else            { CP_WAIT(0); }
        __syncthreads();

        const uint32_t At  = sb + (uint32_t)buf * STAGE_BYTES;
        const uint32_t Alt = At + TILE_BYTES;
        const uint32_t Bt  = At + 2 * TILE_BYTES;
        const uint32_t Blt = At + 3 * TILE_BYTES;

        #pragma unroll
        for (int ks = 0; ks < 32; ks += 16) {
            uint32_t ah[2][4], bh[8][2];
            const uint32_t ksb = (uint32_t)ks * 2;
            LDSM4(ah[0][0], ah[0][1], ah[0][2], ah[0][3], At  + a_off + ksb);
            LDSM4(ah[1][0], ah[1][1], ah[1][2], ah[1][3], At  + a_off + ksb + 16 * ROW_BYTES);
            #pragma unroll
            for (int g = 0; g < 4; g++) {
                uint32_t off = b_row_off + (uint32_t)(g * 16) * ROW_BYTES + b_k_off + ksb;
                LDSM4(bh[2*g][0], bh[2*g][1], bh[2*g+1][0], bh[2*g+1][1], Bt + off);
            }
            #pragma unroll
            for (int mt = 0; mt < 2; mt++)
                #pragma unroll
                for (int nt = 0; nt < 8; nt++) MMA16816(acc[mt][nt], ah[mt], bh[nt]);
            if (!oneterm) {
                uint32_t bl[8][2];
                #pragma unroll
                for (int g = 0; g < 4; g++) {
                    uint32_t off = b_row_off + (uint32_t)(g * 16) * ROW_BYTES + b_k_off + ksb;
                    LDSM4(bl[2*g][0], bl[2*g][1], bl[2*g+1][0], bl[2*g+1][1], Blt + off);
                }
                #pragma unroll
                for (int mt = 0; mt < 2; mt++)
                    #pragma unroll
                    for (int nt = 0; nt < 8; nt++) MMA16816(acc[mt][nt], ah[mt], bl[nt]);
                if (!twoterm) {
                    uint32_t al[2][4];
                    LDSM4(al[0][0], al[0][1], al[0][2], al[0][3], Alt + a_off + ksb);
                    LDSM4(al[1][0], al[1][1], al[1][2], al[1][3], Alt + a_off + ksb + 16 * ROW_BYTES);
                    #pragma unroll
                    for (int mt = 0; mt < 2; mt++)
                        #pragma unroll
                        for (int nt = 0; nt < 8; nt++) MMA16816(acc[mt][nt], al[mt], bh[nt]);
                }
            }
        }
        __syncthreads();
    }

    const int lr = lane >> 2, lc = (lane & 3) * 2;
    #pragma unroll
    for (int mt = 0; mt < 2; mt++) {
        int r0 = brow + wm * 32 + mt * 16 + lr;
        #pragma unroll
        for (int nt = 0; nt < 8; nt++) {
            int cc = bcol + wn * 64 + nt * 8 + lc;
            float bv0 = 0.0f, bv1 = 0.0f;
            if (flags & F_BIAS) { bv0 = bias[cc]; bv1 = bias[cc + 1]; }
            #pragma unroll
            for (int half = 0; half < 2; half++) {
                int r = r0 + half * 8;
                if (r < M) {
                    float v0 = acc[mt][nt][half * 2 + 0] + bv0;
                    float v1 = acc[mt][nt][half * 2 + 1] + bv1;
                    if (flags & F_GELU) {
                        v0 = 0.5f * v0 * (1.0f + erff(v0 * 0.70710678118654752440f));
                        v1 = 0.5f * v1 * (1.0f + erff(v1 * 0.70710678118654752440f));
                    }
                    if (flags & F_OUT16) {
                        __half h0, h1, l0, l1;
                        split_hl(v0, h0, l0); split_hl(v1, h1, l1);
                        *(__half2*)(Ch + (size_t)r * ldc + cc) = __halves2half2(h0, h1);
                        if (!(flags & F_HIONLY))
                            *(__half2*)(Cl + (size_t)r * ldc + cc) = __halves2half2(l0, l1);
                    } else {
                        *(float2*)(C + (size_t)r * ldc + cc) = make_float2(v0, v1);
                    }
                }
            }
        }
    }
}

// ============================================================================
// mask parse
// ============================================================================
__global__ void mask_kernel(const unsigned char* __restrict__ mp)
{
    int tid = threadIdx.x;
    bool big = false, misal = false;
    for (int i = tid; i < BATCH * N_TOK; i += 256) {
        unsigned char v = mp[i];
        if (v >= 2) big = true;
        else if (v && (i & 3)) misal = true;
    }
    int anybig = __syncthreads_or(big ? 1 : 0);
    int anymis = __syncthreads_or(misal ? 1 : 0);
    int type = anybig ? 2 : (anymis ? 1 : 0);
    int b = tid;
    if (b < BATCH) {
        int cnt = 0;
        for (int t = 0; t < N_TOK; t++) {
            int idx = b * N_TOK + t;
            bool m;
            if (type == 2)      m = (((const float*)mp)[idx] != 0.0f);
            else if (type == 1) m = (mp[idx] != 0);
            else                m = (((const int*)mp)[idx] != 0);
            if (m) { g_order[b * N_TOK + cnt] = t; cnt++; }
        }
        g_len[b] = cnt;
    }
}

// ============================================================================
// im2col gather (patch GEMM is 3-term: hi+lo)
// ============================================================================
__global__ void im2col_kernel(const float* __restrict__ x, int Sc)
{
    int s = blockIdx.x, b = blockIdx.y;
    int m = b * Sc + s;
    __half* dh = g_ah + (size_t)m * D_MODEL;
    __half* dl = g_al + (size_t)m * D_MODEL;
    if (s >= g_len[b]) {
        for (int k = threadIdx.x; k < D_MODEL; k += blockDim.x) {
            dh[k] = __float2half(0.0f); dl[k] = __float2half(0.0f);
        }
        return;
    }
    int t = g_order[b * N_TOK + s];
    int gy = t / 14, gx = t % 14;
    const float* xb = x + (size_t)b * 3 * 224 * 224;
    for (int k = threadIdx.x; k < D_MODEL; k += blockDim.x) {
        int c = k >> 8, r = (k >> 4) & 15, cc = k & 15;
        float v = xb[((size_t)c * 224 + (gy * 16 + r)) * 224 + (gx * 16 + cc)];
        __half h, l; split_hl(v, h, l);
        dh[k] = h; dl[k] = l;
    }
}

// patch epilogue: X += patch_b + pos; emit hi fp16; zero pads.
__global__ void patch_epi_kernel(const float* __restrict__ pb,
                                 const float* __restrict__ pos, int Sc)
{
    int s = blockIdx.x, b = blockIdx.y;
    int m = b * Sc + s;
    float* row = g_X + (size_t)m * D_MODEL;
    __half* dh = g_ah + (size_t)m * D_MODEL;
    if (s >= g_len[b]) {
        for (int d = threadIdx.x; d < D_MODEL; d += blockDim.x) {
            row[d] = 0.0f;
            dh[d] = __float2half(0.0f);
        }
        return;
    }
    int t = g_order[b * N_TOK + s];
    const float* pr = pos + (size_t)t * D_MODEL;
    for (int d = threadIdx.x; d < D_MODEL; d += blockDim.x) {
        float v = row[d] + pb[d] + pr[d];
        row[d] = v;
        dh[d] = __float2half(v);
    }
}

// ============================================================================
// Tensor-core flash attention. One CTA per (b,h); 4 warps, each owns m16
// q-tiles (strided). Q/K fp16 in smem (144B rows), V transposed (VT[dim][key]).
// Online softmax in registers (fp32). Output: hi fp16 into g_ah.
// ============================================================================
__global__ void __launch_bounds__(128)
flash_tc_kernel(const __half* __restrict__ qkvh, int Sc, int ScPad)
{
    extern __shared__ char fsm[];
    const int b = blockIdx.x / N_HEADS, h = blockIdx.x % N_HEADS;
    const int len = g_len[b];
    const int tid = threadIdx.x, lane = tid & 31, wid = tid >> 5;

    const int vt_h = ScPad + 8;                     // VT row stride in halves
    __half* Qs = (__half*)fsm;                      // [ScPad][72]
    __half* Ks = Qs + (size_t)ScPad * 72;           // [ScPad][72]
    __half* VT = Ks + (size_t)ScPad * 72;           // [64][vt_h]
    const uint32_t Qb = smem_u32(Qs), Kb = smem_u32(Ks), Vb = smem_u32(VT);

    // fill smem
    for (int idx = tid; idx < ScPad * 64; idx += 128) {
        int r = idx >> 6, d = idx & 63;
        __half qv = __float2half(0.0f), kv = qv, vv = qv;
        if (r < Sc) {
            size_t base = (size_t)(b * Sc + r) * (3 * D_MODEL) + h * HEAD_DIM + d;
            qv = qkvh[base];
            kv = qkvh[base + D_MODEL];
            vv = qkvh[base + 2 * D_MODEL];
        }
        Qs[r * 72 + d] = qv;
        Ks[r * 72 + d] = kv;
        VT[d * vt_h + r] = vv;
    }
    __syncthreads();

    const uint32_t a_off = (uint32_t)(lane & 15) * 144 + (uint32_t)((lane >> 4) << 3) * 2;
    const int      b_mm  = lane >> 3;
    const uint32_t bk_row = (uint32_t)(((b_mm >> 1) << 3) + (lane & 7)) * 144;
    const uint32_t bv_row = (uint32_t)(((b_mm >> 1) << 3) + (lane & 7)) * (uint32_t)(vt_h * 2);
    const uint32_t bk_k   = (uint32_t)((b_mm & 1) << 3) * 2;

    const int nKC = (len + 15) >> 4;

    for (int qt = wid; qt * 16 < Sc; qt += 4) {
        uint32_t aq[4][4];
        #pragma unroll
        for (int ks = 0; ks < 4; ks++)
            LDSM4(aq[ks][0], aq[ks][1], aq[ks][2], aq[ks][3],
                  Qb + (uint32_t)(qt * 16) * 144 + a_off + ks * 32);

        float m0 = -1e30f, m1 = -1e30f, l0 = 0.0f, l1 = 0.0f;
        float o[8][4];
        #pragma unroll
        for (int t = 0; t < 8; t++)
            #pragma unroll
            for (int i = 0; i < 4; i++) o[t][i] = 0.0f;

        for (int kc = 0; kc < nKC; kc++) {
            float s0[4] = {0.f, 0.f, 0.f, 0.f}, s1[4] = {0.f, 0.f, 0.f, 0.f};
            #pragma unroll
            for (int ks = 0; ks < 4; ks++) {
                uint32_t r0, r1, r2, r3;
                LDSM4(r0, r1, r2, r3,
                      Kb + (uint32_t)(kc * 16) * 144 + bk_row + bk_k + ks * 32);
                uint32_t bh0[2] = {r0, r1}, bh1[2] = {r2, r3};
                MMA16816(s0, aq[ks], bh0);
                MMA16816(s1, aq[ks], bh1);
            }
            #pragma unroll
            for (int i = 0; i < 4; i++) { s0[i] *= 0.125f; s1[i] *= 0.125f; }
            // mask padded keys
            int colb = kc * 16 + ((lane & 3) << 1);
            if (colb     >= len) { s0[0] = -1e30f; s0[2] = -1e30f; }
            if (colb + 1 >= len) { s0[1] = -1e30f; s0[3] = -1e30f; }
            if (colb + 8 >= len) { s1[0] = -1e30f; s1[2] = -1e30f; }
            if (colb + 9 >= len) { s1[1] = -1e30f; s1[3] = -1e30f; }
            // row maxima (quad reduction)
            float mu = fmaxf(fmaxf(s0[0], s0[1]), fmaxf(s1[0], s1[1]));
            float mw = fmaxf(fmaxf(s0[2], s0[3]), fmaxf(s1[2], s1[3]));
            mu = fmaxf(mu, __shfl_xor_sync(0xffffffffu, mu, 1));
            mu = fmaxf(mu, __shfl_xor_sync(0xffffffffu, mu, 2));
            mw = fmaxf(mw, __shfl_xor_sync(0xffffffffu, mw, 1));
            mw = fmaxf(mw, __shfl_xor_sync(0xffffffffu, mw, 2));
            float mn0 = fmaxf(m0, mu), mn1 = fmaxf(m1, mw);
            float sc0 = __expf(m0 - mn0), sc1 = __expf(m1 - mn1);
            m0 = mn0; m1 = mn1;
            float p0 = __expf(s0[0] - mn0), p1 = __expf(s0[1] - mn0);
            float p2 = __expf(s1[0] - mn0), p3 = __expf(s1[1] - mn0);
            float p4 = __expf(s0[2] - mn1), p5 = __expf(s0[3] - mn1);
            float p6 = __expf(s1[2] - mn1), p7 = __expf(s1[3] - mn1);
            float su = (p0 + p1) + (p2 + p3);
            float sl = (p4 + p5) + (p6 + p7);
            su += __shfl_xor_sync(0xffffffffu, su, 1);
            su += __shfl_xor_sync(0xffffffffu, su, 2);
            sl += __shfl_xor_sync(0xffffffffu, sl, 1);
            sl += __shfl_xor_sync(0xffffffffu, sl, 2);
            l0 = l0 * sc0 + su;
            l1 = l1 * sc1 + sl;
            #pragma unroll
            for (int t = 0; t < 8; t++) {
                o[t][0] *= sc0; o[t][1] *= sc0;
                o[t][2] *= sc1; o[t][3] *= sc1;
            }
            // repack P into A-fragment (m16 k16)
            uint32_t ap[4];
            ap[0] = f2h2(p0, p1);   // rows g,   k0-7
            ap[1] = f2h2(p4, p5);   // rows g+8, k0-7
            ap[2] = f2h2(p2, p3);   // rows g,   k8-15
            ap[3] = f2h2(p6, p7);   // rows g+8, k8-15
            // P @ V via VT (dims are B-rows)
            #pragma unroll
            for (int g2 = 0; g2 < 4; g2++) {
                uint32_t r0, r1, r2, r3;
                LDSM4(r0, r1, r2, r3,
                      Vb + (uint32_t)(g2 * 16) * (vt_h * 2) + bv_row + bk_k + kc * 32);
                uint32_t bv0[2] = {r0, r1}, bv1[2] = {r2, r3};
                MMA16816(o[2 * g2],     ap, bv0);
                MMA16816(o[2 * g2 + 1], ap, bv1);
            }
        }
        float inv0 = 1.0f / l0, inv1 = 1.0f / l1;
        int r0 = qt * 16 + (lane >> 2), r1 = r0 + 8;
        #pragma unroll
        for (int t = 0; t < 8; t++) {
            int dim = t * 8 + ((lane & 3) << 1);
            if (r0 < Sc) {
                uint32_t u = f2h2(o[t][0] * inv0, o[t][1] * inv0);
                *(uint32_t*)(g_ah + (size_t)(b * Sc + r0) * D_MODEL + h * HEAD_DIM + dim) = u;
            }
            if (r1 < Sc) {
                uint32_t u = f2h2(o[t][2] * inv1, o[t][3] * inv1);
                *(uint32_t*)(g_ah + (size_t)(b * Sc + r1) * D_MODEL + h * HEAD_DIM + dim) = u;
            }
        }
    }
}

// ============================================================================
// LayerNorm (optionally +residual); optionally emits hi fp16.
// ============================================================================
__device__ __forceinline__ float blockReduce256(float v)
{
    __shared__ float sh[8];
    __syncthreads();
    #pragma unroll
    for (int o = 16; o; o >>= 1) v += __shfl_down_sync(0xffffffffu, v, o);
    if ((threadIdx.x & 31) == 0) sh[threadIdx.x >> 5] = v;
    __syncthreads();
    return sh[0] + sh[1] + sh[2] + sh[3] + sh[4] + sh[5] + sh[6] + sh[7];
}

template<bool RESID, bool EMITH>
__global__ void ln_kernel(const float* __restrict__ X, const float* __restrict__ Rsd,
                          const float* __restrict__ gma, const float* __restrict__ bta,
                          float* __restrict__ out, __half* __restrict__ outH)
{
    int m = blockIdx.x;
    int tid = threadIdx.x;
    const float* xr = X + (size_t)m * D_MODEL;
    float v[3];
    #pragma unroll
    for (int i = 0; i < 3; i++) {
        int d = tid + 256 * i;
        v[i] = xr[d];
        if (RESID) v[i] += Rsd[(size_t)m * D_MODEL + d];
    }
    float s = blockReduce256(v[0] + v[1] + v[2]);
    float mean = s * (1.0f / 768.0f);
    float q = 0.0f;
    #pragma unroll
    for (int i = 0; i < 3; i++) { float d = v[i] - mean; q += d * d; }
    q = blockReduce256(q);
    float inv = 1.0f / sqrtf(q * (1.0f / 768.0f) + 1e-5f);
    #pragma unroll
    for (int i = 0; i < 3; i++) {
        int d = tid + 256 * i;
        float r = (v[i] - mean) * inv * gma[d] + bta[d];
        out[(size_t)m * D_MODEL + d] = r;
        if (EMITH) outH[(size_t)m * D_MODEL + d] = __float2half(r);
    }
}

__global__ void pad_out_kernel(float* __restrict__ out2, int Sc)
{
    int i = blockIdx.x * blockDim.x + threadIdx.x;
    if (i < BATCH * Sc) {
        int b = i / Sc, s = i % Sc;
        out2[i] = (s >= g_len[b]) ? 1.0f : 0.0f;
    }
}

// ===========================================================================
static void run_cvt(const float* src, __half* hi, size_t n)
{
    int n4 = (int)(n >> 2);
    cvt_kernel<<<(n4 + 255) / 256, 256>>>((const float4*)src, (__half2*)hi, n4);
}

extern "C" void kernel_launch(void* const* d_in, const int* in_sizes, int n_in,
                              void* d_out, int out_size)
{
    const float* x       = (const float*)d_in[0];
    const void*  mask    = d_in[1];
    const float* patch_w = (const float*)d_in[2];
    const float* patch_b = (const float*)d_in[3];
    const float* pos     = (const float*)d_in[4];
    const float* inw     = (const float*)d_in[5];
    const float* inb     = (const float*)d_in[6];
    const float* outw    = (const float*)d_in[7];
    const float* outb    = (const float*)d_in[8];
    const float* ln1g    = (const float*)d_in[9];
    const float* ln1b    = (const float*)d_in[10];
    const float* f1w     = (const float*)d_in[11];
    const float* f1b     = (const float*)d_in[12];
    const float* f2w     = (const float*)d_in[13];
    const float* f2b     = (const float*)d_in[14];
    const float* ln2g    = (const float*)d_in[15];
    const float* ln2b    = (const float*)d_in[16];
    const float* ng      = (const float*)d_in[17];
    const float* nb      = (const float*)d_in[18];

    int Sc; bool tup;
    if (out_size % (64 * 769) == 0 &&
        out_size / (64 * 769) >= 1 && out_size / (64 * 769) <= N_TOK) {
        Sc = out_size / (64 * 769); tup = true;
    } else {
        Sc = out_size / (64 * 768); tup = false;
    }
    if (Sc < 1) Sc = 1;
    if (Sc > N_TOK) Sc = N_TOK;
    const int M  = BATCH * Sc;
    const int MB = (M + 127) / 128;
    const int ScPad = (Sc + 15) & ~15;
    const int flash_smem = 2 * ScPad * 144 + 64 * (ScPad + 8) * 2;

    float *pX, *pQ, *pP;
    __half *ah, *al, *fh, *wqh, *woh, *w1h, *w2h, *wph, *wpl;
    cudaGetSymbolAddress((void**)&pX,  g_X);
    cudaGetSymbolAddress((void**)&pQ,  g_qkv);
    cudaGetSymbolAddress((void**)&pP,  g_proj);
    cudaGetSymbolAddress((void**)&ah,  g_ah);
    cudaGetSymbolAddress((void**)&al,  g_al);
    cudaGetSymbolAddress((void**)&fh,  g_fh);
    cudaGetSymbolAddress((void**)&wqh, g_wqkv_h);
    cudaGetSymbolAddress((void**)&woh, g_wo_h);
    cudaGetSymbolAddress((void**)&w1h, g_wf1_h);
    cudaGetSymbolAddress((void**)&w2h, g_wf2_h);
    cudaGetSymbolAddress((void**)&wph, g_wp_h);
    cudaGetSymbolAddress((void**)&wpl, g_wp_l);
    __half* qkvh = (__half*)pQ;   // reuse fp32 qkv buffer as fp16 storage

    cudaFuncSetAttribute(mma_gemm_kernel, cudaFuncAttributeMaxDynamicSharedMemorySize,
                         GEMM_SMEM);
    cudaFuncSetAttribute(flash_tc_kernel, cudaFuncAttributeMaxDynamicSharedMemorySize,
                         110000);

    // --- weight conversion ----------------------------------------------------
    run_cvt(inw,  wqh, (size_t)N_LAYERS * 3 * D_MODEL * D_MODEL);
    run_cvt(outw, woh, (size_t)N_LAYERS * D_MODEL * D_MODEL);
    run_cvt(f1w,  w1h, (size_t)N_LAYERS * FF_DIM * D_MODEL);
    run_cvt(f2w,  w2h, (size_t)N_LAYERS * FF_DIM * D_MODEL);
    {
        int n4 = (int)(((size_t)D_MODEL * D_MODEL) >> 2);
        split_kernel<<<(n4 + 255) / 256, 256>>>((const float4*)patch_w,
                                                (__half2*)wph, (__half2*)wpl, n4);
    }

    // --- mask parse + gather + patch embedding --------------------------------
    mask_kernel<<<1, 256>>>((const unsigned char*)mask);
    im2col_kernel<<<dim3(Sc, BATCH), 256>>>(x, Sc);
    mma_gemm_kernel<<<dim3(6, MB), 256, GEMM_SMEM>>>(
        ah, al, wph, wpl, nullptr, pX, nullptr, nullptr, D_MODEL, M, D_MODEL, 0);
    patch_epi_kernel<<<dim3(Sc, BATCH), 256>>>(patch_b, pos, Sc);

    // --- transformer layers (all GEMMs pure fp16 1-term) ----------------------
    const int FT = F_BIAS | F_2TERM | F_1TERM;
    for (int l = 0; l < N_LAYERS; l++) {
        const __half* Wqh = wqh + (size_t)l * 3 * D_MODEL * D_MODEL;
        const __half* Woh = woh + (size_t)l * D_MODEL * D_MODEL;
        const __half* W1h = w1h + (size_t)l * FF_DIM * D_MODEL;
        const __half* W2h = w2h + (size_t)l * FF_DIM * D_MODEL;
        const float* bqkv = inb  + (size_t)l * 3 * D_MODEL;
        const float* bo   = outb + (size_t)l * D_MODEL;
        const float* b1   = f1b  + (size_t)l * FF_DIM;
        const float* b2   = f2b  + (size_t)l * D_MODEL;

        // QKV projection -> fp16 qkvh
        mma_gemm_kernel<<<dim3(18, MB), 256, GEMM_SMEM>>>(
            ah, nullptr, Wqh, nullptr, bqkv, nullptr, qkvh, nullptr,
            3 * D_MODEL, M, D_MODEL, FT | F_OUT16 | F_HIONLY);
        // tensor-core flash attention -> ah
        flash_tc_kernel<<<BATCH * N_HEADS, 128, flash_smem>>>(qkvh, Sc, ScPad);
        // output projection
        mma_gemm_kernel<<<dim3(6, MB), 256, GEMM_SMEM>>>(
            ah, nullptr, Woh, nullptr, bo, pP, nullptr, nullptr, D_MODEL, M, D_MODEL,
            FT);
        // residual + LN1 -> X, ah
        ln_kernel<true, true><<<M, 256>>>(pX, pP, ln1g + l * D_MODEL, ln1b + l * D_MODEL,
                                          pX, ah);
        // FFN1 (+GELU) -> fh (fp16 hi-only)
        mma_gemm_kernel<<<dim3(24, MB), 256, GEMM_SMEM>>>(
            ah, nullptr, W1h, nullptr, b1, nullptr, fh, nullptr, FF_DIM, M, D_MODEL,
            FT | F_GELU | F_OUT16 | F_HIONLY);
        // FFN2
        mma_gemm_kernel<<<dim3(6, MB), 256, GEMM_SMEM>>>(
            fh, nullptr, W2h, nullptr, b2, pP, nullptr, nullptr, D_MODEL, M, FF_DIM,
            FT);
        // residual + LN2 -> X, ah
        ln_kernel<true, true><<<M, 256>>>(pX, pP, ln2g + l * D_MODEL, ln2b + l * D_MODEL,
                                          pX, ah);
    }

    // --- final LN into d_out --------------------------------------------------
    ln_kernel<false, false><<<M, 256>>>(pX, nullptr, ng, nb, (float*)d_out, nullptr);
    if (tup) {
        pad_out_kernel<<<(BATCH * Sc + 255) / 256, 256>>>(
            (float*)d_out + (size_t)M * D_MODEL, Sc);
    }
}

// round 16
// speedup vs baseline: 3.1555x; 1.1096x over previous
#include <cuda_runtime.h>
#include <cuda_fp16.h>
#include <math.h>
#include <stdint.h>

// ============================================================================
// Masked ViT context encoder. R15: dedicated 1-term fp16 GEMM with K-chunk 64
// (2 CTAs/SM, halved barrier count) + residual fused into proj/FFN2 epilogues.
// Tensor-core flash attention. Patch GEMM stays 3-term (old kernel).
// ============================================================================

#define BATCH    64
#define N_TOK    196
#define D_MODEL  768
#define N_HEADS  12
#define HEAD_DIM 64
#define N_LAYERS 12
#define FF_DIM   3072
#define M_MAX    (BATCH * N_TOK)

// flags
#define F_BIAS    1
#define F_GELU    2
#define F_OUT16   4
#define F_2TERM   8
#define F_HIONLY  16
#define F_1TERM   32
#define F_RESID   64

// ---------------- scratch (device globals; no allocation allowed) -----------
__device__ int    g_order[BATCH * N_TOK];
__device__ int    g_len[BATCH];
__device__ float  g_X[(size_t)M_MAX * D_MODEL];
__device__ float  g_qkv[(size_t)M_MAX * 3 * D_MODEL];   // reused as fp16 qkv
__device__ float  g_proj[(size_t)M_MAX * D_MODEL];
__device__ __half g_ah[(size_t)M_MAX * D_MODEL];
__device__ __half g_al[(size_t)M_MAX * D_MODEL];
__device__ __half g_fh[(size_t)M_MAX * FF_DIM];
__device__ __half g_wqkv_h[(size_t)N_LAYERS * 3 * D_MODEL * D_MODEL];
__device__ __half g_wo_h[(size_t)N_LAYERS * D_MODEL * D_MODEL];
__device__ __half g_wf1_h[(size_t)N_LAYERS * FF_DIM * D_MODEL];
__device__ __half g_wf2_h[(size_t)N_LAYERS * FF_DIM * D_MODEL];
__device__ __half g_wp_h[(size_t)D_MODEL * D_MODEL];
__device__ __half g_wp_l[(size_t)D_MODEL * D_MODEL];

// ============================================================================
// helpers
// ============================================================================
__device__ __forceinline__ uint32_t smem_u32(const void* p) {
    uint32_t a;
    asm("{ .reg .u64 t; cvta.to.shared.u64 t, %1; cvt.u32.u64 %0, t; }"
        : "=r"(a) : "l"(p));
    return a;
}
__device__ __forceinline__ void split_hl(float v, __half& h, __half& l) {
    h = __float2half(v);
    l = __float2half(v - __half2float(h));
}
__device__ __forceinline__ uint32_t f2h2(float a, float b) {
    __half2 h = __halves2half2(__float2half(a), __float2half(b));
    return *reinterpret_cast<uint32_t*>(&h);
}

#define CP_ASYNC_16(dst, src) \
    asm volatile("cp.async.cg.shared.global [%0], [%1], 16;" :: "r"(dst), "l"(src))
#define CP_COMMIT() asm volatile("cp.async.commit_group;" ::: "memory")
#define CP_WAIT(n)  asm volatile("cp.async.wait_group %0;" :: "n"(n) : "memory")

#define LDSM4(r0, r1, r2, r3, addr) \
    asm volatile("ldmatrix.sync.aligned.m8n8.x4.shared.b16 {%0,%1,%2,%3}, [%4];" \
        : "=r"(r0), "=r"(r1), "=r"(r2), "=r"(r3) : "r"(addr))

#define MMA16816(c, a, b) \
    asm volatile("mma.sync.aligned.m16n8k16.row.col.f32.f16.f16.f32 " \
        "{%0,%1,%2,%3}, {%4,%5,%6,%7}, {%8,%9}, {%0,%1,%2,%3};" \
        : "+f"((c)[0]), "+f"((c)[1]), "+f"((c)[2]), "+f"((c)[3]) \
        : "r"((a)[0]), "r"((a)[1]), "r"((a)[2]), "r"((a)[3]), \
          "r"((b)[0]), "r"((b)[1]))

// ============================================================================
// weight conversion
// ============================================================================
__global__ void split_kernel(const float4* __restrict__ src,
                             __half2* __restrict__ hi, __half2* __restrict__ lo, int n4)
{
    int i = blockIdx.x * blockDim.x + threadIdx.x;
    if (i >= n4) return;
    float4 v = src[i];
    __half h0, h1, h2, h3, l0, l1, l2, l3;
    split_hl(v.x, h0, l0); split_hl(v.y, h1, l1);
    split_hl(v.z, h2, l2); split_hl(v.w, h3, l3);
    hi[i * 2 + 0] = __halves2half2(h0, h1);
    hi[i * 2 + 1] = __halves2half2(h2, h3);
    lo[i * 2 + 0] = __halves2half2(l0, l1);
    lo[i * 2 + 1] = __halves2half2(l2, l3);
}

__global__ void cvt_kernel(const float4* __restrict__ src,
                           __half2* __restrict__ hi, int n4)
{
    int i = blockIdx.x * blockDim.x + threadIdx.x;
    if (i >= n4) return;
    float4 v = src[i];
    hi[i * 2 + 0] = __halves2half2(__float2half(v.x), __float2half(v.y));
    hi[i * 2 + 1] = __halves2half2(__float2half(v.z), __float2half(v.w));
}

// ============================================================================
// 3-term GEMM (patch only) — proven R7 kernel, K-chunk 32.
// ============================================================================
#define ROW_BYTES   80
#define TILE_BYTES  (128 * ROW_BYTES)
#define STAGE_BYTES (4 * TILE_BYTES)
#define GEMM_SMEM   (2 * STAGE_BYTES)

__global__ void __launch_bounds__(256, 2)
mma_gemm_kernel(const __half* __restrict__ Ah, const __half* __restrict__ Al,
                const __half* __restrict__ Bh, const __half* __restrict__ Bl,
                const float* __restrict__ bias,
                float* __restrict__ C, int ldc, int M, int K, int flags)
{
    extern __shared__ char smem[];
    const uint32_t sb = smem_u32(smem);
    const int tid  = threadIdx.x;
    const int wid  = tid >> 5, lane = tid & 31;
    const int wm   = wid & 3, wn = wid >> 2;
    const int brow = blockIdx.y * 128;
    const int bcol = blockIdx.x * 128;

    float acc[2][8][4];
    #pragma unroll
    for (int mt = 0; mt < 2; mt++)
        #pragma unroll
        for (int nt = 0; nt < 8; nt++)
            #pragma unroll
            for (int i = 0; i < 4; i++) acc[mt][nt][i] = 0.0f;

    const int nC = K >> 5;

    auto load_chunk = [&](int c, int buf) {
        const int k0 = c << 5;
        const uint32_t tb = sb + (uint32_t)buf * STAGE_BYTES;
        #pragma unroll
        for (int j = 0; j < 8; j++) {
            int idx = tid + (j << 8);
            int op  = idx >> 9;
            int rem = idx & 511;
            int r   = rem >> 2;
            int q   = rem & 3;
            const __half* gp;
            if (op < 2) {
                int gr = brow + r;
                if (gr >= M) gr = M - 1;
                gp = (op ? Al : Ah) + (size_t)gr * K + k0 + (q << 3);
            } else {
                int gn = bcol + r;
                gp = (op == 3 ? Bl : Bh) + (size_t)gn * K + k0 + (q << 3);
            }
            uint32_t dst = tb + (uint32_t)op * TILE_BYTES + (uint32_t)r * ROW_BYTES + (q << 4);
            CP_ASYNC_16(dst, gp);
        }
        CP_COMMIT();
    };

    load_chunk(0, 0);

    const uint32_t a_off = (uint32_t)(wm * 32 + (lane & 15)) * ROW_BYTES
                         + (uint32_t)((lane >> 4) << 3) * 2;
    const int      b_mm  = lane >> 3;
    const uint32_t b_row_off = (uint32_t)(wn * 64 + ((b_mm >> 1) << 3) + (lane & 7)) * ROW_BYTES;
    const uint32_t b_k_off   = (uint32_t)((b_mm & 1) << 3) * 2;

    for (int c = 0; c < nC; c++) {
        const int buf = c & 1;
        if (c + 1 < nC) { load_chunk(c + 1, buf ^ 1); CP_WAIT(1); }
        else            { CP_WAIT(0); }
        __syncthreads();

        const uint32_t At  = sb + (uint32_t)buf * STAGE_BYTES;
        const uint32_t Alt = At + TILE_BYTES;
        const uint32_t Bt  = At + 2 * TILE_BYTES;
        const uint32_t Blt = At + 3 * TILE_BYTES;

        #pragma unroll
        for (int ks = 0; ks < 32; ks += 16) {
            uint32_t ah[2][4], bh[8][2], bl[8][2];
            const uint32_t ksb = (uint32_t)ks * 2;
            LDSM4(ah[0][0], ah[0][1], ah[0][2], ah[0][3], At  + a_off + ksb);
            LDSM4(ah[1][0], ah[1][1], ah[1][2], ah[1][3], At  + a_off + ksb + 16 * ROW_BYTES);
            #pragma unroll
            for (int g = 0; g < 4; g++) {
                uint32_t off = b_row_off + (uint32_t)(g * 16) * ROW_BYTES + b_k_off + ksb;
                LDSM4(bh[2*g][0], bh[2*g][1], bh[2*g+1][0], bh[2*g+1][1], Bt  + off);
                LDSM4(bl[2*g][0], bl[2*g][1], bl[2*g+1][0], bl[2*g+1][1], Blt + off);
            }
            #pragma unroll
            for (int mt = 0; mt < 2; mt++)
                #pragma unroll
                for (int nt = 0; nt < 8; nt++) MMA16816(acc[mt][nt], ah[mt], bh[nt]);
            #pragma unroll
            for (int mt = 0; mt < 2; mt++)
                #pragma unroll
                for (int nt = 0; nt < 8; nt++) MMA16816(acc[mt][nt], ah[mt], bl[nt]);
            {
                uint32_t al[2][4];
                LDSM4(al[0][0], al[0][1], al[0][2], al[0][3], Alt + a_off + ksb);
                LDSM4(al[1][0], al[1][1], al[1][2], al[1][3], Alt + a_off + ksb + 16 * ROW_BYTES);
                #pragma unroll
                for (int mt = 0; mt < 2; mt++)
                    #pragma unroll
                    for (int nt = 0; nt < 8; nt++) MMA16816(acc[mt][nt], al[mt], bh[nt]);
            }
        }
        __syncthreads();
    }

    const int lr = lane >> 2, lc = (lane & 3) * 2;
    #pragma unroll
    for (int mt = 0; mt < 2; mt++) {
        int r0 = brow + wm * 32 + mt * 16 + lr;
        #pragma unroll
        for (int nt = 0; nt < 8; nt++) {
            int cc = bcol + wn * 64 + nt * 8 + lc;
            float bv0 = 0.0f, bv1 = 0.0f;
            if (flags & F_BIAS) { bv0 = bias[cc]; bv1 = bias[cc + 1]; }
            #pragma unroll
            for (int half = 0; half < 2; half++) {
                int r = r0 + half * 8;
                if (r < M) {
                    float v0 = acc[mt][nt][half * 2 + 0] + bv0;
                    float v1 = acc[mt][nt][half * 2 + 1] + bv1;
                    *(float2*)(C + (size_t)r * ldc + cc) = make_float2(v0, v1);
                }
            }
        }
    }
}

// ============================================================================
// 1-term fp16 GEMM: C = A(fp16) @ B(fp16)^T, fp32 accum. K-chunk 64,
// 36.9KB stages (2 buffers = 73.7KB => 2 CTAs/SM), ldmatrix, 8 warps (4m x 2n).
// flags: F_BIAS, F_GELU, F_OUT16 (write hi fp16 to Ch), F_RESID (C += R).
// ============================================================================
#define G1_ROW   144
#define G1_TILE  (128 * G1_ROW)       // 18432
#define G1_STAGE (2 * G1_TILE)        // 36864
#define G1_SMEM  (2 * G1_STAGE)       // 73728

__global__ void __launch_bounds__(256, 2)
gemm1_kernel(const __half* __restrict__ A, const __half* __restrict__ B,
             const float* __restrict__ bias, const float* __restrict__ R,
             float* __restrict__ C, __half* __restrict__ Ch,
             int ldc, int M, int K, int flags)
{
    extern __shared__ char smem[];
    const uint32_t sb = smem_u32(smem);
    const int tid  = threadIdx.x;
    const int wid  = tid >> 5, lane = tid & 31;
    const int wm   = wid & 3, wn = wid >> 2;     // 4(m) x 2(n)
    const int brow = blockIdx.y * 128;
    const int bcol = blockIdx.x * 128;

    float acc[2][8][4];
    #pragma unroll
    for (int mt = 0; mt < 2; mt++)
        #pragma unroll
        for (int nt = 0; nt < 8; nt++)
            #pragma unroll
            for (int i = 0; i < 4; i++) acc[mt][nt][i] = 0.0f;

    const int nC = K >> 6;

    // 2048 16B-chunks per stage (A:1024, B:1024); 8 per thread.
    auto load_chunk = [&](int c, int buf) {
        const int k0 = c << 6;
        const uint32_t tb = sb + (uint32_t)buf * G1_STAGE;
        #pragma unroll
        for (int j = 0; j < 8; j++) {
            int idx = tid + (j << 8);
            int op  = idx >> 10;          // 0=A 1=B
            int rem = idx & 1023;
            int r   = rem >> 3;           // row 0..127
            int q   = rem & 7;            // 16B chunk
            const __half* gp;
            if (op == 0) {
                int gr = brow + r;
                if (gr >= M) gr = M - 1;
                gp = A + (size_t)gr * K + k0 + (q << 3);
            } else {
                int gn = bcol + r;
                gp = B + (size_t)gn * K + k0 + (q << 3);
            }
            uint32_t dst = tb + (uint32_t)op * G1_TILE + (uint32_t)r * G1_ROW + (q << 4);
            CP_ASYNC_16(dst, gp);
        }
        CP_COMMIT();
    };

    load_chunk(0, 0);

    const uint32_t a_off = (uint32_t)(wm * 32 + (lane & 15)) * G1_ROW
                         + (uint32_t)((lane >> 4) << 3) * 2;
    const int      b_mm  = lane >> 3;
    const uint32_t b_row_off = (uint32_t)(wn * 64 + ((b_mm >> 1) << 3) + (lane & 7)) * G1_ROW;
    const uint32_t b_k_off   = (uint32_t)((b_mm & 1) << 3) * 2;

    for (int c = 0; c < nC; c++) {
        const int buf = c & 1;
        if (c + 1 < nC) { load_chunk(c + 1, buf ^ 1); CP_WAIT(1); }
        else            { CP_WAIT(0); }
        __syncthreads();

        const uint32_t At = sb + (uint32_t)buf * G1_STAGE;
        const uint32_t Bt = At + G1_TILE;

        #pragma unroll
        for (int ks = 0; ks < 64; ks += 16) {
            uint32_t ar[2][4], br[8][2];
            const uint32_t ksb = (uint32_t)ks * 2;
            LDSM4(ar[0][0], ar[0][1], ar[0][2], ar[0][3], At + a_off + ksb);
            LDSM4(ar[1][0], ar[1][1], ar[1][2], ar[1][3], At + a_off + ksb + 16 * G1_ROW);
            #pragma unroll
            for (int g = 0; g < 4; g++) {
                uint32_t off = b_row_off + (uint32_t)(g * 16) * G1_ROW + b_k_off + ksb;
                LDSM4(br[2*g][0], br[2*g][1], br[2*g+1][0], br[2*g+1][1], Bt + off);
            }
            #pragma unroll
            for (int mt = 0; mt < 2; mt++)
                #pragma unroll
                for (int nt = 0; nt < 8; nt++) MMA16816(acc[mt][nt], ar[mt], br[nt]);
        }
        __syncthreads();
    }

    const int lr = lane >> 2, lc = (lane & 3) * 2;
    #pragma unroll
    for (int mt = 0; mt < 2; mt++) {
        int r0 = brow + wm * 32 + mt * 16 + lr;
        #pragma unroll
        for (int nt = 0; nt < 8; nt++) {
            int cc = bcol + wn * 64 + nt * 8 + lc;
            float bv0 = 0.0f, bv1 = 0.0f;
            if (flags & F_BIAS) { bv0 = bias[cc]; bv1 = bias[cc + 1]; }
            #pragma unroll
            for (int half = 0; half < 2; half++) {
                int r = r0 + half * 8;
                if (r < M) {
                    float v0 = acc[mt][nt][half * 2 + 0] + bv0;
                    float v1 = acc[mt][nt][half * 2 + 1] + bv1;
                    if (flags & F_RESID) {
                        float2 rr = *(const float2*)(R + (size_t)r * ldc + cc);
                        v0 += rr.x; v1 += rr.y;
                    }
                    if (flags & F_GELU) {
                        v0 = 0.5f * v0 * (1.0f + erff(v0 * 0.70710678118654752440f));
                        v1 = 0.5f * v1 * (1.0f + erff(v1 * 0.70710678118654752440f));
                    }
                    if (flags & F_OUT16) {
                        *(uint32_t*)(Ch + (size_t)r * ldc + cc) = f2h2(v0, v1);
                    } else {
                        *(float2*)(C + (size_t)r * ldc + cc) = make_float2(v0, v1);
                    }
                }
            }
        }
    }
}

// ============================================================================
// mask parse
// ============================================================================
__global__ void mask_kernel(const unsigned char* __restrict__ mp)
{
    int tid = threadIdx.x;
    bool big = false, misal = false;
    for (int i = tid; i < BATCH * N_TOK; i += 256) {
        unsigned char v = mp[i];
        if (v >= 2) big = true;
        else if (v && (i & 3)) misal = true;
    }
    int anybig = __syncthreads_or(big ? 1 : 0);
    int anymis = __syncthreads_or(misal ? 1 : 0);
    int type = anybig ? 2 : (anymis ? 1 : 0);
    int b = tid;
    if (b < BATCH) {
        int cnt = 0;
        for (int t = 0; t < N_TOK; t++) {
            int idx = b * N_TOK + t;
            bool m;
            if (type == 2)      m = (((const float*)mp)[idx] != 0.0f);
            else if (type == 1) m = (mp[idx] != 0);
            else                m = (((const int*)mp)[idx] != 0);
            if (m) { g_order[b * N_TOK + cnt] = t; cnt++; }
        }
        g_len[b] = cnt;
    }
}

// ============================================================================
// im2col gather (patch GEMM is 3-term: hi+lo)
// ============================================================================
__global__ void im2col_kernel(const float* __restrict__ x, int Sc)
{
    int s = blockIdx.x, b = blockIdx.y;
    int m = b * Sc + s;
    __half* dh = g_ah + (size_t)m * D_MODEL;
    __half* dl = g_al + (size_t)m * D_MODEL;
    if (s >= g_len[b]) {
        for (int k = threadIdx.x; k < D_MODEL; k += blockDim.x) {
            dh[k] = __float2half(0.0f); dl[k] = __float2half(0.0f);
        }
        return;
    }
    int t = g_order[b * N_TOK + s];
    int gy = t / 14, gx = t % 14;
    const float* xb = x + (size_t)b * 3 * 224 * 224;
    for (int k = threadIdx.x; k < D_MODEL; k += blockDim.x) {
        int c = k >> 8, r = (k >> 4) & 15, cc = k & 15;
        float v = xb[((size_t)c * 224 + (gy * 16 + r)) * 224 + (gx * 16 + cc)];
        __half h, l; split_hl(v, h, l);
        dh[k] = h; dl[k] = l;
    }
}

// patch epilogue: X += patch_b + pos; emit hi fp16; zero pads.
__global__ void patch_epi_kernel(const float* __restrict__ pb,
                                 const float* __restrict__ pos, int Sc)
{
    int s = blockIdx.x, b = blockIdx.y;
    int m = b * Sc + s;
    float* row = g_X + (size_t)m * D_MODEL;
    __half* dh = g_ah + (size_t)m * D_MODEL;
    if (s >= g_len[b]) {
        for (int d = threadIdx.x; d < D_MODEL; d += blockDim.x) {
            row[d] = 0.0f;
            dh[d] = __float2half(0.0f);
        }
        return;
    }
    int t = g_order[b * N_TOK + s];
    const float* pr = pos + (size_t)t * D_MODEL;
    for (int d = threadIdx.x; d < D_MODEL; d += blockDim.x) {
        float v = row[d] + pb[d] + pr[d];
        row[d] = v;
        dh[d] = __float2half(v);
    }
}

// ============================================================================
// Tensor-core flash attention (unchanged from R14).
// ============================================================================
__global__ void __launch_bounds__(128)
flash_tc_kernel(const __half* __restrict__ qkvh, int Sc, int ScPad)
{
    extern __shared__ char fsm[];
    const int b = blockIdx.x / N_HEADS, h = blockIdx.x % N_HEADS;
    const int len = g_len[b];
    const int tid = threadIdx.x, lane = tid & 31, wid = tid >> 5;

    const int vt_h = ScPad + 8;
    __half* Qs = (__half*)fsm;
    __half* Ks = Qs + (size_t)ScPad * 72;
    __half* VT = Ks + (size_t)ScPad * 72;
    const uint32_t Qb = smem_u32(Qs), Kb = smem_u32(Ks), Vb = smem_u32(VT);

    for (int idx = tid; idx < ScPad * 64; idx += 128) {
        int r = idx >> 6, d = idx & 63;
        __half qv = __float2half(0.0f), kv = qv, vv = qv;
        if (r < Sc) {
            size_t base = (size_t)(b * Sc + r) * (3 * D_MODEL) + h * HEAD_DIM + d;
            qv = qkvh[base];
            kv = qkvh[base + D_MODEL];
            vv = qkvh[base + 2 * D_MODEL];
        }
        Qs[r * 72 + d] = qv;
        Ks[r * 72 + d] = kv;
        VT[d * vt_h + r] = vv;
    }
    __syncthreads();

    const uint32_t a_off = (uint32_t)(lane & 15) * 144 + (uint32_t)((lane >> 4) << 3) * 2;
    const int      b_mm  = lane >> 3;
    const uint32_t bk_row = (uint32_t)(((b_mm >> 1) << 3) + (lane & 7)) * 144;
    const uint32_t bv_row = (uint32_t)(((b_mm >> 1) << 3) + (lane & 7)) * (uint32_t)(vt_h * 2);
    const uint32_t bk_k   = (uint32_t)((b_mm & 1) << 3) * 2;

    const int nKC = (len + 15) >> 4;

    for (int qt = wid; qt * 16 < Sc; qt += 4) {
        uint32_t aq[4][4];
        #pragma unroll
        for (int ks = 0; ks < 4; ks++)
            LDSM4(aq[ks][0], aq[ks][1], aq[ks][2], aq[ks][3],
                  Qb + (uint32_t)(qt * 16) * 144 + a_off + ks * 32);

        float m0 = -1e30f, m1 = -1e30f, l0 = 0.0f, l1 = 0.0f;
        float o[8][4];
        #pragma unroll
        for (int t = 0; t < 8; t++)
            #pragma unroll
            for (int i = 0; i < 4; i++) o[t][i] = 0.0f;

        for (int kc = 0; kc < nKC; kc++) {
            float s0[4] = {0.f, 0.f, 0.f, 0.f}, s1[4] = {0.f, 0.f, 0.f, 0.f};
            #pragma unroll
            for (int ks = 0; ks < 4; ks++) {
                uint32_t r0, r1, r2, r3;
                LDSM4(r0, r1, r2, r3,
                      Kb + (uint32_t)(kc * 16) * 144 + bk_row + bk_k + ks * 32);
                uint32_t bh0[2] = {r0, r1}, bh1[2] = {r2, r3};
                MMA16816(s0, aq[ks], bh0);
                MMA16816(s1, aq[ks], bh1);
            }
            #pragma unroll
            for (int i = 0; i < 4; i++) { s0[i] *= 0.125f; s1[i] *= 0.125f; }
            int colb = kc * 16 + ((lane & 3) << 1);
            if (colb     >= len) { s0[0] = -1e30f; s0[2] = -1e30f; }
            if (colb + 1 >= len) { s0[1] = -1e30f; s0[3] = -1e30f; }
            if (colb + 8 >= len) { s1[0] = -1e30f; s1[2] = -1e30f; }
            if (colb + 9 >= len) { s1[1] = -1e30f; s1[3] = -1e30f; }
            float mu = fmaxf(fmaxf(s0[0], s0[1]), fmaxf(s1[0], s1[1]));
            float mw = fmaxf(fmaxf(s0[2], s0[3]), fmaxf(s1[2], s1[3]));
            mu = fmaxf(mu, __shfl_xor_sync(0xffffffffu, mu, 1));
            mu = fmaxf(mu, __shfl_xor_sync(0xffffffffu, mu, 2));
            mw = fmaxf(mw, __shfl_xor_sync(0xffffffffu, mw, 1));
            mw = fmaxf(mw, __shfl_xor_sync(0xffffffffu, mw, 2));
            float mn0 = fmaxf(m0, mu), mn1 = fmaxf(m1, mw);
            float sc0 = __expf(m0 - mn0), sc1 = __expf(m1 - mn1);
            m0 = mn0; m1 = mn1;
            float p0 = __expf(s0[0] - mn0), p1 = __expf(s0[1] - mn0);
            float p2 = __expf(s1[0] - mn0), p3 = __expf(s1[1] - mn0);
            float p4 = __expf(s0[2] - mn1), p5 = __expf(s0[3] - mn1);
            float p6 = __expf(s1[2] - mn1), p7 = __expf(s1[3] - mn1);
            float su = (p0 + p1) + (p2 + p3);
            float sl = (p4 + p5) + (p6 + p7);
            su += __shfl_xor_sync(0xffffffffu, su, 1);
            su += __shfl_xor_sync(0xffffffffu, su, 2);
            sl += __shfl_xor_sync(0xffffffffu, sl, 1);
            sl += __shfl_xor_sync(0xffffffffu, sl, 2);
            l0 = l0 * sc0 + su;
            l1 = l1 * sc1 + sl;
            #pragma unroll
            for (int t = 0; t < 8; t++) {
                o[t][0] *= sc0; o[t][1] *= sc0;
                o[t][2] *= sc1; o[t][3] *= sc1;
            }
            uint32_t ap[4];
            ap[0] = f2h2(p0, p1);
            ap[1] = f2h2(p4, p5);
            ap[2] = f2h2(p2, p3);
            ap[3] = f2h2(p6, p7);
            #pragma unroll
            for (int g2 = 0; g2 < 4; g2++) {
                uint32_t r0, r1, r2, r3;
                LDSM4(r0, r1, r2, r3,
                      Vb + (uint32_t)(g2 * 16) * (vt_h * 2) + bv_row + bk_k + kc * 32);
                uint32_t bv0[2] = {r0, r1}, bv1[2] = {r2, r3};
                MMA16816(o[2 * g2],     ap, bv0);
                MMA16816(o[2 * g2 + 1], ap, bv1);
            }
        }
        float inv0 = 1.0f / l0, inv1 = 1.0f / l1;
        int r0 = qt * 16 + (lane >> 2), r1 = r0 + 8;
        #pragma unroll
        for (int t = 0; t < 8; t++) {
            int dim = t * 8 + ((lane & 3) << 1);
            if (r0 < Sc) {
                uint32_t u = f2h2(o[t][0] * inv0, o[t][1] * inv0);
                *(uint32_t*)(g_ah + (size_t)(b * Sc + r0) * D_MODEL + h * HEAD_DIM + dim) = u;
            }
            if (r1 < Sc) {
                uint32_t u = f2h2(o[t][2] * inv1, o[t][3] * inv1);
                *(uint32_t*)(g_ah + (size_t)(b * Sc + r1) * D_MODEL + h * HEAD_DIM + dim) = u;
            }
        }
    }
}

// ============================================================================
// LayerNorm (optionally +residual); optionally emits hi fp16.
// ============================================================================
__device__ __forceinline__ float blockReduce256(float v)
{
    __shared__ float sh[8];
    __syncthreads();
    #pragma unroll
    for (int o = 16; o; o >>= 1) v += __shfl_down_sync(0xffffffffu, v, o);
    if ((threadIdx.x & 31) == 0) sh[threadIdx.x >> 5] = v;
    __syncthreads();
    return sh[0] + sh[1] + sh[2] + sh[3] + sh[4] + sh[5] + sh[6] + sh[7];
}

template<bool RESID, bool EMITH>
__global__ void ln_kernel(const float* __restrict__ X, const float* __restrict__ Rsd,
                          const float* __restrict__ gma, const float* __restrict__ bta,
                          float* __restrict__ out, __half* __restrict__ outH)
{
    int m = blockIdx.x;
    int tid = threadIdx.x;
    const float* xr = X + (size_t)m * D_MODEL;
    float v[3];
    #pragma unroll
    for (int i = 0; i < 3; i++) {
        int d = tid + 256 * i;
        v[i] = xr[d];
        if (RESID) v[i] += Rsd[(size_t)m * D_MODEL + d];
    }
    float s = blockReduce256(v[0] + v[1] + v[2]);
    float mean = s * (1.0f / 768.0f);
    float q = 0.0f;
    #pragma unroll
    for (int i = 0; i < 3; i++) { float d = v[i] - mean; q += d * d; }
    q = blockReduce256(q);
    float inv = 1.0f / sqrtf(q * (1.0f / 768.0f) + 1e-5f);
    #pragma unroll
    for (int i = 0; i < 3; i++) {
        int d = tid + 256 * i;
        float r = (v[i] - mean) * inv * gma[d] + bta[d];
        out[(size_t)m * D_MODEL + d] = r;
        if (EMITH) outH[(size_t)m * D_MODEL + d] = __float2half(r);
    }
}

__global__ void pad_out_kernel(float* __restrict__ out2, int Sc)
{
    int i = blockIdx.x * blockDim.x + threadIdx.x;
    if (i < BATCH * Sc) {
        int b = i / Sc, s = i % Sc;
        out2[i] = (s >= g_len[b]) ? 1.0f : 0.0f;
    }
}

// ===========================================================================
static void run_cvt(const float* src, __half* hi, size_t n)
{
    int n4 = (int)(n >> 2);
    cvt_kernel<<<(n4 + 255) / 256, 256>>>((const float4*)src, (__half2*)hi, n4);
}

extern "C" void kernel_launch(void* const* d_in, const int* in_sizes, int n_in,
                              void* d_out, int out_size)
{
    const float* x       = (const float*)d_in[0];
    const void*  mask    = d_in[1];
    const float* patch_w = (const float*)d_in[2];
    const float* patch_b = (const float*)d_in[3];
    const float* pos     = (const float*)d_in[4];
    const float* inw     = (const float*)d_in[5];
    const float* inb     = (const float*)d_in[6];
    const float* outw    = (const float*)d_in[7];
    const float* outb    = (const float*)d_in[8];
    const float* ln1g    = (const float*)d_in[9];
    const float* ln1b    = (const float*)d_in[10];
    const float* f1w     = (const float*)d_in[11];
    const float* f1b     = (const float*)d_in[12];
    const float* f2w     = (const float*)d_in[13];
    const float* f2b     = (const float*)d_in[14];
    const float* ln2g    = (const float*)d_in[15];
    const float* ln2b    = (const float*)d_in[16];
    const float* ng      = (const float*)d_in[17];
    const float* nb      = (const float*)d_in[18];

    int Sc; bool tup;
    if (out_size % (64 * 769) == 0 &&
        out_size / (64 * 769) >= 1 && out_size / (64 * 769) <= N_TOK) {
        Sc = out_size / (64 * 769); tup = true;
    } else {
        Sc = out_size / (64 * 768); tup = false;
    }
    if (Sc < 1) Sc = 1;
    if (Sc > N_TOK) Sc = N_TOK;
    const int M  = BATCH * Sc;
    const int MB = (M + 127) / 128;
    const int ScPad = (Sc + 15) & ~15;
    const int flash_smem = 2 * ScPad * 144 + 64 * (ScPad + 8) * 2;

    float *pX, *pQ, *pP;
    __half *ah, *al, *fh, *wqh, *woh, *w1h, *w2h, *wph, *wpl;
    cudaGetSymbolAddress((void**)&pX,  g_X);
    cudaGetSymbolAddress((void**)&pQ,  g_qkv);
    cudaGetSymbolAddress((void**)&pP,  g_proj);
    cudaGetSymbolAddress((void**)&ah,  g_ah);
    cudaGetSymbolAddress((void**)&al,  g_al);
    cudaGetSymbolAddress((void**)&fh,  g_fh);
    cudaGetSymbolAddress((void**)&wqh, g_wqkv_h);
    cudaGetSymbolAddress((void**)&woh, g_wo_h);
    cudaGetSymbolAddress((void**)&w1h, g_wf1_h);
    cudaGetSymbolAddress((void**)&w2h, g_wf2_h);
    cudaGetSymbolAddress((void**)&wph, g_wp_h);
    cudaGetSymbolAddress((void**)&wpl, g_wp_l);
    __half* qkvh = (__half*)pQ;

    cudaFuncSetAttribute(mma_gemm_kernel, cudaFuncAttributeMaxDynamicSharedMemorySize,
                         GEMM_SMEM);
    cudaFuncSetAttribute(gemm1_kernel, cudaFuncAttributeMaxDynamicSharedMemorySize,
                         G1_SMEM);
    cudaFuncSetAttribute(flash_tc_kernel, cudaFuncAttributeMaxDynamicSharedMemorySize,
                         110000);

    // --- weight conversion ----------------------------------------------------
    run_cvt(inw,  wqh, (size_t)N_LAYERS * 3 * D_MODEL * D_MODEL);
    run_cvt(outw, woh, (size_t)N_LAYERS * D_MODEL * D_MODEL);
    run_cvt(f1w,  w1h, (size_t)N_LAYERS * FF_DIM * D_MODEL);
    run_cvt(f2w,  w2h, (size_t)N_LAYERS * FF_DIM * D_MODEL);
    {
        int n4 = (int)(((size_t)D_MODEL * D_MODEL) >> 2);
        split_kernel<<<(n4 + 255) / 256, 256>>>((const float4*)patch_w,
                                                (__half2*)wph, (__half2*)wpl, n4);
    }

    // --- mask parse + gather + patch embedding --------------------------------
    mask_kernel<<<1, 256>>>((const unsigned char*)mask);
    im2col_kernel<<<dim3(Sc, BATCH), 256>>>(x, Sc);
    mma_gemm_kernel<<<dim3(6, MB), 256, GEMM_SMEM>>>(
        ah, al, wph, wpl, nullptr, pX, D_MODEL, M, D_MODEL, 0);
    patch_epi_kernel<<<dim3(Sc, BATCH), 256>>>(patch_b, pos, Sc);

    // --- transformer layers ---------------------------------------------------
    for (int l = 0; l < N_LAYERS; l++) {
        const __half* Wqh = wqh + (size_t)l * 3 * D_MODEL * D_MODEL;
        const __half* Woh = woh + (size_t)l * D_MODEL * D_MODEL;
        const __half* W1h = w1h + (size_t)l * FF_DIM * D_MODEL;
        const __half* W2h = w2h + (size_t)l * FF_DIM * D_MODEL;
        const float* bqkv = inb  + (size_t)l * 3 * D_MODEL;
        const float* bo   = outb + (size_t)l * D_MODEL;
        const float* b1   = f1b  + (size_t)l * FF_DIM;
        const float* b2   = f2b  + (size_t)l * D_MODEL;

        // QKV projection -> fp16 qkvh
        gemm1_kernel<<<dim3(18, MB), 256, G1_SMEM>>>(
            ah, Wqh, bqkv, nullptr, nullptr, qkvh, 3 * D_MODEL, M, D_MODEL,
            F_BIAS | F_OUT16);
        // tensor-core flash attention -> ah
        flash_tc_kernel<<<BATCH * N_HEADS, 128, flash_smem>>>(qkvh, Sc, ScPad);
        // output projection + residual -> pP (pre-LN sum)
        gemm1_kernel<<<dim3(6, MB), 256, G1_SMEM>>>(
            ah, Woh, bo, pX, pP, nullptr, D_MODEL, M, D_MODEL,
            F_BIAS | F_RESID);
        // LN1 -> X, ah
        ln_kernel<false, true><<<M, 256>>>(pP, nullptr, ln1g + l * D_MODEL,
                                           ln1b + l * D_MODEL, pX, ah);
        // FFN1 (+GELU) -> fh
        gemm1_kernel<<<dim3(24, MB), 256, G1_SMEM>>>(
            ah, W1h, b1, nullptr, nullptr, fh, FF_DIM, M, D_MODEL,
            F_BIAS | F_GELU | F_OUT16);
        // FFN2 + residual -> pP (pre-LN sum)
        gemm1_kernel<<<dim3(6, MB), 256, G1_SMEM>>>(
            fh, W2h, b2, pX, pP, nullptr, D_MODEL, M, FF_DIM,
            F_BIAS | F_RESID);
        // LN2 -> X, ah
        ln_kernel<false, true><<<M, 256>>>(pP, nullptr, ln2g + l * D_MODEL,
                                           ln2b + l * D_MODEL, pX, ah);
    }

    // --- final LN into d_out --------------------------------------------------
    ln_kernel<false, false><<<M, 256>>>(pX, nullptr, ng, nb, (float*)d_out, nullptr);
    if (tup) {
        pad_out_kernel<<<(BATCH * Sc + 255) / 256, 256>>>(
            (float*)d_out + (size_t)M * D_MODEL, Sc);
    }
}

// round 17
// speedup vs baseline: 3.3394x; 1.0583x over previous
#include <cuda_runtime.h>
#include <cuda_fp16.h>
#include <math.h>
#include <stdint.h>

// ============================================================================
// Masked ViT context encoder. R16: 1-term fp16 GEMMs move to M-tile 64
// (4 CTAs/SM, fine-grained scheduling => no wave tails). Residual fused in
// proj/FFN2 epilogues. Tensor-core flash attention. Patch GEMM 3-term M128.
// ============================================================================

#define BATCH    64
#define N_TOK    196
#define D_MODEL  768
#define N_HEADS  12
#define HEAD_DIM 64
#define N_LAYERS 12
#define FF_DIM   3072
#define M_MAX    (BATCH * N_TOK)

// flags
#define F_BIAS    1
#define F_GELU    2
#define F_OUT16   4
#define F_RESID   64

// ---------------- scratch (device globals; no allocation allowed) -----------
__device__ int    g_order[BATCH * N_TOK];
__device__ int    g_len[BATCH];
__device__ float  g_X[(size_t)M_MAX * D_MODEL];
__device__ float  g_qkv[(size_t)M_MAX * 3 * D_MODEL];   // reused as fp16 qkv
__device__ float  g_proj[(size_t)M_MAX * D_MODEL];
__device__ __half g_ah[(size_t)M_MAX * D_MODEL];
__device__ __half g_al[(size_t)M_MAX * D_MODEL];
__device__ __half g_fh[(size_t)M_MAX * FF_DIM];
__device__ __half g_wqkv_h[(size_t)N_LAYERS * 3 * D_MODEL * D_MODEL];
__device__ __half g_wo_h[(size_t)N_LAYERS * D_MODEL * D_MODEL];
__device__ __half g_wf1_h[(size_t)N_LAYERS * FF_DIM * D_MODEL];
__device__ __half g_wf2_h[(size_t)N_LAYERS * FF_DIM * D_MODEL];
__device__ __half g_wp_h[(size_t)D_MODEL * D_MODEL];
__device__ __half g_wp_l[(size_t)D_MODEL * D_MODEL];

// ============================================================================
// helpers
// ============================================================================
__device__ __forceinline__ uint32_t smem_u32(const void* p) {
    uint32_t a;
    asm("{ .reg .u64 t; cvta.to.shared.u64 t, %1; cvt.u32.u64 %0, t; }"
        : "=r"(a) : "l"(p));
    return a;
}
__device__ __forceinline__ void split_hl(float v, __half& h, __half& l) {
    h = __float2half(v);
    l = __float2half(v - __half2float(h));
}
__device__ __forceinline__ uint32_t f2h2(float a, float b) {
    __half2 h = __halves2half2(__float2half(a), __float2half(b));
    return *reinterpret_cast<uint32_t*>(&h);
}

#define CP_ASYNC_16(dst, src) \
    asm volatile("cp.async.cg.shared.global [%0], [%1], 16;" :: "r"(dst), "l"(src))
#define CP_COMMIT() asm volatile("cp.async.commit_group;" ::: "memory")
#define CP_WAIT(n)  asm volatile("cp.async.wait_group %0;" :: "n"(n) : "memory")

#define LDSM4(r0, r1, r2, r3, addr) \
    asm volatile("ldmatrix.sync.aligned.m8n8.x4.shared.b16 {%0,%1,%2,%3}, [%4];" \
        : "=r"(r0), "=r"(r1), "=r"(r2), "=r"(r3) : "r"(addr))

#define MMA16816(c, a, b) \
    asm volatile("mma.sync.aligned.m16n8k16.row.col.f32.f16.f16.f32 " \
        "{%0,%1,%2,%3}, {%4,%5,%6,%7}, {%8,%9}, {%0,%1,%2,%3};" \
        : "+f"((c)[0]), "+f"((c)[1]), "+f"((c)[2]), "+f"((c)[3]) \
        : "r"((a)[0]), "r"((a)[1]), "r"((a)[2]), "r"((a)[3]), \
          "r"((b)[0]), "r"((b)[1]))

// ============================================================================
// weight conversion
// ============================================================================
__global__ void split_kernel(const float4* __restrict__ src,
                             __half2* __restrict__ hi, __half2* __restrict__ lo, int n4)
{
    int i = blockIdx.x * blockDim.x + threadIdx.x;
    if (i >= n4) return;
    float4 v = src[i];
    __half h0, h1, h2, h3, l0, l1, l2, l3;
    split_hl(v.x, h0, l0); split_hl(v.y, h1, l1);
    split_hl(v.z, h2, l2); split_hl(v.w, h3, l3);
    hi[i * 2 + 0] = __halves2half2(h0, h1);
    hi[i * 2 + 1] = __halves2half2(h2, h3);
    lo[i * 2 + 0] = __halves2half2(l0, l1);
    lo[i * 2 + 1] = __halves2half2(l2, l3);
}

__global__ void cvt_kernel(const float4* __restrict__ src,
                           __half2* __restrict__ hi, int n4)
{
    int i = blockIdx.x * blockDim.x + threadIdx.x;
    if (i >= n4) return;
    float4 v = src[i];
    hi[i * 2 + 0] = __halves2half2(__float2half(v.x), __float2half(v.y));
    hi[i * 2 + 1] = __halves2half2(__float2half(v.z), __float2half(v.w));
}

// ============================================================================
// 3-term GEMM (patch only) — proven kernel, M-tile 128, K-chunk 32.
// ============================================================================
#define ROW_BYTES   80
#define TILE_BYTES  (128 * ROW_BYTES)
#define STAGE_BYTES (4 * TILE_BYTES)
#define GEMM_SMEM   (2 * STAGE_BYTES)

__global__ void __launch_bounds__(256, 2)
mma_gemm_kernel(const __half* __restrict__ Ah, const __half* __restrict__ Al,
                const __half* __restrict__ Bh, const __half* __restrict__ Bl,
                const float* __restrict__ bias,
                float* __restrict__ C, int ldc, int M, int K, int flags)
{
    extern __shared__ char smem[];
    const uint32_t sb = smem_u32(smem);
    const int tid  = threadIdx.x;
    const int wid  = tid >> 5, lane = tid & 31;
    const int wm   = wid & 3, wn = wid >> 2;
    const int brow = blockIdx.y * 128;
    const int bcol = blockIdx.x * 128;

    float acc[2][8][4];
    #pragma unroll
    for (int mt = 0; mt < 2; mt++)
        #pragma unroll
        for (int nt = 0; nt < 8; nt++)
            #pragma unroll
            for (int i = 0; i < 4; i++) acc[mt][nt][i] = 0.0f;

    const int nC = K >> 5;

    auto load_chunk = [&](int c, int buf) {
        const int k0 = c << 5;
        const uint32_t tb = sb + (uint32_t)buf * STAGE_BYTES;
        #pragma unroll
        for (int j = 0; j < 8; j++) {
            int idx = tid + (j << 8);
            int op  = idx >> 9;
            int rem = idx & 511;
            int r   = rem >> 2;
            int q   = rem & 3;
            const __half* gp;
            if (op < 2) {
                int gr = brow + r;
                if (gr >= M) gr = M - 1;
                gp = (op ? Al : Ah) + (size_t)gr * K + k0 + (q << 3);
            } else {
                int gn = bcol + r;
                gp = (op == 3 ? Bl : Bh) + (size_t)gn * K + k0 + (q << 3);
            }
            uint32_t dst = tb + (uint32_t)op * TILE_BYTES + (uint32_t)r * ROW_BYTES + (q << 4);
            CP_ASYNC_16(dst, gp);
        }
        CP_COMMIT();
    };

    load_chunk(0, 0);

    const uint32_t a_off = (uint32_t)(wm * 32 + (lane & 15)) * ROW_BYTES
                         + (uint32_t)((lane >> 4) << 3) * 2;
    const int      b_mm  = lane >> 3;
    const uint32_t b_row_off = (uint32_t)(wn * 64 + ((b_mm >> 1) << 3) + (lane & 7)) * ROW_BYTES;
    const uint32_t b_k_off   = (uint32_t)((b_mm & 1) << 3) * 2;

    for (int c = 0; c < nC; c++) {
        const int buf = c & 1;
        if (c + 1 < nC) { load_chunk(c + 1, buf ^ 1); CP_WAIT(1); }
        else            { CP_WAIT(0); }
        __syncthreads();

        const uint32_t At  = sb + (uint32_t)buf * STAGE_BYTES;
        const uint32_t Alt = At + TILE_BYTES;
        const uint32_t Bt  = At + 2 * TILE_BYTES;
        const uint32_t Blt = At + 3 * TILE_BYTES;

        #pragma unroll
        for (int ks = 0; ks < 32; ks += 16) {
            uint32_t ah[2][4], bh[8][2], bl[8][2];
            const uint32_t ksb = (uint32_t)ks * 2;
            LDSM4(ah[0][0], ah[0][1], ah[0][2], ah[0][3], At  + a_off + ksb);
            LDSM4(ah[1][0], ah[1][1], ah[1][2], ah[1][3], At  + a_off + ksb + 16 * ROW_BYTES);
            #pragma unroll
            for (int g = 0; g < 4; g++) {
                uint32_t off = b_row_off + (uint32_t)(g * 16) * ROW_BYTES + b_k_off + ksb;
                LDSM4(bh[2*g][0], bh[2*g][1], bh[2*g+1][0], bh[2*g+1][1], Bt  + off);
                LDSM4(bl[2*g][0], bl[2*g][1], bl[2*g+1][0], bl[2*g+1][1], Blt + off);
            }
            #pragma unroll
            for (int mt = 0; mt < 2; mt++)
                #pragma unroll
                for (int nt = 0; nt < 8; nt++) MMA16816(acc[mt][nt], ah[mt], bh[nt]);
            #pragma unroll
            for (int mt = 0; mt < 2; mt++)
                #pragma unroll
                for (int nt = 0; nt < 8; nt++) MMA16816(acc[mt][nt], ah[mt], bl[nt]);
            {
                uint32_t al[2][4];
                LDSM4(al[0][0], al[0][1], al[0][2], al[0][3], Alt + a_off + ksb);
                LDSM4(al[1][0], al[1][1], al[1][2], al[1][3], Alt + a_off + ksb + 16 * ROW_BYTES);
                #pragma unroll
                for (int mt = 0; mt < 2; mt++)
                    #pragma unroll
                    for (int nt = 0; nt < 8; nt++) MMA16816(acc[mt][nt], al[mt], bh[nt]);
            }
        }
        __syncthreads();
    }

    const int lr = lane >> 2, lc = (lane & 3) * 2;
    #pragma unroll
    for (int mt = 0; mt < 2; mt++) {
        int r0 = brow + wm * 32 + mt * 16 + lr;
        #pragma unroll
        for (int nt = 0; nt < 8; nt++) {
            int cc = bcol + wn * 64 + nt * 8 + lc;
            float bv0 = 0.0f, bv1 = 0.0f;
            if (flags & F_BIAS) { bv0 = bias[cc]; bv1 = bias[cc + 1]; }
            #pragma unroll
            for (int half = 0; half < 2; half++) {
                int r = r0 + half * 8;
                if (r < M) {
                    float v0 = acc[mt][nt][half * 2 + 0] + bv0;
                    float v1 = acc[mt][nt][half * 2 + 1] + bv1;
                    *(float2*)(C + (size_t)r * ldc + cc) = make_float2(v0, v1);
                }
            }
        }
    }
}

// ============================================================================
// 1-term fp16 GEMM, M-tile 64: C = A @ B^T, fp32 accum. K-chunk 64,
// 4 warps (2m x 2n, warp tile 32x64), stage (64+128)*144 = 27.6KB,
// double buffer 55.3KB => 4 CTAs/SM (fine-grained scheduling).
// flags: F_BIAS, F_GELU, F_OUT16 (hi fp16 to Ch), F_RESID (+= R).
// ============================================================================
#define G1_ROW    144
#define G1_ATILE  (64 * G1_ROW)        // 9216
#define G1_BTILE  (128 * G1_ROW)       // 18432
#define G1_STAGE  (G1_ATILE + G1_BTILE) // 27648
#define G1_SMEM   (2 * G1_STAGE)        // 55296

__global__ void __launch_bounds__(128, 4)
gemm1_kernel(const __half* __restrict__ A, const __half* __restrict__ B,
             const float* __restrict__ bias, const float* __restrict__ R,
             float* __restrict__ C, __half* __restrict__ Ch,
             int ldc, int M, int K, int flags)
{
    extern __shared__ char smem[];
    const uint32_t sb = smem_u32(smem);
    const int tid  = threadIdx.x;
    const int wid  = tid >> 5, lane = tid & 31;
    const int wm   = wid & 1, wn = wid >> 1;     // 2(m) x 2(n)
    const int brow = blockIdx.y * 64;
    const int bcol = blockIdx.x * 128;

    float acc[2][8][4];
    #pragma unroll
    for (int mt = 0; mt < 2; mt++)
        #pragma unroll
        for (int nt = 0; nt < 8; nt++)
            #pragma unroll
            for (int i = 0; i < 4; i++) acc[mt][nt][i] = 0.0f;

    const int nC = K >> 6;

    // per stage: A 512 chunks + B 1024 chunks = 1536; 12 per thread.
    auto load_chunk = [&](int c, int buf) {
        const int k0 = c << 6;
        const uint32_t tb = sb + (uint32_t)buf * G1_STAGE;
        #pragma unroll
        for (int j = 0; j < 12; j++) {
            int idx = tid + (j << 7);
            const __half* gp;
            uint32_t dst;
            if (idx < 512) {                      // A: 64 rows x 8 chunks
                int r = idx >> 3, q = idx & 7;
                int gr = brow + r;
                if (gr >= M) gr = M - 1;
                gp  = A + (size_t)gr * K + k0 + (q << 3);
                dst = tb + (uint32_t)r * G1_ROW + (q << 4);
            } else {                              // B: 128 rows x 8 chunks
                int idx2 = idx - 512;
                int r = idx2 >> 3, q = idx2 & 7;
                int gn = bcol + r;
                gp  = B + (size_t)gn * K + k0 + (q << 3);
                dst = tb + G1_ATILE + (uint32_t)r * G1_ROW + (q << 4);
            }
            CP_ASYNC_16(dst, gp);
        }
        CP_COMMIT();
    };

    load_chunk(0, 0);

    const uint32_t a_off = (uint32_t)(wm * 32 + (lane & 15)) * G1_ROW
                         + (uint32_t)((lane >> 4) << 3) * 2;
    const int      b_mm  = lane >> 3;
    const uint32_t b_row_off = (uint32_t)(wn * 64 + ((b_mm >> 1) << 3) + (lane & 7)) * G1_ROW;
    const uint32_t b_k_off   = (uint32_t)((b_mm & 1) << 3) * 2;

    for (int c = 0; c < nC; c++) {
        const int buf = c & 1;
        if (c + 1 < nC) { load_chunk(c + 1, buf ^ 1); CP_WAIT(1); }
        else            { CP_WAIT(0); }
        __syncthreads();

        const uint32_t At = sb + (uint32_t)buf * G1_STAGE;
        const uint32_t Bt = At + G1_ATILE;

        #pragma unroll
        for (int ks = 0; ks < 64; ks += 16) {
            uint32_t ar[2][4], br[8][2];
            const uint32_t ksb = (uint32_t)ks * 2;
            LDSM4(ar[0][0], ar[0][1], ar[0][2], ar[0][3], At + a_off + ksb);
            LDSM4(ar[1][0], ar[1][1], ar[1][2], ar[1][3], At + a_off + ksb + 16 * G1_ROW);
            #pragma unroll
            for (int g = 0; g < 4; g++) {
                uint32_t off = b_row_off + (uint32_t)(g * 16) * G1_ROW + b_k_off + ksb;
                LDSM4(br[2*g][0], br[2*g][1], br[2*g+1][0], br[2*g+1][1], Bt + off);
            }
            #pragma unroll
            for (int mt = 0; mt < 2; mt++)
                #pragma unroll
                for (int nt = 0; nt < 8; nt++) MMA16816(acc[mt][nt], ar[mt], br[nt]);
        }
        __syncthreads();
    }

    const int lr = lane >> 2, lc = (lane & 3) * 2;
    #pragma unroll
    for (int mt = 0; mt < 2; mt++) {
        int r0 = brow + wm * 32 + mt * 16 + lr;
        #pragma unroll
        for (int nt = 0; nt < 8; nt++) {
            int cc = bcol + wn * 64 + nt * 8 + lc;
            float bv0 = 0.0f, bv1 = 0.0f;
            if (flags & F_BIAS) { bv0 = bias[cc]; bv1 = bias[cc + 1]; }
            #pragma unroll
            for (int half = 0; half < 2; half++) {
                int r = r0 + half * 8;
                if (r < M) {
                    float v0 = acc[mt][nt][half * 2 + 0] + bv0;
                    float v1 = acc[mt][nt][half * 2 + 1] + bv1;
                    if (flags & F_RESID) {
                        float2 rr = *(const float2*)(R + (size_t)r * ldc + cc);
                        v0 += rr.x; v1 += rr.y;
                    }
                    if (flags & F_GELU) {
                        v0 = 0.5f * v0 * (1.0f + erff(v0 * 0.70710678118654752440f));
                        v1 = 0.5f * v1 * (1.0f + erff(v1 * 0.70710678118654752440f));
                    }
                    if (flags & F_OUT16) {
                        *(uint32_t*)(Ch + (size_t)r * ldc + cc) = f2h2(v0, v1);
                    } else {
                        *(float2*)(C + (size_t)r * ldc + cc) = make_float2(v0, v1);
                    }
                }
            }
        }
    }
}

// ============================================================================
// mask parse
// ============================================================================
__global__ void mask_kernel(const unsigned char* __restrict__ mp)
{
    int tid = threadIdx.x;
    bool big = false, misal = false;
    for (int i = tid; i < BATCH * N_TOK; i += 256) {
        unsigned char v = mp[i];
        if (v >= 2) big = true;
        else if (v && (i & 3)) misal = true;
    }
    int anybig = __syncthreads_or(big ? 1 : 0);
    int anymis = __syncthreads_or(misal ? 1 : 0);
    int type = anybig ? 2 : (anymis ? 1 : 0);
    int b = tid;
    if (b < BATCH) {
        int cnt = 0;
        for (int t = 0; t < N_TOK; t++) {
            int idx = b * N_TOK + t;
            bool m;
            if (type == 2)      m = (((const float*)mp)[idx] != 0.0f);
            else if (type == 1) m = (mp[idx] != 0);
            else                m = (((const int*)mp)[idx] != 0);
            if (m) { g_order[b * N_TOK + cnt] = t; cnt++; }
        }
        g_len[b] = cnt;
    }
}

// ============================================================================
// im2col gather (patch GEMM is 3-term: hi+lo)
// ============================================================================
__global__ void im2col_kernel(const float* __restrict__ x, int Sc)
{
    int s = blockIdx.x, b = blockIdx.y;
    int m = b * Sc + s;
    __half* dh = g_ah + (size_t)m * D_MODEL;
    __half* dl = g_al + (size_t)m * D_MODEL;
    if (s >= g_len[b]) {
        for (int k = threadIdx.x; k < D_MODEL; k += blockDim.x) {
            dh[k] = __float2half(0.0f); dl[k] = __float2half(0.0f);
        }
        return;
    }
    int t = g_order[b * N_TOK + s];
    int gy = t / 14, gx = t % 14;
    const float* xb = x + (size_t)b * 3 * 224 * 224;
    for (int k = threadIdx.x; k < D_MODEL; k += blockDim.x) {
        int c = k >> 8, r = (k >> 4) & 15, cc = k & 15;
        float v = xb[((size_t)c * 224 + (gy * 16 + r)) * 224 + (gx * 16 + cc)];
        __half h, l; split_hl(v, h, l);
        dh[k] = h; dl[k] = l;
    }
}

// patch epilogue: X += patch_b + pos; emit hi fp16; zero pads.
__global__ void patch_epi_kernel(const float* __restrict__ pb,
                                 const float* __restrict__ pos, int Sc)
{
    int s = blockIdx.x, b = blockIdx.y;
    int m = b * Sc + s;
    float* row = g_X + (size_t)m * D_MODEL;
    __half* dh = g_ah + (size_t)m * D_MODEL;
    if (s >= g_len[b]) {
        for (int d = threadIdx.x; d < D_MODEL; d += blockDim.x) {
            row[d] = 0.0f;
            dh[d] = __float2half(0.0f);
        }
        return;
    }
    int t = g_order[b * N_TOK + s];
    const float* pr = pos + (size_t)t * D_MODEL;
    for (int d = threadIdx.x; d < D_MODEL; d += blockDim.x) {
        float v = row[d] + pb[d] + pr[d];
        row[d] = v;
        dh[d] = __float2half(v);
    }
}

// ============================================================================
// Tensor-core flash attention (unchanged).
// ============================================================================
__global__ void __launch_bounds__(128)
flash_tc_kernel(const __half* __restrict__ qkvh, int Sc, int ScPad)
{
    extern __shared__ char fsm[];
    const int b = blockIdx.x / N_HEADS, h = blockIdx.x % N_HEADS;
    const int len = g_len[b];
    const int tid = threadIdx.x, lane = tid & 31, wid = tid >> 5;

    const int vt_h = ScPad + 8;
    __half* Qs = (__half*)fsm;
    __half* Ks = Qs + (size_t)ScPad * 72;
    __half* VT = Ks + (size_t)ScPad * 72;
    const uint32_t Qb = smem_u32(Qs), Kb = smem_u32(Ks), Vb = smem_u32(VT);

    for (int idx = tid; idx < ScPad * 64; idx += 128) {
        int r = idx >> 6, d = idx & 63;
        __half qv = __float2half(0.0f), kv = qv, vv = qv;
        if (r < Sc) {
            size_t base = (size_t)(b * Sc + r) * (3 * D_MODEL) + h * HEAD_DIM + d;
            qv = qkvh[base];
            kv = qkvh[base + D_MODEL];
            vv = qkvh[base + 2 * D_MODEL];
        }
        Qs[r * 72 + d] = qv;
        Ks[r * 72 + d] = kv;
        VT[d * vt_h + r] = vv;
    }
    __syncthreads();

    const uint32_t a_off = (uint32_t)(lane & 15) * 144 + (uint32_t)((lane >> 4) << 3) * 2;
    const int      b_mm  = lane >> 3;
    const uint32_t bk_row = (uint32_t)(((b_mm >> 1) << 3) + (lane & 7)) * 144;
    const uint32_t bv_row = (uint32_t)(((b_mm >> 1) << 3) + (lane & 7)) * (uint32_t)(vt_h * 2);
    const uint32_t bk_k   = (uint32_t)((b_mm & 1) << 3) * 2;

    const int nKC = (len + 15) >> 4;

    for (int qt = wid; qt * 16 < Sc; qt += 4) {
        uint32_t aq[4][4];
        #pragma unroll
        for (int ks = 0; ks < 4; ks++)
            LDSM4(aq[ks][0], aq[ks][1], aq[ks][2], aq[ks][3],
                  Qb + (uint32_t)(qt * 16) * 144 + a_off + ks * 32);

        float m0 = -1e30f, m1 = -1e30f, l0 = 0.0f, l1 = 0.0f;
        float o[8][4];
        #pragma unroll
        for (int t = 0; t < 8; t++)
            #pragma unroll
            for (int i = 0; i < 4; i++) o[t][i] = 0.0f;

        for (int kc = 0; kc < nKC; kc++) {
            float s0[4] = {0.f, 0.f, 0.f, 0.f}, s1[4] = {0.f, 0.f, 0.f, 0.f};
            #pragma unroll
            for (int ks = 0; ks < 4; ks++) {
                uint32_t r0, r1, r2, r3;
                LDSM4(r0, r1, r2, r3,
                      Kb + (uint32_t)(kc * 16) * 144 + bk_row + bk_k + ks * 32);
                uint32_t bh0[2] = {r0, r1}, bh1[2] = {r2, r3};
                MMA16816(s0, aq[ks], bh0);
                MMA16816(s1, aq[ks], bh1);
            }
            #pragma unroll
            for (int i = 0; i < 4; i++) { s0[i] *= 0.125f; s1[i] *= 0.125f; }
            int colb = kc * 16 + ((lane & 3) << 1);
            if (colb     >= len) { s0[0] = -1e30f; s0[2] = -1e30f; }
            if (colb + 1 >= len) { s0[1] = -1e30f; s0[3] = -1e30f; }
            if (colb + 8 >= len) { s1[0] = -1e30f; s1[2] = -1e30f; }
            if (colb + 9 >= len) { s1[1] = -1e30f; s1[3] = -1e30f; }
            float mu = fmaxf(fmaxf(s0[0], s0[1]), fmaxf(s1[0], s1[1]));
            float mw = fmaxf(fmaxf(s0[2], s0[3]), fmaxf(s1[2], s1[3]));
            mu = fmaxf(mu, __shfl_xor_sync(0xffffffffu, mu, 1));
            mu = fmaxf(mu, __shfl_xor_sync(0xffffffffu, mu, 2));
            mw = fmaxf(mw, __shfl_xor_sync(0xffffffffu, mw, 1));
            mw = fmaxf(mw, __shfl_xor_sync(0xffffffffu, mw, 2));
            float mn0 = fmaxf(m0, mu), mn1 = fmaxf(m1, mw);
            float sc0 = __expf(m0 - mn0), sc1 = __expf(m1 - mn1);
            m0 = mn0; m1 = mn1;
            float p0 = __expf(s0[0] - mn0), p1 = __expf(s0[1] - mn0);
            float p2 = __expf(s1[0] - mn0), p3 = __expf(s1[1] - mn0);
            float p4 = __expf(s0[2] - mn1), p5 = __expf(s0[3] - mn1);
            float p6 = __expf(s1[2] - mn1), p7 = __expf(s1[3] - mn1);
            float su = (p0 + p1) + (p2 + p3);
            float sl = (p4 + p5) + (p6 + p7);
            su += __shfl_xor_sync(0xffffffffu, su, 1);
            su += __shfl_xor_sync(0xffffffffu, su, 2);
            sl += __shfl_xor_sync(0xffffffffu, sl, 1);
            sl += __shfl_xor_sync(0xffffffffu, sl, 2);
            l0 = l0 * sc0 + su;
            l1 = l1 * sc1 + sl;
            #pragma unroll
            for (int t = 0; t < 8; t++) {
                o[t][0] *= sc0; o[t][1] *= sc0;
                o[t][2] *= sc1; o[t][3] *= sc1;
            }
            uint32_t ap[4];
            ap[0] = f2h2(p0, p1);
            ap[1] = f2h2(p4, p5);
            ap[2] = f2h2(p2, p3);
            ap[3] = f2h2(p6, p7);
            #pragma unroll
            for (int g2 = 0; g2 < 4; g2++) {
                uint32_t r0, r1, r2, r3;
                LDSM4(r0, r1, r2, r3,
                      Vb + (uint32_t)(g2 * 16) * (vt_h * 2) + bv_row + bk_k + kc * 32);
                uint32_t bv0[2] = {r0, r1}, bv1[2] = {r2, r3};
                MMA16816(o[2 * g2],     ap, bv0);
                MMA16816(o[2 * g2 + 1], ap, bv1);
            }
        }
        float inv0 = 1.0f / l0, inv1 = 1.0f / l1;
        int r0 = qt * 16 + (lane >> 2), r1 = r0 + 8;
        #pragma unroll
        for (int t = 0; t < 8; t++) {
            int dim = t * 8 + ((lane & 3) << 1);
            if (r0 < Sc) {
                uint32_t u = f2h2(o[t][0] * inv0, o[t][1] * inv0);
                *(uint32_t*)(g_ah + (size_t)(b * Sc + r0) * D_MODEL + h * HEAD_DIM + dim) = u;
            }
            if (r1 < Sc) {
                uint32_t u = f2h2(o[t][2] * inv1, o[t][3] * inv1);
                *(uint32_t*)(g_ah + (size_t)(b * Sc + r1) * D_MODEL + h * HEAD_DIM + dim) = u;
            }
        }
    }
}

// ============================================================================
// LayerNorm; optionally emits hi fp16.
// ============================================================================
__device__ __forceinline__ float blockReduce256(float v)
{
    __shared__ float sh[8];
    __syncthreads();
    #pragma unroll
    for (int o = 16; o; o >>= 1) v += __shfl_down_sync(0xffffffffu, v, o);
    if ((threadIdx.x & 31) == 0) sh[threadIdx.x >> 5] = v;
    __syncthreads();
    return sh[0] + sh[1] + sh[2] + sh[3] + sh[4] + sh[5] + sh[6] + sh[7];
}

template<bool RESID, bool EMITH>
__global__ void ln_kernel(const float* __restrict__ X, const float* __restrict__ Rsd,
                          const float* __restrict__ gma, const float* __restrict__ bta,
                          float* __restrict__ out, __half* __restrict__ outH)
{
    int m = blockIdx.x;
    int tid = threadIdx.x;
    const float* xr = X + (size_t)m * D_MODEL;
    float v[3];
    #pragma unroll
    for (int i = 0; i < 3; i++) {
        int d = tid + 256 * i;
        v[i] = xr[d];
        if (RESID) v[i] += Rsd[(size_t)m * D_MODEL + d];
    }
    float s = blockReduce256(v[0] + v[1] + v[2]);
    float mean = s * (1.0f / 768.0f);
    float q = 0.0f;
    #pragma unroll
    for (int i = 0; i < 3; i++) { float d = v[i] - mean; q += d * d; }
    q = blockReduce256(q);
    float inv = 1.0f / sqrtf(q * (1.0f / 768.0f) + 1e-5f);
    #pragma unroll
    for (int i = 0; i < 3; i++) {
        int d = tid + 256 * i;
        float r = (v[i] - mean) * inv * gma[d] + bta[d];
        out[(size_t)m * D_MODEL + d] = r;
        if (EMITH) outH[(size_t)m * D_MODEL + d] = __float2half(r);
    }
}

__global__ void pad_out_kernel(float* __restrict__ out2, int Sc)
{
    int i = blockIdx.x * blockDim.x + threadIdx.x;
    if (i < BATCH * Sc) {
        int b = i / Sc, s = i % Sc;
        out2[i] = (s >= g_len[b]) ? 1.0f : 0.0f;
    }
}

// ===========================================================================
static void run_cvt(const float* src, __half* hi, size_t n)
{
    int n4 = (int)(n >> 2);
    cvt_kernel<<<(n4 + 255) / 256, 256>>>((const float4*)src, (__half2*)hi, n4);
}

extern "C" void kernel_launch(void* const* d_in, const int* in_sizes, int n_in,
                              void* d_out, int out_size)
{
    const float* x       = (const float*)d_in[0];
    const void*  mask    = d_in[1];
    const float* patch_w = (const float*)d_in[2];
    const float* patch_b = (const float*)d_in[3];
    const float* pos     = (const float*)d_in[4];
    const float* inw     = (const float*)d_in[5];
    const float* inb     = (const float*)d_in[6];
    const float* outw    = (const float*)d_in[7];
    const float* outb    = (const float*)d_in[8];
    const float* ln1g    = (const float*)d_in[9];
    const float* ln1b    = (const float*)d_in[10];
    const float* f1w     = (const float*)d_in[11];
    const float* f1b     = (const float*)d_in[12];
    const float* f2w     = (const float*)d_in[13];
    const float* f2b     = (const float*)d_in[14];
    const float* ln2g    = (const float*)d_in[15];
    const float* ln2b    = (const float*)d_in[16];
    const float* ng      = (const float*)d_in[17];
    const float* nb      = (const float*)d_in[18];

    int Sc; bool tup;
    if (out_size % (64 * 769) == 0 &&
        out_size / (64 * 769) >= 1 && out_size / (64 * 769) <= N_TOK) {
        Sc = out_size / (64 * 769); tup = true;
    } else {
        Sc = out_size / (64 * 768); tup = false;
    }
    if (Sc < 1) Sc = 1;
    if (Sc > N_TOK) Sc = N_TOK;
    const int M    = BATCH * Sc;
    const int MB   = (M + 127) / 128;
    const int MB64 = (M + 63) / 64;
    const int ScPad = (Sc + 15) & ~15;
    const int flash_smem = 2 * ScPad * 144 + 64 * (ScPad + 8) * 2;

    float *pX, *pQ, *pP;
    __half *ah, *al, *fh, *wqh, *woh, *w1h, *w2h, *wph, *wpl;
    cudaGetSymbolAddress((void**)&pX,  g_X);
    cudaGetSymbolAddress((void**)&pQ,  g_qkv);
    cudaGetSymbolAddress((void**)&pP,  g_proj);
    cudaGetSymbolAddress((void**)&ah,  g_ah);
    cudaGetSymbolAddress((void**)&al,  g_al);
    cudaGetSymbolAddress((void**)&fh,  g_fh);
    cudaGetSymbolAddress((void**)&wqh, g_wqkv_h);
    cudaGetSymbolAddress((void**)&woh, g_wo_h);
    cudaGetSymbolAddress((void**)&w1h, g_wf1_h);
    cudaGetSymbolAddress((void**)&w2h, g_wf2_h);
    cudaGetSymbolAddress((void**)&wph, g_wp_h);
    cudaGetSymbolAddress((void**)&wpl, g_wp_l);
    __half* qkvh = (__half*)pQ;

    cudaFuncSetAttribute(mma_gemm_kernel, cudaFuncAttributeMaxDynamicSharedMemorySize,
                         GEMM_SMEM);
    cudaFuncSetAttribute(gemm1_kernel, cudaFuncAttributeMaxDynamicSharedMemorySize,
                         G1_SMEM);
    cudaFuncSetAttribute(flash_tc_kernel, cudaFuncAttributeMaxDynamicSharedMemorySize,
                         110000);

    // --- weight conversion ----------------------------------------------------
    run_cvt(inw,  wqh, (size_t)N_LAYERS * 3 * D_MODEL * D_MODEL);
    run_cvt(outw, woh, (size_t)N_LAYERS * D_MODEL * D_MODEL);
    run_cvt(f1w,  w1h, (size_t)N_LAYERS * FF_DIM * D_MODEL);
    run_cvt(f2w,  w2h, (size_t)N_LAYERS * FF_DIM * D_MODEL);
    {
        int n4 = (int)(((size_t)D_MODEL * D_MODEL) >> 2);
        split_kernel<<<(n4 + 255) / 256, 256>>>((const float4*)patch_w,
                                                (__half2*)wph, (__half2*)wpl, n4);
    }

    // --- mask parse + gather + patch embedding --------------------------------
    mask_kernel<<<1, 256>>>((const unsigned char*)mask);
    im2col_kernel<<<dim3(Sc, BATCH), 256>>>(x, Sc);
    mma_gemm_kernel<<<dim3(6, MB), 256, GEMM_SMEM>>>(
        ah, al, wph, wpl, nullptr, pX, D_MODEL, M, D_MODEL, 0);
    patch_epi_kernel<<<dim3(Sc, BATCH), 256>>>(patch_b, pos, Sc);

    // --- transformer layers ---------------------------------------------------
    for (int l = 0; l < N_LAYERS; l++) {
        const __half* Wqh = wqh + (size_t)l * 3 * D_MODEL * D_MODEL;
        const __half* Woh = woh + (size_t)l * D_MODEL * D_MODEL;
        const __half* W1h = w1h + (size_t)l * FF_DIM * D_MODEL;
        const __half* W2h = w2h + (size_t)l * FF_DIM * D_MODEL;
        const float* bqkv = inb  + (size_t)l * 3 * D_MODEL;
        const float* bo   = outb + (size_t)l * D_MODEL;
        const float* b1   = f1b  + (size_t)l * FF_DIM;
        const float* b2   = f2b  + (size_t)l * D_MODEL;

        // QKV projection -> fp16 qkvh
        gemm1_kernel<<<dim3(18, MB64), 128, G1_SMEM>>>(
            ah, Wqh, bqkv, nullptr, nullptr, qkvh, 3 * D_MODEL, M, D_MODEL,
            F_BIAS | F_OUT16);
        // tensor-core flash attention -> ah
        flash_tc_kernel<<<BATCH * N_HEADS, 128, flash_smem>>>(qkvh, Sc, ScPad);
        // output projection + residual -> pP (pre-LN sum)
        gemm1_kernel<<<dim3(6, MB64), 128, G1_SMEM>>>(
            ah, Woh, bo, pX, pP, nullptr, D_MODEL, M, D_MODEL,
            F_BIAS | F_RESID);
        // LN1 -> X, ah
        ln_kernel<false, true><<<M, 256>>>(pP, nullptr, ln1g + l * D_MODEL,
                                           ln1b + l * D_MODEL, pX, ah);
        // FFN1 (+GELU) -> fh
        gemm1_kernel<<<dim3(24, MB64), 128, G1_SMEM>>>(
            ah, W1h, b1, nullptr, nullptr, fh, FF_DIM, M, D_MODEL,
            F_BIAS | F_GELU | F_OUT16);
        // FFN2 + residual -> pP (pre-LN sum)
        gemm1_kernel<<<dim3(6, MB64), 128, G1_SMEM>>>(
            fh, W2h, b2, pX, pP, nullptr, D_MODEL, M, FF_DIM,
            F_BIAS | F_RESID);
        // LN2 -> X, ah
        ln_kernel<false, true><<<M, 256>>>(pP, nullptr, ln2g + l * D_MODEL,
                                           ln2b + l * D_MODEL, pX, ah);
    }

    // --- final LN into d_out --------------------------------------------------
    ln_kernel<false, false><<<M, 256>>>(pX, nullptr, ng, nb, (float*)d_out, nullptr);
    if (tup) {
        pad_out_kernel<<<(BATCH * Sc + 255) / 256, 256>>>(
            (float*)d_out + (size_t)M * D_MODEL, Sc);
    }
}